// round 2
// baseline (speedup 1.0000x reference)
#include <cuda_runtime.h>
#include <math.h>

// ---------------- problem constants ----------------
#define D_MODEL 768
#define D_STATE 16
#define D_CONV  4
#define INNER   1536
#define N2      (2*INNER)     // 3072
#define BATCH   2
#define SEQLEN  2048
#define NTOK    (BATCH*SEQLEN)  // 4096
#define NCHUNK  16
#define CHUNK   (SEQLEN/NCHUNK) // 128

// ---------------- scratch (static device globals; no allocation) ----------------
__device__ float g_xz  [NTOK * N2];          // in_proj output (proj | gate)
__device__ float g_u   [NTOK * INNER];       // conv+silu output, token-major
__device__ float g_dt  [NTOK * INNER];       // softplus(dt_proj), token-major
__device__ float g_yg  [NTOK * INNER];       // (y + D*u)*silu(z), token-major
__device__ float g_hend[BATCH*NCHUNK*D_STATE*INNER];
__device__ float g_h0  [BATCH*NCHUNK*D_STATE*INNER];
__device__ float g_sdt [BATCH*NCHUNK*INNER];

// ---------------- helpers ----------------
__device__ __forceinline__ float siluf(float x) {
    return x * (1.0f / (1.0f + __expf(-x)));
}
__device__ __forceinline__ float softplusf(float x) {
    return fmaxf(x, 0.0f) + log1pf(__expf(-fabsf(x)));
}

// ---------------- generic NT SGEMM: C[M,N] = A[M,K] * B[N,K]^T ----------------
// BM=BN=128, BK=8, 256 threads, 8x8 per thread. All dims divide tiles exactly.
// EPI: 0 = plain store, 1 = softplus(x + b1[col] + b2[col])
template<int EPI>
__global__ __launch_bounds__(256)
void sgemm_nt(const float* __restrict__ A, const float* __restrict__ B,
              float* __restrict__ C, int M, int N, int K,
              const float* __restrict__ b1, const float* __restrict__ b2)
{
    __shared__ float As[8][128];
    __shared__ float Bs[8][128];

    const int tid  = threadIdx.x;
    const int row2 = tid >> 1;          // 0..127
    const int seg  = (tid & 1) * 4;     // 0 or 4

    const float* Ag = A + (size_t)(blockIdx.y * 128 + row2) * K + seg;
    const float* Bg = B + (size_t)(blockIdx.x * 128 + row2) * K + seg;

    const int tr = (tid >> 4) * 8;      // row offset in tile
    const int tc = (tid & 15) * 8;      // col offset in tile

    float acc[8][8];
    #pragma unroll
    for (int i = 0; i < 8; ++i)
        #pragma unroll
        for (int j = 0; j < 8; ++j) acc[i][j] = 0.0f;

    for (int k0 = 0; k0 < K; k0 += 8) {
        float4 va = *(const float4*)(Ag + k0);
        float4 vb = *(const float4*)(Bg + k0);
        As[seg+0][row2] = va.x; As[seg+1][row2] = va.y;
        As[seg+2][row2] = va.z; As[seg+3][row2] = va.w;
        Bs[seg+0][row2] = vb.x; Bs[seg+1][row2] = vb.y;
        Bs[seg+2][row2] = vb.z; Bs[seg+3][row2] = vb.w;
        __syncthreads();
        #pragma unroll
        for (int k = 0; k < 8; ++k) {
            float ar[8], br[8];
            #pragma unroll
            for (int i = 0; i < 4; ++i) {
                ((float4*)ar)[0] = *(const float4*)&As[k][tr];
                ((float4*)ar)[1] = *(const float4*)&As[k][tr+4];
                ((float4*)br)[0] = *(const float4*)&Bs[k][tc];
                ((float4*)br)[1] = *(const float4*)&Bs[k][tc+4];
                break;
            }
            #pragma unroll
            for (int i = 0; i < 8; ++i)
                #pragma unroll
                for (int j = 0; j < 8; ++j)
                    acc[i][j] = fmaf(ar[i], br[j], acc[i][j]);
        }
        __syncthreads();
    }

    const int crow = blockIdx.y * 128 + tr;
    const int ccol = blockIdx.x * 128 + tc;
    #pragma unroll
    for (int i = 0; i < 8; ++i) {
        float* cp = C + (size_t)(crow + i) * N + ccol;
        #pragma unroll
        for (int j = 0; j < 8; ++j) {
            float v = acc[i][j];
            if (EPI == 1) v = softplusf(v + b1[ccol + j] + b2[ccol + j]);
            cp[j] = v;
        }
    }
}

// ---------------- depthwise causal conv(4) + bias + SiLU ----------------
// reads proj half of g_xz, writes g_u token-major
__global__ __launch_bounds__(256)
void conv_silu_kernel(const float* __restrict__ xz,
                      const float* __restrict__ cw,
                      const float* __restrict__ cb,
                      float* __restrict__ u)
{
    int idx = blockIdx.x * blockDim.x + threadIdx.x;
    if (idx >= NTOK * INNER) return;
    int c = idx % INNER;
    int t = idx / INNER;
    int l = t & (SEQLEN - 1);

    float acc = cb[c];
    #pragma unroll
    for (int k = 0; k < D_CONV; ++k) {
        int ll = l - (D_CONV - 1) + k;
        if (ll >= 0)
            acc = fmaf(cw[c * D_CONV + k],
                       xz[(size_t)(t - (D_CONV - 1) + k) * N2 + c], acc);
    }
    u[idx] = siluf(acc);
}

// ---------------- scan pass 1: per-chunk local scan (h0 = 0) ----------------
__global__ __launch_bounds__(256)
void scan_pass1(const float* __restrict__ dt, const float* __restrict__ u,
                const float* __restrict__ A_log, const float* __restrict__ Bp,
                float* __restrict__ hend, float* __restrict__ sdtb)
{
    int idx = blockIdx.x * blockDim.x + threadIdx.x; // < BATCH*NCHUNK*INNER
    int d = idx % INNER;
    int c = (idx / INNER) & (NCHUNK - 1);
    int b = idx / (INNER * NCHUNK);

    float Av[D_STATE], Bv[D_STATE], h[D_STATE];
    #pragma unroll
    for (int n = 0; n < D_STATE; ++n) {
        Av[n] = -__expf(A_log[d * D_STATE + n]);
        Bv[n] = Bp[d * D_STATE + n];
        h[n]  = 0.0f;
    }
    float sdt = 0.0f;
    int t0 = b * SEQLEN + c * CHUNK;
    for (int j = 0; j < CHUNK; ++j) {
        size_t off = (size_t)(t0 + j) * INNER + d;
        float dtv = dt[off];
        float uv  = u[off];
        sdt += dtv;
        float du = dtv * uv;
        #pragma unroll
        for (int n = 0; n < D_STATE; ++n)
            h[n] = fmaf(__expf(dtv * Av[n]), h[n], du * Bv[n]);
    }
    int bc = b * NCHUNK + c;
    #pragma unroll
    for (int n = 0; n < D_STATE; ++n)
        hend[(size_t)(bc * D_STATE + n) * INNER + d] = h[n];
    sdtb[(size_t)bc * INNER + d] = sdt;
}

// ---------------- scan fixup: serial prefix over 16 chunks ----------------
__global__ __launch_bounds__(256)
void scan_fix(const float* __restrict__ A_log,
              const float* __restrict__ hend, const float* __restrict__ sdtb,
              float* __restrict__ h0buf)
{
    int idx = blockIdx.x * blockDim.x + threadIdx.x; // < BATCH*INNER
    if (idx >= BATCH * INNER) return;
    int d = idx % INNER;
    int b = idx / INNER;

    float Av[D_STATE], h[D_STATE];
    #pragma unroll
    for (int n = 0; n < D_STATE; ++n) {
        Av[n] = -__expf(A_log[d * D_STATE + n]);
        h[n] = 0.0f;
    }
    for (int c = 0; c < NCHUNK; ++c) {
        int bc = b * NCHUNK + c;
        #pragma unroll
        for (int n = 0; n < D_STATE; ++n)
            h0buf[(size_t)(bc * D_STATE + n) * INNER + d] = h[n];
        float s = sdtb[(size_t)bc * INNER + d];
        #pragma unroll
        for (int n = 0; n < D_STATE; ++n)
            h[n] = fmaf(__expf(Av[n] * s), h[n],
                        hend[(size_t)(bc * D_STATE + n) * INNER + d]);
    }
}

// ---------------- scan pass 2: rerun with correct h0, emit gated output ----------------
__global__ __launch_bounds__(256)
void scan_pass2(const float* __restrict__ dt, const float* __restrict__ u,
                const float* __restrict__ xz,
                const float* __restrict__ A_log, const float* __restrict__ Bp,
                const float* __restrict__ Cp, const float* __restrict__ Dp,
                const float* __restrict__ h0buf, float* __restrict__ yg)
{
    int idx = blockIdx.x * blockDim.x + threadIdx.x;
    int d = idx % INNER;
    int c = (idx / INNER) & (NCHUNK - 1);
    int b = idx / (INNER * NCHUNK);
    int bc = b * NCHUNK + c;

    float Av[D_STATE], Bv[D_STATE], Cv[D_STATE], h[D_STATE];
    #pragma unroll
    for (int n = 0; n < D_STATE; ++n) {
        Av[n] = -__expf(A_log[d * D_STATE + n]);
        Bv[n] = Bp[d * D_STATE + n];
        Cv[n] = Cp[d * D_STATE + n];
        h[n]  = h0buf[(size_t)(bc * D_STATE + n) * INNER + d];
    }
    float Dv = Dp[d];

    int t0 = b * SEQLEN + c * CHUNK;
    for (int j = 0; j < CHUNK; ++j) {
        int t = t0 + j;
        size_t off = (size_t)t * INNER + d;
        float dtv = dt[off];
        float uv  = u[off];
        float du  = dtv * uv;
        float y = 0.0f;
        #pragma unroll
        for (int n = 0; n < D_STATE; ++n) {
            h[n] = fmaf(__expf(dtv * Av[n]), h[n], du * Bv[n]);
            y = fmaf(h[n], Cv[n], y);
        }
        float z = xz[(size_t)t * N2 + INNER + d];
        yg[off] = (y + Dv * uv) * siluf(z);
    }
}

// ---------------- launcher ----------------
extern "C" void kernel_launch(void* const* d_in, const int* in_sizes, int n_in,
                              void* d_out, int out_size)
{
    const float* hidden    = (const float*)d_in[0];
    const float* in_proj_w = (const float*)d_in[1];
    const float* out_proj_w= (const float*)d_in[2];
    const float* dt_proj_w = (const float*)d_in[3];
    const float* dt_proj_b = (const float*)d_in[4];
    const float* conv_w    = (const float*)d_in[5];
    const float* conv_b    = (const float*)d_in[6];
    const float* A_log     = (const float*)d_in[7];
    const float* B_param   = (const float*)d_in[8];
    const float* C_param   = (const float*)d_in[9];
    const float* D_param   = (const float*)d_in[10];
    const float* dt_bias   = (const float*)d_in[11];
    float* out = (float*)d_out;

    float *xz, *u, *dtb, *yg, *hend, *h0, *sdt;
    cudaGetSymbolAddress((void**)&xz,   g_xz);
    cudaGetSymbolAddress((void**)&u,    g_u);
    cudaGetSymbolAddress((void**)&dtb,  g_dt);
    cudaGetSymbolAddress((void**)&yg,   g_yg);
    cudaGetSymbolAddress((void**)&hend, g_hend);
    cudaGetSymbolAddress((void**)&h0,   g_h0);
    cudaGetSymbolAddress((void**)&sdt,  g_sdt);

    // 1) in_proj: xz[4096,3072] = hidden[4096,768] * in_proj_w[3072,768]^T
    {
        dim3 grid(N2 / 128, NTOK / 128);
        sgemm_nt<0><<<grid, 256>>>(hidden, in_proj_w, xz, NTOK, N2, D_MODEL,
                                   nullptr, nullptr);
    }
    // 2) depthwise conv + SiLU -> u
    {
        int n = NTOK * INNER;
        conv_silu_kernel<<<n / 256, 256>>>(xz, conv_w, conv_b, u);
    }
    // 3) dt_proj + softplus: dt[4096,1536] = softplus(u * dt_proj_w^T + b)
    {
        dim3 grid(INNER / 128, NTOK / 128);
        sgemm_nt<1><<<grid, 256>>>(u, dt_proj_w, dtb, NTOK, INNER, INNER,
                                   dt_proj_b, dt_bias);
    }
    // 4) chunked selective scan
    {
        int n1 = BATCH * NCHUNK * INNER;
        scan_pass1<<<n1 / 256, 256>>>(dtb, u, A_log, B_param, hend, sdt);
        scan_fix<<<(BATCH * INNER + 255) / 256, 256>>>(A_log, hend, sdt, h0);
        scan_pass2<<<n1 / 256, 256>>>(dtb, u, xz, A_log, B_param, C_param,
                                      D_param, h0, yg);
    }
    // 5) out_proj: out[4096,768] = yg[4096,1536] * out_proj_w[768,1536]^T
    {
        dim3 grid(D_MODEL / 128, NTOK / 128);
        sgemm_nt<0><<<grid, 256>>>(yg, out_proj_w, out, NTOK, D_MODEL, INNER,
                                   nullptr, nullptr);
    }
}

// round 3
// speedup vs baseline: 1.4132x; 1.4132x over previous
#include <cuda_runtime.h>
#include <math.h>
#include <stdint.h>

// ---------------- problem constants ----------------
#define D_MODEL 768
#define D_STATE 16
#define D_CONV  4
#define INNER   1536
#define N2      (2*INNER)     // 3072
#define BATCH   2
#define SEQLEN  2048
#define NTOK    (BATCH*SEQLEN)  // 4096
#define NCHUNK  16
#define CHUNK   (SEQLEN/NCHUNK) // 128

// ---------------- scratch (static device globals; no allocation) ----------------
__device__ float g_xz  [NTOK * N2];          // in_proj output (proj | gate)
__device__ float g_u   [NTOK * INNER];       // conv+silu output, token-major
__device__ float g_dt  [NTOK * INNER];       // softplus(dt_proj), token-major
__device__ float g_hend[BATCH*NCHUNK*D_STATE*INNER];
__device__ float g_h0  [BATCH*NCHUNK*D_STATE*INNER];
__device__ float g_sdt [BATCH*NCHUNK*INNER];

// tf32 hi/lo splits
__device__ float g_hid_hi[NTOK * D_MODEL];
__device__ float g_hid_lo[NTOK * D_MODEL];
__device__ float g_wi_hi [N2 * D_MODEL];
__device__ float g_wi_lo [N2 * D_MODEL];
__device__ float g_wd_hi [INNER * INNER];
__device__ float g_wd_lo [INNER * INNER];
__device__ float g_wo_hi [D_MODEL * INNER];
__device__ float g_wo_lo [D_MODEL * INNER];
__device__ float g_u_hi  [NTOK * INNER];
__device__ float g_u_lo  [NTOK * INNER];
__device__ float g_yg_hi [NTOK * INNER];
__device__ float g_yg_lo [NTOK * INNER];

// ---------------- helpers ----------------
__device__ __forceinline__ float siluf(float x) {
    return x * (1.0f / (1.0f + __expf(-x)));
}
__device__ __forceinline__ float softplusf(float x) {
    return fmaxf(x, 0.0f) + log1pf(__expf(-fabsf(x)));
}
__device__ __forceinline__ float tf32_round(float v) {
    uint32_t u;
    asm("cvt.rna.tf32.f32 %0, %1;" : "=r"(u) : "f"(v));
    return __uint_as_float(u);
}

__device__ __forceinline__ void cp_async16(void* s, const void* g) {
    uint32_t sa = (uint32_t)__cvta_generic_to_shared(s);
    asm volatile("cp.async.cg.shared.global [%0], [%1], 16;\n" :: "r"(sa), "l"(g));
}
__device__ __forceinline__ void cp_commit() {
    asm volatile("cp.async.commit_group;\n");
}
template<int N> __device__ __forceinline__ void cp_wait() {
    asm volatile("cp.async.wait_group %0;\n" :: "n"(N));
}

__device__ __forceinline__ void mma_tf32(float* d, const float* a, float b0, float b1) {
    asm volatile(
        "mma.sync.aligned.m16n8k8.row.col.f32.tf32.tf32.f32 "
        "{%0,%1,%2,%3}, {%4,%5,%6,%7}, {%8,%9}, {%0,%1,%2,%3};\n"
        : "+f"(d[0]), "+f"(d[1]), "+f"(d[2]), "+f"(d[3])
        : "r"(__float_as_uint(a[0])), "r"(__float_as_uint(a[1])),
          "r"(__float_as_uint(a[2])), "r"(__float_as_uint(a[3])),
          "r"(__float_as_uint(b0)),   "r"(__float_as_uint(b1)));
}

// ---------------- split kernel: x -> (tf32 hi, residual lo) ----------------
__global__ __launch_bounds__(256)
void split_kernel(const float* __restrict__ x, float* __restrict__ hi,
                  float* __restrict__ lo, int n)
{
    int i = blockIdx.x * blockDim.x + threadIdx.x;
    if (i < n) {
        float v = x[i];
        float h = tf32_round(v);
        hi[i] = h;
        lo[i] = v - h;
    }
}

// ---------------- tf32x3 NT GEMM: C[M,N] = A[M,K] * B[N,K]^T ----------------
// BM=BN=128, BK=32, 256 threads (8 warps, each 64x32).
// A,B provided as (hi,lo) tf32 splits; computes hi*hi + hi*lo + lo*hi.
// EPI: 0 = plain store, 1 = softplus(x + b1[col] + b2[col])
#define GSTRIDE 36
#define GTS (128 * GSTRIDE)

template<int EPI>
__global__ __launch_bounds__(256)
void gemm_tf32x3(const float* __restrict__ Ahi, const float* __restrict__ Alo,
                 const float* __restrict__ Bhi, const float* __restrict__ Blo,
                 float* __restrict__ C, int M, int N, int K,
                 const float* __restrict__ b1, const float* __restrict__ b2)
{
    extern __shared__ float sm[];

    const int tid  = threadIdx.x;
    const int wid  = tid >> 5;
    const int lane = tid & 31;
    const int wm   = wid & 1;       // warp row block (0..1) -> rows wm*64
    const int wn   = wid >> 1;      // warp col block (0..3) -> cols wn*32
    const int lr   = lane >> 2;     // 0..7
    const int lc   = lane & 3;      // 0..3

    const int row0 = blockIdx.y * 128;
    const int col0 = blockIdx.x * 128;

    float acc[4][4][4];
    #pragma unroll
    for (int mt = 0; mt < 4; ++mt)
        #pragma unroll
        for (int nt = 0; nt < 4; ++nt)
            #pragma unroll
            for (int r = 0; r < 4; ++r) acc[mt][nt][r] = 0.0f;

    const int KT = K / 32;

    // tile loader: 128 rows x 32 cols fp32 -> smem [row][GSTRIDE]
    auto load_stage = [&](int stage, int k0) {
        float* s = sm + stage * 4 * GTS;
        const float* gp[4] = { Ahi + (size_t)row0 * K + k0,
                               Alo + (size_t)row0 * K + k0,
                               Bhi + (size_t)col0 * K + k0,
                               Blo + (size_t)col0 * K + k0 };
        #pragma unroll
        for (int t = 0; t < 4; ++t) {
            float* dst = s + t * GTS;
            const float* src = gp[t];
            #pragma unroll
            for (int i = 0; i < 4; ++i) {
                int c = tid + i * 256;
                int r = c >> 3, kk = (c & 7) * 4;
                cp_async16(dst + r * GSTRIDE + kk, src + (size_t)r * K + kk);
            }
        }
    };

    load_stage(0, 0);
    cp_commit();

    for (int kt = 0; kt < KT; ++kt) {
        if (kt + 1 < KT) {
            load_stage((kt + 1) & 1, (kt + 1) * 32);
            cp_commit();
            cp_wait<1>();
        } else {
            cp_wait<0>();
        }
        __syncthreads();

        const float* s   = sm + (kt & 1) * 4 * GTS;
        const float* sAh = s;
        const float* sAl = s + GTS;
        const float* sBh = s + 2 * GTS;
        const float* sBl = s + 3 * GTS;

        #pragma unroll
        for (int k8 = 0; k8 < 4; ++k8) {
            const int kc = k8 * 8 + lc;
            float ah[4][4], al[4][4];
            #pragma unroll
            for (int mt = 0; mt < 4; ++mt) {
                const int r = wm * 64 + mt * 16 + lr;
                const float* p = sAh + r * GSTRIDE + kc;
                ah[mt][0] = p[0];
                ah[mt][1] = p[8 * GSTRIDE];
                ah[mt][2] = p[4];
                ah[mt][3] = p[8 * GSTRIDE + 4];
                const float* q = sAl + r * GSTRIDE + kc;
                al[mt][0] = q[0];
                al[mt][1] = q[8 * GSTRIDE];
                al[mt][2] = q[4];
                al[mt][3] = q[8 * GSTRIDE + 4];
            }
            #pragma unroll
            for (int nt = 0; nt < 4; ++nt) {
                const int n = wn * 32 + nt * 8 + lr;
                const float* pb = sBh + n * GSTRIDE + kc;
                float bh0 = pb[0], bh1 = pb[4];
                const float* qb = sBl + n * GSTRIDE + kc;
                float bl0 = qb[0], bl1 = qb[4];
                #pragma unroll
                for (int mt = 0; mt < 4; ++mt) {
                    mma_tf32(acc[mt][nt], ah[mt], bh0, bh1);
                    mma_tf32(acc[mt][nt], ah[mt], bl0, bl1);
                    mma_tf32(acc[mt][nt], al[mt], bh0, bh1);
                }
            }
        }
        __syncthreads();
    }

    // epilogue
    #pragma unroll
    for (int mt = 0; mt < 4; ++mt) {
        #pragma unroll
        for (int nt = 0; nt < 4; ++nt) {
            const int gr = row0 + wm * 64 + mt * 16 + lr;
            const int gc = col0 + wn * 32 + nt * 8 + lc * 2;
            float v0 = acc[mt][nt][0];
            float v1 = acc[mt][nt][1];
            float v2 = acc[mt][nt][2];
            float v3 = acc[mt][nt][3];
            if (EPI == 1) {
                float e0 = b1[gc] + b2[gc];
                float e1 = b1[gc + 1] + b2[gc + 1];
                v0 = softplusf(v0 + e0);
                v1 = softplusf(v1 + e1);
                v2 = softplusf(v2 + e0);
                v3 = softplusf(v3 + e1);
            }
            C[(size_t)gr * N + gc]           = v0;
            C[(size_t)gr * N + gc + 1]       = v1;
            C[(size_t)(gr + 8) * N + gc]     = v2;
            C[(size_t)(gr + 8) * N + gc + 1] = v3;
        }
    }
}

// ---------------- depthwise causal conv(4) + bias + SiLU (+ tf32 split) ----------------
__global__ __launch_bounds__(256)
void conv_silu_kernel(const float* __restrict__ xz,
                      const float* __restrict__ cw,
                      const float* __restrict__ cb,
                      float* __restrict__ u,
                      float* __restrict__ uhi,
                      float* __restrict__ ulo)
{
    int idx = blockIdx.x * blockDim.x + threadIdx.x;
    if (idx >= NTOK * INNER) return;
    int c = idx % INNER;
    int t = idx / INNER;
    int l = t & (SEQLEN - 1);

    float acc = cb[c];
    #pragma unroll
    for (int k = 0; k < D_CONV; ++k) {
        int ll = l - (D_CONV - 1) + k;
        if (ll >= 0)
            acc = fmaf(cw[c * D_CONV + k],
                       xz[(size_t)(t - (D_CONV - 1) + k) * N2 + c], acc);
    }
    float v = siluf(acc);
    u[idx] = v;
    float h = tf32_round(v);
    uhi[idx] = h;
    ulo[idx] = v - h;
}

// ---------------- scan pass 1: per-chunk local scan (h0 = 0) ----------------
__global__ __launch_bounds__(256)
void scan_pass1(const float* __restrict__ dt, const float* __restrict__ u,
                const float* __restrict__ A_log, const float* __restrict__ Bp,
                float* __restrict__ hend, float* __restrict__ sdtb)
{
    int idx = blockIdx.x * blockDim.x + threadIdx.x; // < BATCH*NCHUNK*INNER
    int d = idx % INNER;
    int c = (idx / INNER) & (NCHUNK - 1);
    int b = idx / (INNER * NCHUNK);

    float Av[D_STATE], Bv[D_STATE], h[D_STATE];
    #pragma unroll
    for (int n = 0; n < D_STATE; ++n) {
        Av[n] = -__expf(A_log[d * D_STATE + n]);
        Bv[n] = Bp[d * D_STATE + n];
        h[n]  = 0.0f;
    }
    float sdt = 0.0f;
    int t0 = b * SEQLEN + c * CHUNK;
    for (int j = 0; j < CHUNK; ++j) {
        size_t off = (size_t)(t0 + j) * INNER + d;
        float dtv = dt[off];
        float uv  = u[off];
        sdt += dtv;
        float du = dtv * uv;
        #pragma unroll
        for (int n = 0; n < D_STATE; ++n)
            h[n] = fmaf(__expf(dtv * Av[n]), h[n], du * Bv[n]);
    }
    int bc = b * NCHUNK + c;
    #pragma unroll
    for (int n = 0; n < D_STATE; ++n)
        hend[(size_t)(bc * D_STATE + n) * INNER + d] = h[n];
    sdtb[(size_t)bc * INNER + d] = sdt;
}

// ---------------- scan fixup: serial prefix over 16 chunks ----------------
__global__ __launch_bounds__(256)
void scan_fix(const float* __restrict__ A_log,
              const float* __restrict__ hend, const float* __restrict__ sdtb,
              float* __restrict__ h0buf)
{
    int idx = blockIdx.x * blockDim.x + threadIdx.x; // < BATCH*INNER
    if (idx >= BATCH * INNER) return;
    int d = idx % INNER;
    int b = idx / INNER;

    float Av[D_STATE], h[D_STATE];
    #pragma unroll
    for (int n = 0; n < D_STATE; ++n) {
        Av[n] = -__expf(A_log[d * D_STATE + n]);
        h[n] = 0.0f;
    }
    for (int c = 0; c < NCHUNK; ++c) {
        int bc = b * NCHUNK + c;
        #pragma unroll
        for (int n = 0; n < D_STATE; ++n)
            h0buf[(size_t)(bc * D_STATE + n) * INNER + d] = h[n];
        float s = sdtb[(size_t)bc * INNER + d];
        #pragma unroll
        for (int n = 0; n < D_STATE; ++n)
            h[n] = fmaf(__expf(Av[n] * s), h[n],
                        hend[(size_t)(bc * D_STATE + n) * INNER + d]);
    }
}

// ---------------- scan pass 2: rerun with correct h0, emit gated output (tf32 split) ----------------
__global__ __launch_bounds__(256)
void scan_pass2(const float* __restrict__ dt, const float* __restrict__ u,
                const float* __restrict__ xz,
                const float* __restrict__ A_log, const float* __restrict__ Bp,
                const float* __restrict__ Cp, const float* __restrict__ Dp,
                const float* __restrict__ h0buf,
                float* __restrict__ yghi, float* __restrict__ yglo)
{
    int idx = blockIdx.x * blockDim.x + threadIdx.x;
    int d = idx % INNER;
    int c = (idx / INNER) & (NCHUNK - 1);
    int b = idx / (INNER * NCHUNK);
    int bc = b * NCHUNK + c;

    float Av[D_STATE], Bv[D_STATE], Cv[D_STATE], h[D_STATE];
    #pragma unroll
    for (int n = 0; n < D_STATE; ++n) {
        Av[n] = -__expf(A_log[d * D_STATE + n]);
        Bv[n] = Bp[d * D_STATE + n];
        Cv[n] = Cp[d * D_STATE + n];
        h[n]  = h0buf[(size_t)(bc * D_STATE + n) * INNER + d];
    }
    float Dv = Dp[d];

    int t0 = b * SEQLEN + c * CHUNK;
    for (int j = 0; j < CHUNK; ++j) {
        int t = t0 + j;
        size_t off = (size_t)t * INNER + d;
        float dtv = dt[off];
        float uv  = u[off];
        float du  = dtv * uv;
        float y = 0.0f;
        #pragma unroll
        for (int n = 0; n < D_STATE; ++n) {
            h[n] = fmaf(__expf(dtv * Av[n]), h[n], du * Bv[n]);
            y = fmaf(h[n], Cv[n], y);
        }
        float z = xz[(size_t)t * N2 + INNER + d];
        float v = (y + Dv * uv) * siluf(z);
        float hh = tf32_round(v);
        yghi[off] = hh;
        yglo[off] = v - hh;
    }
}

// ---------------- launcher ----------------
extern "C" void kernel_launch(void* const* d_in, const int* in_sizes, int n_in,
                              void* d_out, int out_size)
{
    const float* hidden    = (const float*)d_in[0];
    const float* in_proj_w = (const float*)d_in[1];
    const float* out_proj_w= (const float*)d_in[2];
    const float* dt_proj_w = (const float*)d_in[3];
    const float* dt_proj_b = (const float*)d_in[4];
    const float* conv_w    = (const float*)d_in[5];
    const float* conv_b    = (const float*)d_in[6];
    const float* A_log     = (const float*)d_in[7];
    const float* B_param   = (const float*)d_in[8];
    const float* C_param   = (const float*)d_in[9];
    const float* D_param   = (const float*)d_in[10];
    const float* dt_bias   = (const float*)d_in[11];
    float* out = (float*)d_out;

    float *xz, *u, *dtb, *hend, *h0, *sdt;
    float *hid_hi, *hid_lo, *wi_hi, *wi_lo, *wd_hi, *wd_lo, *wo_hi, *wo_lo;
    float *u_hi, *u_lo, *yg_hi, *yg_lo;
    cudaGetSymbolAddress((void**)&xz,     g_xz);
    cudaGetSymbolAddress((void**)&u,      g_u);
    cudaGetSymbolAddress((void**)&dtb,    g_dt);
    cudaGetSymbolAddress((void**)&hend,   g_hend);
    cudaGetSymbolAddress((void**)&h0,     g_h0);
    cudaGetSymbolAddress((void**)&sdt,    g_sdt);
    cudaGetSymbolAddress((void**)&hid_hi, g_hid_hi);
    cudaGetSymbolAddress((void**)&hid_lo, g_hid_lo);
    cudaGetSymbolAddress((void**)&wi_hi,  g_wi_hi);
    cudaGetSymbolAddress((void**)&wi_lo,  g_wi_lo);
    cudaGetSymbolAddress((void**)&wd_hi,  g_wd_hi);
    cudaGetSymbolAddress((void**)&wd_lo,  g_wd_lo);
    cudaGetSymbolAddress((void**)&wo_hi,  g_wo_hi);
    cudaGetSymbolAddress((void**)&wo_lo,  g_wo_lo);
    cudaGetSymbolAddress((void**)&u_hi,   g_u_hi);
    cudaGetSymbolAddress((void**)&u_lo,   g_u_lo);
    cudaGetSymbolAddress((void**)&yg_hi,  g_yg_hi);
    cudaGetSymbolAddress((void**)&yg_lo,  g_yg_lo);

    const int SMEM_BYTES = 2 * 4 * GTS * (int)sizeof(float);  // 147456
    cudaFuncSetAttribute(gemm_tf32x3<0>,
                         cudaFuncAttributeMaxDynamicSharedMemorySize, SMEM_BYTES);
    cudaFuncSetAttribute(gemm_tf32x3<1>,
                         cudaFuncAttributeMaxDynamicSharedMemorySize, SMEM_BYTES);

    // 0) tf32 splits of inputs/weights
    split_kernel<<<(NTOK * D_MODEL + 255) / 256, 256>>>(hidden, hid_hi, hid_lo, NTOK * D_MODEL);
    split_kernel<<<(N2 * D_MODEL + 255) / 256, 256>>>(in_proj_w, wi_hi, wi_lo, N2 * D_MODEL);
    split_kernel<<<(INNER * INNER + 255) / 256, 256>>>(dt_proj_w, wd_hi, wd_lo, INNER * INNER);
    split_kernel<<<(D_MODEL * INNER + 255) / 256, 256>>>(out_proj_w, wo_hi, wo_lo, D_MODEL * INNER);

    // 1) in_proj: xz[4096,3072] = hidden[4096,768] * in_proj_w[3072,768]^T
    {
        dim3 grid(N2 / 128, NTOK / 128);
        gemm_tf32x3<0><<<grid, 256, SMEM_BYTES>>>(hid_hi, hid_lo, wi_hi, wi_lo,
                                                  xz, NTOK, N2, D_MODEL,
                                                  nullptr, nullptr);
    }
    // 2) depthwise conv + SiLU -> u (+ split)
    {
        int n = NTOK * INNER;
        conv_silu_kernel<<<n / 256, 256>>>(xz, conv_w, conv_b, u, u_hi, u_lo);
    }
    // 3) dt_proj + softplus
    {
        dim3 grid(INNER / 128, NTOK / 128);
        gemm_tf32x3<1><<<grid, 256, SMEM_BYTES>>>(u_hi, u_lo, wd_hi, wd_lo,
                                                  dtb, NTOK, INNER, INNER,
                                                  dt_proj_b, dt_bias);
    }
    // 4) chunked selective scan
    {
        int n1 = BATCH * NCHUNK * INNER;
        scan_pass1<<<n1 / 256, 256>>>(dtb, u, A_log, B_param, hend, sdt);
        scan_fix<<<(BATCH * INNER + 255) / 256, 256>>>(A_log, hend, sdt, h0);
        scan_pass2<<<n1 / 256, 256>>>(dtb, u, xz, A_log, B_param, C_param,
                                      D_param, h0, yg_hi, yg_lo);
    }
    // 5) out_proj: out[4096,768] = yg[4096,1536] * out_proj_w[768,1536]^T
    {
        dim3 grid(D_MODEL / 128, NTOK / 128);
        gemm_tf32x3<0><<<grid, 256, SMEM_BYTES>>>(yg_hi, yg_lo, wo_hi, wo_lo,
                                                  out, NTOK, D_MODEL, INNER,
                                                  nullptr, nullptr);
    }
}

// round 4
// speedup vs baseline: 1.4233x; 1.0072x over previous
#include <cuda_runtime.h>
#include <math.h>
#include <stdint.h>

// ---------------- problem constants ----------------
#define D_MODEL 768
#define D_STATE 16
#define D_CONV  4
#define INNER   1536
#define N2      (2*INNER)     // 3072
#define BATCH   2
#define SEQLEN  2048
#define NTOK    (BATCH*SEQLEN)  // 4096
#define NCHUNK  16
#define CHUNK   (SEQLEN/NCHUNK) // 128

// ---------------- scratch (static device globals; no allocation) ----------------
__device__ float g_xz  [NTOK * N2];          // in_proj output (proj | gate)
__device__ float g_u   [NTOK * INNER];       // conv+silu output, token-major
__device__ float g_dt  [NTOK * INNER];       // softplus(dt_proj), token-major
__device__ float g_hend[BATCH*NCHUNK*D_STATE*INNER];
__device__ float g_h0  [BATCH*NCHUNK*D_STATE*INNER];
__device__ float g_sdt [BATCH*NCHUNK*INNER];

// tf32 hi/lo splits
__device__ float g_hid_hi[NTOK * D_MODEL];
__device__ float g_hid_lo[NTOK * D_MODEL];
__device__ float g_wi_hi [N2 * D_MODEL];
__device__ float g_wi_lo [N2 * D_MODEL];
__device__ float g_wd_hi [INNER * INNER];
__device__ float g_wd_lo [INNER * INNER];
__device__ float g_wo_hi [D_MODEL * INNER];
__device__ float g_wo_lo [D_MODEL * INNER];
__device__ float g_u_hi  [NTOK * INNER];
__device__ float g_u_lo  [NTOK * INNER];
__device__ float g_yg_hi [NTOK * INNER];
__device__ float g_yg_lo [NTOK * INNER];

// ---------------- helpers ----------------
__device__ __forceinline__ float siluf(float x) {
    return x * (1.0f / (1.0f + __expf(-x)));
}
__device__ __forceinline__ float softplusf(float x) {
    return fmaxf(x, 0.0f) + log1pf(__expf(-fabsf(x)));
}
__device__ __forceinline__ float tf32_round(float v) {
    uint32_t u;
    asm("cvt.rna.tf32.f32 %0, %1;" : "=r"(u) : "f"(v));
    return __uint_as_float(u);
}

__device__ __forceinline__ void cp_async16(void* s, const void* g) {
    uint32_t sa = (uint32_t)__cvta_generic_to_shared(s);
    asm volatile("cp.async.cg.shared.global [%0], [%1], 16;\n" :: "r"(sa), "l"(g));
}
__device__ __forceinline__ void cp_commit() {
    asm volatile("cp.async.commit_group;\n");
}
template<int N> __device__ __forceinline__ void cp_wait() {
    asm volatile("cp.async.wait_group %0;\n" :: "n"(N));
}

__device__ __forceinline__ void mma_tf32(float* d, const float* a, float b0, float b1) {
    asm volatile(
        "mma.sync.aligned.m16n8k8.row.col.f32.tf32.tf32.f32 "
        "{%0,%1,%2,%3}, {%4,%5,%6,%7}, {%8,%9}, {%0,%1,%2,%3};\n"
        : "+f"(d[0]), "+f"(d[1]), "+f"(d[2]), "+f"(d[3])
        : "r"(__float_as_uint(a[0])), "r"(__float_as_uint(a[1])),
          "r"(__float_as_uint(a[2])), "r"(__float_as_uint(a[3])),
          "r"(__float_as_uint(b0)),   "r"(__float_as_uint(b1)));
}

// ---------------- split kernel: x -> (tf32 hi, residual lo) ----------------
__global__ __launch_bounds__(256)
void split_kernel(const float* __restrict__ x, float* __restrict__ hi,
                  float* __restrict__ lo, int n)
{
    int i = blockIdx.x * blockDim.x + threadIdx.x;
    if (i < n) {
        float v = x[i];
        float h = tf32_round(v);
        hi[i] = h;
        lo[i] = v - h;
    }
}

// ---------------- tf32x3 NT GEMM: C[M,N] = A[M,K] * B[N,K]^T ----------------
// BM=BN=128, BK=32, 256 threads (8 warps, each 64x32).
// A,B provided as (hi,lo) tf32 splits; computes hi*hi + hi*lo + lo*hi.
// EPI: 0 = plain store, 1 = softplus(x + b1[col] + b2[col])
#define GSTRIDE 36
#define GTS (128 * GSTRIDE)

template<int EPI>
__global__ __launch_bounds__(256)
void gemm_tf32x3(const float* __restrict__ Ahi, const float* __restrict__ Alo,
                 const float* __restrict__ Bhi, const float* __restrict__ Blo,
                 float* __restrict__ C, int M, int N, int K,
                 const float* __restrict__ b1, const float* __restrict__ b2)
{
    extern __shared__ float sm[];

    const int tid  = threadIdx.x;
    const int wid  = tid >> 5;
    const int lane = tid & 31;
    const int wm   = wid & 1;       // warp row block (0..1) -> rows wm*64
    const int wn   = wid >> 1;      // warp col block (0..3) -> cols wn*32
    const int lr   = lane >> 2;     // 0..7
    const int lc   = lane & 3;      // 0..3

    const int row0 = blockIdx.y * 128;
    const int col0 = blockIdx.x * 128;

    float acc[4][4][4];
    #pragma unroll
    for (int mt = 0; mt < 4; ++mt)
        #pragma unroll
        for (int nt = 0; nt < 4; ++nt)
            #pragma unroll
            for (int r = 0; r < 4; ++r) acc[mt][nt][r] = 0.0f;

    const int KT = K / 32;

    // tile loader: 128 rows x 32 cols fp32 -> smem [row][GSTRIDE]
    auto load_stage = [&](int stage, int k0) {
        float* s = sm + stage * 4 * GTS;
        const float* gp[4] = { Ahi + (size_t)row0 * K + k0,
                               Alo + (size_t)row0 * K + k0,
                               Bhi + (size_t)col0 * K + k0,
                               Blo + (size_t)col0 * K + k0 };
        #pragma unroll
        for (int t = 0; t < 4; ++t) {
            float* dst = s + t * GTS;
            const float* src = gp[t];
            #pragma unroll
            for (int i = 0; i < 4; ++i) {
                int c = tid + i * 256;
                int r = c >> 3, kk = (c & 7) * 4;
                cp_async16(dst + r * GSTRIDE + kk, src + (size_t)r * K + kk);
            }
        }
    };

    load_stage(0, 0);
    cp_commit();

    for (int kt = 0; kt < KT; ++kt) {
        if (kt + 1 < KT) {
            load_stage((kt + 1) & 1, (kt + 1) * 32);
            cp_commit();
            cp_wait<1>();
        } else {
            cp_wait<0>();
        }
        __syncthreads();

        const float* s   = sm + (kt & 1) * 4 * GTS;
        const float* sAh = s;
        const float* sAl = s + GTS;
        const float* sBh = s + 2 * GTS;
        const float* sBl = s + 3 * GTS;

        #pragma unroll
        for (int k8 = 0; k8 < 4; ++k8) {
            const int kc = k8 * 8 + lc;
            float ah[4][4], al[4][4];
            #pragma unroll
            for (int mt = 0; mt < 4; ++mt) {
                const int r = wm * 64 + mt * 16 + lr;
                const float* p = sAh + r * GSTRIDE + kc;
                ah[mt][0] = p[0];
                ah[mt][1] = p[8 * GSTRIDE];
                ah[mt][2] = p[4];
                ah[mt][3] = p[8 * GSTRIDE + 4];
                const float* q = sAl + r * GSTRIDE + kc;
                al[mt][0] = q[0];
                al[mt][1] = q[8 * GSTRIDE];
                al[mt][2] = q[4];
                al[mt][3] = q[8 * GSTRIDE + 4];
            }
            #pragma unroll
            for (int nt = 0; nt < 4; ++nt) {
                const int n = wn * 32 + nt * 8 + lr;
                const float* pb = sBh + n * GSTRIDE + kc;
                float bh0 = pb[0], bh1 = pb[4];
                const float* qb = sBl + n * GSTRIDE + kc;
                float bl0 = qb[0], bl1 = qb[4];
                #pragma unroll
                for (int mt = 0; mt < 4; ++mt) {
                    mma_tf32(acc[mt][nt], ah[mt], bh0, bh1);
                    mma_tf32(acc[mt][nt], ah[mt], bl0, bl1);
                    mma_tf32(acc[mt][nt], al[mt], bh0, bh1);
                }
            }
        }
        __syncthreads();
    }

    // epilogue
    #pragma unroll
    for (int mt = 0; mt < 4; ++mt) {
        #pragma unroll
        for (int nt = 0; nt < 4; ++nt) {
            const int gr = row0 + wm * 64 + mt * 16 + lr;
            const int gc = col0 + wn * 32 + nt * 8 + lc * 2;
            float v0 = acc[mt][nt][0];
            float v1 = acc[mt][nt][1];
            float v2 = acc[mt][nt][2];
            float v3 = acc[mt][nt][3];
            if (EPI == 1) {
                float e0 = b1[gc] + b2[gc];
                float e1 = b1[gc + 1] + b2[gc + 1];
                v0 = softplusf(v0 + e0);
                v1 = softplusf(v1 + e1);
                v2 = softplusf(v2 + e0);
                v3 = softplusf(v3 + e1);
            }
            C[(size_t)gr * N + gc]           = v0;
            C[(size_t)gr * N + gc + 1]       = v1;
            C[(size_t)(gr + 8) * N + gc]     = v2;
            C[(size_t)(gr + 8) * N + gc + 1] = v3;
        }
    }
}

// ---------------- depthwise causal conv(4) + bias + SiLU (+ tf32 split) ----------------
__global__ __launch_bounds__(256)
void conv_silu_kernel(const float* __restrict__ xz,
                      const float* __restrict__ cw,
                      const float* __restrict__ cb,
                      float* __restrict__ u,
                      float* __restrict__ uhi,
                      float* __restrict__ ulo)
{
    int idx = blockIdx.x * blockDim.x + threadIdx.x;
    if (idx >= NTOK * INNER) return;
    int c = idx % INNER;
    int t = idx / INNER;
    int l = t & (SEQLEN - 1);

    float acc = cb[c];
    #pragma unroll
    for (int k = 0; k < D_CONV; ++k) {
        int ll = l - (D_CONV - 1) + k;
        if (ll >= 0)
            acc = fmaf(cw[c * D_CONV + k],
                       xz[(size_t)(t - (D_CONV - 1) + k) * N2 + c], acc);
    }
    float v = siluf(acc);
    u[idx] = v;
    float h = tf32_round(v);
    uhi[idx] = h;
    ulo[idx] = v - h;
}

// ---------------- scan pass 1: per-chunk local scan (h0 = 0) ----------------
__global__ __launch_bounds__(256)
void scan_pass1(const float* __restrict__ dt, const float* __restrict__ u,
                const float* __restrict__ A_log, const float* __restrict__ Bp,
                float* __restrict__ hend, float* __restrict__ sdtb)
{
    int idx = blockIdx.x * blockDim.x + threadIdx.x; // < BATCH*NCHUNK*INNER
    int d = idx % INNER;
    int c = (idx / INNER) & (NCHUNK - 1);
    int b = idx / (INNER * NCHUNK);

    float Av[D_STATE], Bv[D_STATE], h[D_STATE];
    #pragma unroll
    for (int n = 0; n < D_STATE; ++n) {
        Av[n] = -__expf(A_log[d * D_STATE + n]);
        Bv[n] = Bp[d * D_STATE + n];
        h[n]  = 0.0f;
    }
    float sdt = 0.0f;
    int t0 = b * SEQLEN + c * CHUNK;
    for (int j = 0; j < CHUNK; ++j) {
        size_t off = (size_t)(t0 + j) * INNER + d;
        float dtv = dt[off];
        float uv  = u[off];
        sdt += dtv;
        float du = dtv * uv;
        #pragma unroll
        for (int n = 0; n < D_STATE; ++n)
            h[n] = fmaf(__expf(dtv * Av[n]), h[n], du * Bv[n]);
    }
    int bc = b * NCHUNK + c;
    #pragma unroll
    for (int n = 0; n < D_STATE; ++n)
        hend[(size_t)(bc * D_STATE + n) * INNER + d] = h[n];
    sdtb[(size_t)bc * INNER + d] = sdt;
}

// ---------------- scan fixup: serial prefix over 16 chunks ----------------
__global__ __launch_bounds__(256)
void scan_fix(const float* __restrict__ A_log,
              const float* __restrict__ hend, const float* __restrict__ sdtb,
              float* __restrict__ h0buf)
{
    int idx = blockIdx.x * blockDim.x + threadIdx.x; // < BATCH*INNER
    if (idx >= BATCH * INNER) return;
    int d = idx % INNER;
    int b = idx / INNER;

    float Av[D_STATE], h[D_STATE];
    #pragma unroll
    for (int n = 0; n < D_STATE; ++n) {
        Av[n] = -__expf(A_log[d * D_STATE + n]);
        h[n] = 0.0f;
    }
    for (int c = 0; c < NCHUNK; ++c) {
        int bc = b * NCHUNK + c;
        #pragma unroll
        for (int n = 0; n < D_STATE; ++n)
            h0buf[(size_t)(bc * D_STATE + n) * INNER + d] = h[n];
        float s = sdtb[(size_t)bc * INNER + d];
        #pragma unroll
        for (int n = 0; n < D_STATE; ++n)
            h[n] = fmaf(__expf(Av[n] * s), h[n],
                        hend[(size_t)(bc * D_STATE + n) * INNER + d]);
    }
}

// ---------------- scan pass 2: rerun with correct h0, emit gated output (tf32 split) ----------------
__global__ __launch_bounds__(256)
void scan_pass2(const float* __restrict__ dt, const float* __restrict__ u,
                const float* __restrict__ xz,
                const float* __restrict__ A_log, const float* __restrict__ Bp,
                const float* __restrict__ Cp, const float* __restrict__ Dp,
                const float* __restrict__ h0buf,
                float* __restrict__ yghi, float* __restrict__ yglo)
{
    int idx = blockIdx.x * blockDim.x + threadIdx.x;
    int d = idx % INNER;
    int c = (idx / INNER) & (NCHUNK - 1);
    int b = idx / (INNER * NCHUNK);
    int bc = b * NCHUNK + c;

    float Av[D_STATE], Bv[D_STATE], Cv[D_STATE], h[D_STATE];
    #pragma unroll
    for (int n = 0; n < D_STATE; ++n) {
        Av[n] = -__expf(A_log[d * D_STATE + n]);
        Bv[n] = Bp[d * D_STATE + n];
        Cv[n] = Cp[d * D_STATE + n];
        h[n]  = h0buf[(size_t)(bc * D_STATE + n) * INNER + d];
    }
    float Dv = Dp[d];

    int t0 = b * SEQLEN + c * CHUNK;
    for (int j = 0; j < CHUNK; ++j) {
        int t = t0 + j;
        size_t off = (size_t)t * INNER + d;
        float dtv = dt[off];
        float uv  = u[off];
        float du  = dtv * uv;
        float y = 0.0f;
        #pragma unroll
        for (int n = 0; n < D_STATE; ++n) {
            h[n] = fmaf(__expf(dtv * Av[n]), h[n], du * Bv[n]);
            y = fmaf(h[n], Cv[n], y);
        }
        float z = xz[(size_t)t * N2 + INNER + d];
        float v = (y + Dv * uv) * siluf(z);
        float hh = tf32_round(v);
        yghi[off] = hh;
        yglo[off] = v - hh;
    }
}

// ---------------- launcher ----------------
extern "C" void kernel_launch(void* const* d_in, const int* in_sizes, int n_in,
                              void* d_out, int out_size)
{
    const float* hidden    = (const float*)d_in[0];
    const float* in_proj_w = (const float*)d_in[1];
    const float* out_proj_w= (const float*)d_in[2];
    const float* dt_proj_w = (const float*)d_in[3];
    const float* dt_proj_b = (const float*)d_in[4];
    const float* conv_w    = (const float*)d_in[5];
    const float* conv_b    = (const float*)d_in[6];
    const float* A_log     = (const float*)d_in[7];
    const float* B_param   = (const float*)d_in[8];
    const float* C_param   = (const float*)d_in[9];
    const float* D_param   = (const float*)d_in[10];
    const float* dt_bias   = (const float*)d_in[11];
    float* out = (float*)d_out;

    float *xz, *u, *dtb, *hend, *h0, *sdt;
    float *hid_hi, *hid_lo, *wi_hi, *wi_lo, *wd_hi, *wd_lo, *wo_hi, *wo_lo;
    float *u_hi, *u_lo, *yg_hi, *yg_lo;
    cudaGetSymbolAddress((void**)&xz,     g_xz);
    cudaGetSymbolAddress((void**)&u,      g_u);
    cudaGetSymbolAddress((void**)&dtb,    g_dt);
    cudaGetSymbolAddress((void**)&hend,   g_hend);
    cudaGetSymbolAddress((void**)&h0,     g_h0);
    cudaGetSymbolAddress((void**)&sdt,    g_sdt);
    cudaGetSymbolAddress((void**)&hid_hi, g_hid_hi);
    cudaGetSymbolAddress((void**)&hid_lo, g_hid_lo);
    cudaGetSymbolAddress((void**)&wi_hi,  g_wi_hi);
    cudaGetSymbolAddress((void**)&wi_lo,  g_wi_lo);
    cudaGetSymbolAddress((void**)&wd_hi,  g_wd_hi);
    cudaGetSymbolAddress((void**)&wd_lo,  g_wd_lo);
    cudaGetSymbolAddress((void**)&wo_hi,  g_wo_hi);
    cudaGetSymbolAddress((void**)&wo_lo,  g_wo_lo);
    cudaGetSymbolAddress((void**)&u_hi,   g_u_hi);
    cudaGetSymbolAddress((void**)&u_lo,   g_u_lo);
    cudaGetSymbolAddress((void**)&yg_hi,  g_yg_hi);
    cudaGetSymbolAddress((void**)&yg_lo,  g_yg_lo);

    const int SMEM_BYTES = 2 * 4 * GTS * (int)sizeof(float);  // 147456
    cudaFuncSetAttribute(gemm_tf32x3<0>,
                         cudaFuncAttributeMaxDynamicSharedMemorySize, SMEM_BYTES);
    cudaFuncSetAttribute(gemm_tf32x3<1>,
                         cudaFuncAttributeMaxDynamicSharedMemorySize, SMEM_BYTES);

    // 0) tf32 splits of inputs/weights
    split_kernel<<<(NTOK * D_MODEL + 255) / 256, 256>>>(hidden, hid_hi, hid_lo, NTOK * D_MODEL);
    split_kernel<<<(N2 * D_MODEL + 255) / 256, 256>>>(in_proj_w, wi_hi, wi_lo, N2 * D_MODEL);
    split_kernel<<<(INNER * INNER + 255) / 256, 256>>>(dt_proj_w, wd_hi, wd_lo, INNER * INNER);
    split_kernel<<<(D_MODEL * INNER + 255) / 256, 256>>>(out_proj_w, wo_hi, wo_lo, D_MODEL * INNER);

    // 1) in_proj: xz[4096,3072] = hidden[4096,768] * in_proj_w[3072,768]^T
    {
        dim3 grid(N2 / 128, NTOK / 128);
        gemm_tf32x3<0><<<grid, 256, SMEM_BYTES>>>(hid_hi, hid_lo, wi_hi, wi_lo,
                                                  xz, NTOK, N2, D_MODEL,
                                                  nullptr, nullptr);
    }
    // 2) depthwise conv + SiLU -> u (+ split)
    {
        int n = NTOK * INNER;
        conv_silu_kernel<<<n / 256, 256>>>(xz, conv_w, conv_b, u, u_hi, u_lo);
    }
    // 3) dt_proj + softplus
    {
        dim3 grid(INNER / 128, NTOK / 128);
        gemm_tf32x3<1><<<grid, 256, SMEM_BYTES>>>(u_hi, u_lo, wd_hi, wd_lo,
                                                  dtb, NTOK, INNER, INNER,
                                                  dt_proj_b, dt_bias);
    }
    // 4) chunked selective scan
    {
        int n1 = BATCH * NCHUNK * INNER;
        scan_pass1<<<n1 / 256, 256>>>(dtb, u, A_log, B_param, hend, sdt);
        scan_fix<<<(BATCH * INNER + 255) / 256, 256>>>(A_log, hend, sdt, h0);
        scan_pass2<<<n1 / 256, 256>>>(dtb, u, xz, A_log, B_param, C_param,
                                      D_param, h0, yg_hi, yg_lo);
    }
    // 5) out_proj: out[4096,768] = yg[4096,1536] * out_proj_w[768,1536]^T
    {
        dim3 grid(D_MODEL / 128, NTOK / 128);
        gemm_tf32x3<0><<<grid, 256, SMEM_BYTES>>>(yg_hi, yg_lo, wo_hi, wo_lo,
                                                  out, NTOK, D_MODEL, INNER,
                                                  nullptr, nullptr);
    }
}

// round 7
// speedup vs baseline: 2.3316x; 1.6381x over previous
#include <cuda_runtime.h>
#include <cuda_fp16.h>
#include <math.h>
#include <stdint.h>

// ---------------- problem constants ----------------
#define D_MODEL 768
#define D_STATE 16
#define D_CONV  4
#define INNER   1536
#define N2      (2*INNER)     // 3072
#define BATCH   2
#define SEQLEN  2048
#define NTOK    (BATCH*SEQLEN)  // 4096
#define NCHUNK  64
#define CHUNK   (SEQLEN/NCHUNK) // 32

// ---------------- scratch (static device globals; no allocation) ----------------
__device__ float g_xz  [NTOK * N2];
__device__ float g_u   [NTOK * INNER];
__device__ float g_dt  [NTOK * INNER];
__device__ float g_hend[BATCH*NCHUNK*D_STATE*INNER];
__device__ float g_h0  [BATCH*NCHUNK*D_STATE*INNER];
__device__ float g_sdt [BATCH*NCHUNK*INNER];

// fp16 hi/lo splits
__device__ __half g_hid_hi[NTOK * D_MODEL];
__device__ __half g_hid_lo[NTOK * D_MODEL];
__device__ __half g_wi_hi [N2 * D_MODEL];
__device__ __half g_wi_lo [N2 * D_MODEL];
__device__ __half g_wd_hi [INNER * INNER];
__device__ __half g_wd_lo [INNER * INNER];
__device__ __half g_wo_hi [D_MODEL * INNER];
__device__ __half g_wo_lo [D_MODEL * INNER];
__device__ __half g_u_hi  [NTOK * INNER];
__device__ __half g_u_lo  [NTOK * INNER];
__device__ __half g_yg_hi [NTOK * INNER];
__device__ __half g_yg_lo [NTOK * INNER];

// ---------------- helpers ----------------
__device__ __forceinline__ float siluf(float x) {
    return x * (1.0f / (1.0f + __expf(-x)));
}
__device__ __forceinline__ float softplusf(float x) {
    return fmaxf(x, 0.0f) + log1pf(__expf(-fabsf(x)));
}
__device__ __forceinline__ uint32_t smem_u32(const void* p) {
    uint32_t a;
    asm("{ .reg .u64 t; cvta.to.shared.u64 t, %1; cvt.u32.u64 %0, t; }"
        : "=r"(a) : "l"(p));
    return a;
}
__device__ __forceinline__ void cp16(uint32_t s, const void* g) {
    asm volatile("cp.async.cg.shared.global [%0], [%1], 16;\n" :: "r"(s), "l"(g));
}
__device__ __forceinline__ void cp_commit() {
    asm volatile("cp.async.commit_group;\n");
}
template<int N> __device__ __forceinline__ void cp_wait() {
    asm volatile("cp.async.wait_group %0;\n" :: "n"(N));
}
__device__ __forceinline__ void ldm_x4(uint32_t a, uint32_t* r) {
    asm volatile("ldmatrix.sync.aligned.m8n8.x4.shared.b16 {%0,%1,%2,%3}, [%4];"
                 : "=r"(r[0]), "=r"(r[1]), "=r"(r[2]), "=r"(r[3]) : "r"(a));
}
__device__ __forceinline__ void mma_fp16(float* d, const uint32_t* a,
                                         uint32_t b0, uint32_t b1) {
    asm volatile(
        "mma.sync.aligned.m16n8k16.row.col.f32.f16.f16.f32 "
        "{%0,%1,%2,%3}, {%4,%5,%6,%7}, {%8,%9}, {%0,%1,%2,%3};\n"
        : "+f"(d[0]), "+f"(d[1]), "+f"(d[2]), "+f"(d[3])
        : "r"(a[0]), "r"(a[1]), "r"(a[2]), "r"(a[3]), "r"(b0), "r"(b1));
}

// ---------------- split kernel: fp32 -> (fp16 hi, fp16 lo) ----------------
__global__ __launch_bounds__(256)
void split_kernel(const float* __restrict__ x, __half* __restrict__ hi,
                  __half* __restrict__ lo, int n)
{
    int i = blockIdx.x * blockDim.x + threadIdx.x;
    if (i < n) {
        float v = x[i];
        __half h = __float2half_rn(v);
        hi[i] = h;
        lo[i] = __float2half_rn(v - __half2float(h));
    }
}

// ---------------- fp16x3 NT GEMM: C[M,N] = A[M,K]*B[N,K]^T ----------------
// BM=BN=128, BK=64 halves (128B rows). 8 warps, warptile 64x32.
// Tiles in smem: [stage][Ahi,Alo,Bhi,Blo][128 rows][8 x 16B chunks], chunk XOR-swizzled.
// EPI: 0 plain, 1 softplus(x + b1[col] + b2[col])
#define TILE_B 16384
#define GEMM_SMEM (8 * TILE_B)   // 131072

template<int EPI>
__global__ __launch_bounds__(256)
void gemm_fp16x3(const __half* __restrict__ Ahi, const __half* __restrict__ Alo,
                 const __half* __restrict__ Bhi, const __half* __restrict__ Blo,
                 float* __restrict__ C, int M, int N, int K,
                 const float* __restrict__ b1, const float* __restrict__ b2)
{
    extern __shared__ char smem[];
    const uint32_t sb = smem_u32(smem);

    const int tid  = threadIdx.x;
    const int wid  = tid >> 5;
    const int lane = tid & 31;
    const int wm   = wid & 1;     // rows wm*64
    const int wn   = wid >> 1;    // cols wn*32
    const int g    = lane >> 3;   // ldmatrix lane group 0..3
    const int lr   = lane & 7;

    const int row0 = blockIdx.y * 128;
    const int col0 = blockIdx.x * 128;

    const __half* srcs[4] = {
        Ahi + (size_t)row0 * K, Alo + (size_t)row0 * K,
        Bhi + (size_t)col0 * K, Blo + (size_t)col0 * K };

    float acc[4][4][4];
    #pragma unroll
    for (int mt = 0; mt < 4; ++mt)
        #pragma unroll
        for (int nt = 0; nt < 4; ++nt)
            #pragma unroll
            for (int r = 0; r < 4; ++r) acc[mt][nt][r] = 0.0f;

    auto load_stage = [&](int s, int kc) {
        #pragma unroll
        for (int t = 0; t < 4; ++t) {
            uint32_t dst = sb + (uint32_t)(s * 4 + t) * TILE_B;
            const __half* src = srcs[t] + kc;
            #pragma unroll
            for (int i = 0; i < 4; ++i) {
                int c = tid + i * 256;
                int r = c >> 3, ch = c & 7;
                cp16(dst + r * 128 + ((ch ^ (r & 7)) << 4),
                     src + (size_t)r * K + ch * 8);
            }
        }
    };

    const int KT = K / 64;
    load_stage(0, 0);
    cp_commit();

    for (int kt = 0; kt < KT; ++kt) {
        if (kt + 1 < KT) {
            load_stage((kt + 1) & 1, (kt + 1) * 64);
            cp_commit();
            cp_wait<1>();
        } else {
            cp_wait<0>();
        }
        __syncthreads();

        const uint32_t st = sb + (uint32_t)(kt & 1) * 4 * TILE_B;
        const uint32_t sAh = st, sAl = st + TILE_B;
        const uint32_t sBh = st + 2 * TILE_B, sBl = st + 3 * TILE_B;

        #pragma unroll
        for (int k16 = 0; k16 < 4; ++k16) {
            const int c0 = k16 * 2;
            // A lane mapping: mats {m0-7@c0, m8-15@c0, m0-7@c1, m8-15@c1}
            const int arow_off = ((g & 1) << 3) + lr;
            const int ach = c0 + (g >> 1);
            // B lane mapping: mats {n0-7@c0, n0-7@c1, n8-15@c0, n8-15@c1}
            const int brow_off = ((g >> 1) << 3) + lr;
            const int bch = c0 + (g & 1);

            uint32_t ah[4][4], al[4][4];
            #pragma unroll
            for (int mt = 0; mt < 4; ++mt) {
                int row = wm * 64 + mt * 16 + arow_off;
                uint32_t off = row * 128 + (((ach ^ (row & 7))) << 4);
                ldm_x4(sAh + off, ah[mt]);
                ldm_x4(sAl + off, al[mt]);
            }
            uint32_t bh[4][2], bl[4][2];
            #pragma unroll
            for (int nn = 0; nn < 2; ++nn) {
                int row = wn * 32 + nn * 16 + brow_off;
                uint32_t off = row * 128 + (((bch ^ (row & 7))) << 4);
                uint32_t t4[4];
                ldm_x4(sBh + off, t4);
                bh[nn*2][0] = t4[0]; bh[nn*2][1] = t4[1];
                bh[nn*2+1][0] = t4[2]; bh[nn*2+1][1] = t4[3];
                ldm_x4(sBl + off, t4);
                bl[nn*2][0] = t4[0]; bl[nn*2][1] = t4[1];
                bl[nn*2+1][0] = t4[2]; bl[nn*2+1][1] = t4[3];
            }
            #pragma unroll
            for (int mt = 0; mt < 4; ++mt)
                #pragma unroll
                for (int nt = 0; nt < 4; ++nt) {
                    mma_fp16(acc[mt][nt], ah[mt], bh[nt][0], bh[nt][1]);
                    mma_fp16(acc[mt][nt], ah[mt], bl[nt][0], bl[nt][1]);
                    mma_fp16(acc[mt][nt], al[mt], bh[nt][0], bh[nt][1]);
                }
        }
        __syncthreads();
    }

    // epilogue: direct register -> gmem (float2 per pair)
    const int qr = lane >> 2;          // 0..7
    const int qc = (lane & 3) * 2;     // 0,2,4,6
    #pragma unroll
    for (int mt = 0; mt < 4; ++mt) {
        #pragma unroll
        for (int nt = 0; nt < 4; ++nt) {
            int gr = row0 + wm * 64 + mt * 16 + qr;
            int gc = col0 + wn * 32 + nt * 8 + qc;
            float v0 = acc[mt][nt][0], v1 = acc[mt][nt][1];
            float v2 = acc[mt][nt][2], v3 = acc[mt][nt][3];
            if (EPI == 1) {
                float e0 = b1[gc] + b2[gc];
                float e1 = b1[gc + 1] + b2[gc + 1];
                v0 = softplusf(v0 + e0); v1 = softplusf(v1 + e1);
                v2 = softplusf(v2 + e0); v3 = softplusf(v3 + e1);
            }
            *(float2*)&C[(size_t)gr * N + gc]       = make_float2(v0, v1);
            *(float2*)&C[(size_t)(gr + 8) * N + gc] = make_float2(v2, v3);
        }
    }
}

// ---------------- depthwise causal conv(4) + bias + SiLU (+ fp16 split) ----------------
__global__ __launch_bounds__(256)
void conv_silu_kernel(const float* __restrict__ xz,
                      const float* __restrict__ cw,
                      const float* __restrict__ cb,
                      float* __restrict__ u,
                      __half* __restrict__ uhi,
                      __half* __restrict__ ulo)
{
    int idx = blockIdx.x * blockDim.x + threadIdx.x;
    if (idx >= NTOK * INNER) return;
    int c = idx % INNER;
    int t = idx / INNER;
    int l = t & (SEQLEN - 1);

    float acc = cb[c];
    #pragma unroll
    for (int k = 0; k < D_CONV; ++k) {
        int ll = l - (D_CONV - 1) + k;
        if (ll >= 0)
            acc = fmaf(cw[c * D_CONV + k],
                       xz[(size_t)(t - (D_CONV - 1) + k) * N2 + c], acc);
    }
    float v = siluf(acc);
    u[idx] = v;
    __half h = __float2half_rn(v);
    uhi[idx] = h;
    ulo[idx] = __float2half_rn(v - __half2float(h));
}

// ---------------- scan pass 1: per-chunk local scan (h0 = 0) ----------------
__global__ __launch_bounds__(256)
void scan_pass1(const float* __restrict__ dt, const float* __restrict__ u,
                const float* __restrict__ A_log, const float* __restrict__ Bp,
                float* __restrict__ hend, float* __restrict__ sdtb)
{
    int idx = blockIdx.x * blockDim.x + threadIdx.x;
    int d = idx % INNER;
    int c = (idx / INNER) & (NCHUNK - 1);
    int b = idx / (INNER * NCHUNK);

    float Av[D_STATE], Bv[D_STATE], h[D_STATE];
    #pragma unroll
    for (int n = 0; n < D_STATE; ++n) {
        Av[n] = -__expf(A_log[d * D_STATE + n]);
        Bv[n] = Bp[d * D_STATE + n];
        h[n]  = 0.0f;
    }
    float sdt = 0.0f;
    int t0 = b * SEQLEN + c * CHUNK;
    for (int j = 0; j < CHUNK; ++j) {
        size_t off = (size_t)(t0 + j) * INNER + d;
        float dtv = dt[off];
        float uv  = u[off];
        sdt += dtv;
        float du = dtv * uv;
        #pragma unroll
        for (int n = 0; n < D_STATE; ++n)
            h[n] = fmaf(__expf(dtv * Av[n]), h[n], du * Bv[n]);
    }
    int bc = b * NCHUNK + c;
    #pragma unroll
    for (int n = 0; n < D_STATE; ++n)
        hend[(size_t)(bc * D_STATE + n) * INNER + d] = h[n];
    sdtb[(size_t)bc * INNER + d] = sdt;
}

// ---------------- scan fixup: serial prefix over chunks ----------------
__global__ __launch_bounds__(256)
void scan_fix(const float* __restrict__ A_log,
              const float* __restrict__ hend, const float* __restrict__ sdtb,
              float* __restrict__ h0buf)
{
    int idx = blockIdx.x * blockDim.x + threadIdx.x;
    if (idx >= BATCH * INNER) return;
    int d = idx % INNER;
    int b = idx / INNER;

    float Av[D_STATE], h[D_STATE];
    #pragma unroll
    for (int n = 0; n < D_STATE; ++n) {
        Av[n] = -__expf(A_log[d * D_STATE + n]);
        h[n] = 0.0f;
    }
    for (int c = 0; c < NCHUNK; ++c) {
        int bc = b * NCHUNK + c;
        #pragma unroll
        for (int n = 0; n < D_STATE; ++n)
            h0buf[(size_t)(bc * D_STATE + n) * INNER + d] = h[n];
        float s = sdtb[(size_t)bc * INNER + d];
        #pragma unroll
        for (int n = 0; n < D_STATE; ++n)
            h[n] = fmaf(__expf(Av[n] * s), h[n],
                        hend[(size_t)(bc * D_STATE + n) * INNER + d]);
    }
}

// ---------------- scan pass 2: correct h0, emit gated output (fp16 split) ----------------
__global__ __launch_bounds__(256)
void scan_pass2(const float* __restrict__ dt, const float* __restrict__ u,
                const float* __restrict__ xz,
                const float* __restrict__ A_log, const float* __restrict__ Bp,
                const float* __restrict__ Cp, const float* __restrict__ Dp,
                const float* __restrict__ h0buf,
                __half* __restrict__ yghi, __half* __restrict__ yglo)
{
    int idx = blockIdx.x * blockDim.x + threadIdx.x;
    int d = idx % INNER;
    int c = (idx / INNER) & (NCHUNK - 1);
    int b = idx / (INNER * NCHUNK);
    int bc = b * NCHUNK + c;

    float Av[D_STATE], Bv[D_STATE], Cv[D_STATE], h[D_STATE];
    #pragma unroll
    for (int n = 0; n < D_STATE; ++n) {
        Av[n] = -__expf(A_log[d * D_STATE + n]);
        Bv[n] = Bp[d * D_STATE + n];
        Cv[n] = Cp[d * D_STATE + n];
        h[n]  = h0buf[(size_t)(bc * D_STATE + n) * INNER + d];
    }
    float Dv = Dp[d];

    int t0 = b * SEQLEN + c * CHUNK;
    for (int j = 0; j < CHUNK; ++j) {
        int t = t0 + j;
        size_t off = (size_t)t * INNER + d;
        float dtv = dt[off];
        float uv  = u[off];
        float du  = dtv * uv;
        float y = 0.0f;
        #pragma unroll
        for (int n = 0; n < D_STATE; ++n) {
            h[n] = fmaf(__expf(dtv * Av[n]), h[n], du * Bv[n]);
            y = fmaf(h[n], Cv[n], y);
        }
        float z = xz[(size_t)t * N2 + INNER + d];
        float v = (y + Dv * uv) * siluf(z);
        __half hh = __float2half_rn(v);
        yghi[off] = hh;
        yglo[off] = __float2half_rn(v - __half2float(hh));
    }
}

// ---------------- launcher ----------------
extern "C" void kernel_launch(void* const* d_in, const int* in_sizes, int n_in,
                              void* d_out, int out_size)
{
    const float* hidden    = (const float*)d_in[0];
    const float* in_proj_w = (const float*)d_in[1];
    const float* out_proj_w= (const float*)d_in[2];
    const float* dt_proj_w = (const float*)d_in[3];
    const float* dt_proj_b = (const float*)d_in[4];
    const float* conv_w    = (const float*)d_in[5];
    const float* conv_b    = (const float*)d_in[6];
    const float* A_log     = (const float*)d_in[7];
    const float* B_param   = (const float*)d_in[8];
    const float* C_param   = (const float*)d_in[9];
    const float* D_param   = (const float*)d_in[10];
    const float* dt_bias   = (const float*)d_in[11];
    float* out = (float*)d_out;

    float *xz, *u, *dtb, *hend, *h0, *sdt;
    __half *hid_hi, *hid_lo, *wi_hi, *wi_lo, *wd_hi, *wd_lo, *wo_hi, *wo_lo;
    __half *u_hi, *u_lo, *yg_hi, *yg_lo;
    cudaGetSymbolAddress((void**)&xz,     g_xz);
    cudaGetSymbolAddress((void**)&u,      g_u);
    cudaGetSymbolAddress((void**)&dtb,    g_dt);
    cudaGetSymbolAddress((void**)&hend,   g_hend);
    cudaGetSymbolAddress((void**)&h0,     g_h0);
    cudaGetSymbolAddress((void**)&sdt,    g_sdt);
    cudaGetSymbolAddress((void**)&hid_hi, g_hid_hi);
    cudaGetSymbolAddress((void**)&hid_lo, g_hid_lo);
    cudaGetSymbolAddress((void**)&wi_hi,  g_wi_hi);
    cudaGetSymbolAddress((void**)&wi_lo,  g_wi_lo);
    cudaGetSymbolAddress((void**)&wd_hi,  g_wd_hi);
    cudaGetSymbolAddress((void**)&wd_lo,  g_wd_lo);
    cudaGetSymbolAddress((void**)&wo_hi,  g_wo_hi);
    cudaGetSymbolAddress((void**)&wo_lo,  g_wo_lo);
    cudaGetSymbolAddress((void**)&u_hi,   g_u_hi);
    cudaGetSymbolAddress((void**)&u_lo,   g_u_lo);
    cudaGetSymbolAddress((void**)&yg_hi,  g_yg_hi);
    cudaGetSymbolAddress((void**)&yg_lo,  g_yg_lo);

    cudaFuncSetAttribute(gemm_fp16x3<0>,
                         cudaFuncAttributeMaxDynamicSharedMemorySize, GEMM_SMEM);
    cudaFuncSetAttribute(gemm_fp16x3<1>,
                         cudaFuncAttributeMaxDynamicSharedMemorySize, GEMM_SMEM);

    // 0) fp16 splits of inputs/weights
    split_kernel<<<(NTOK * D_MODEL + 255) / 256, 256>>>(hidden, hid_hi, hid_lo, NTOK * D_MODEL);
    split_kernel<<<(N2 * D_MODEL + 255) / 256, 256>>>(in_proj_w, wi_hi, wi_lo, N2 * D_MODEL);
    split_kernel<<<(INNER * INNER + 255) / 256, 256>>>(dt_proj_w, wd_hi, wd_lo, INNER * INNER);
    split_kernel<<<(D_MODEL * INNER + 255) / 256, 256>>>(out_proj_w, wo_hi, wo_lo, D_MODEL * INNER);

    // 1) in_proj: xz[4096,3072]
    {
        dim3 grid(N2 / 128, NTOK / 128);
        gemm_fp16x3<0><<<grid, 256, GEMM_SMEM>>>(hid_hi, hid_lo, wi_hi, wi_lo,
                                                 xz, NTOK, N2, D_MODEL, nullptr, nullptr);
    }
    // 2) depthwise conv + SiLU -> u (+ split)
    conv_silu_kernel<<<NTOK * INNER / 256, 256>>>(xz, conv_w, conv_b, u, u_hi, u_lo);
    // 3) dt_proj + softplus
    {
        dim3 grid(INNER / 128, NTOK / 128);
        gemm_fp16x3<1><<<grid, 256, GEMM_SMEM>>>(u_hi, u_lo, wd_hi, wd_lo,
                                                 dtb, NTOK, INNER, INNER,
                                                 dt_proj_b, dt_bias);
    }
    // 4) chunked selective scan
    {
        int n1 = BATCH * NCHUNK * INNER;
        scan_pass1<<<n1 / 256, 256>>>(dtb, u, A_log, B_param, hend, sdt);
        scan_fix<<<(BATCH * INNER + 255) / 256, 256>>>(A_log, hend, sdt, h0);
        scan_pass2<<<n1 / 256, 256>>>(dtb, u, xz, A_log, B_param, C_param,
                                      D_param, h0, yg_hi, yg_lo);
    }
    // 5) out_proj: out[4096,768]
    {
        dim3 grid(D_MODEL / 128, NTOK / 128);
        gemm_fp16x3<0><<<grid, 256, GEMM_SMEM>>>(yg_hi, yg_lo, wo_hi, wo_lo,
                                                 out, NTOK, D_MODEL, INNER, nullptr, nullptr);
    }
}

// round 8
// speedup vs baseline: 3.2491x; 1.3935x over previous
#include <cuda_runtime.h>
#include <cuda_fp16.h>
#include <math.h>
#include <stdint.h>

// ---------------- problem constants ----------------
#define D_MODEL 768
#define D_STATE 16
#define D_CONV  4
#define INNER   1536
#define N2      (2*INNER)     // 3072
#define BATCH   2
#define SEQLEN  2048
#define NTOK    (BATCH*SEQLEN)  // 4096
#define NCHUNK  64
#define CHUNK   (SEQLEN/NCHUNK) // 32

// ---------------- scratch (static device globals; no allocation) ----------------
__device__ float g_xz  [NTOK * N2];
__device__ float g_u   [NTOK * INNER];
__device__ float g_dt  [NTOK * INNER];
__device__ float g_hend[BATCH*NCHUNK*D_STATE*INNER];
__device__ float g_h0  [BATCH*NCHUNK*D_STATE*INNER];
__device__ float g_sdt [BATCH*NCHUNK*INNER];

// fp16 hi/lo splits
__device__ __half g_hid_hi[NTOK * D_MODEL];
__device__ __half g_hid_lo[NTOK * D_MODEL];
__device__ __half g_wi_hi [N2 * D_MODEL];
__device__ __half g_wi_lo [N2 * D_MODEL];
__device__ __half g_wd_hi [INNER * INNER];
__device__ __half g_wd_lo [INNER * INNER];
__device__ __half g_wo_hi [D_MODEL * INNER];
__device__ __half g_wo_lo [D_MODEL * INNER];
__device__ __half g_u_hi  [NTOK * INNER];
__device__ __half g_u_lo  [NTOK * INNER];
__device__ __half g_yg_hi [NTOK * INNER];
__device__ __half g_yg_lo [NTOK * INNER];

// ---------------- helpers ----------------
__device__ __forceinline__ float siluf(float x) {
    return x * (1.0f / (1.0f + __expf(-x)));
}
__device__ __forceinline__ float softplusf(float x) {
    return fmaxf(x, 0.0f) + log1pf(__expf(-fabsf(x)));
}
__device__ __forceinline__ uint32_t smem_u32(const void* p) {
    uint32_t a;
    asm("{ .reg .u64 t; cvta.to.shared.u64 t, %1; cvt.u32.u64 %0, t; }"
        : "=r"(a) : "l"(p));
    return a;
}
__device__ __forceinline__ void cp16(uint32_t s, const void* g) {
    asm volatile("cp.async.cg.shared.global [%0], [%1], 16;\n" :: "r"(s), "l"(g));
}
__device__ __forceinline__ void cp_commit() {
    asm volatile("cp.async.commit_group;\n");
}
template<int N> __device__ __forceinline__ void cp_wait() {
    asm volatile("cp.async.wait_group %0;\n" :: "n"(N));
}
__device__ __forceinline__ void ldm_x4(uint32_t a, uint32_t* r) {
    asm volatile("ldmatrix.sync.aligned.m8n8.x4.shared.b16 {%0,%1,%2,%3}, [%4];"
                 : "=r"(r[0]), "=r"(r[1]), "=r"(r[2]), "=r"(r[3]) : "r"(a));
}
__device__ __forceinline__ void mma_fp16(float* d, const uint32_t* a,
                                         uint32_t b0, uint32_t b1) {
    asm volatile(
        "mma.sync.aligned.m16n8k16.row.col.f32.f16.f16.f32 "
        "{%0,%1,%2,%3}, {%4,%5,%6,%7}, {%8,%9}, {%0,%1,%2,%3};\n"
        : "+f"(d[0]), "+f"(d[1]), "+f"(d[2]), "+f"(d[3])
        : "r"(a[0]), "r"(a[1]), "r"(a[2]), "r"(a[3]), "r"(b0), "r"(b1));
}

// ---------------- split kernel: fp32 -> (fp16 hi, fp16 lo) ----------------
__global__ __launch_bounds__(256)
void split_kernel(const float* __restrict__ x, __half* __restrict__ hi,
                  __half* __restrict__ lo, int n)
{
    int i = blockIdx.x * blockDim.x + threadIdx.x;
    if (i < n) {
        float v = x[i];
        __half h = __float2half_rn(v);
        hi[i] = h;
        lo[i] = __float2half_rn(v - __half2float(h));
    }
}

// ---------------- fp16xN NT GEMM: C[M,N] = A[M,K]*B[N,K]^T ----------------
// BM=BN=128, BK=64 halves (128B rows). 8 warps, warptile 64x32.
// NMMA=3: hi*hi + hi*lo + lo*hi.  NMMA=2: hi*hi + hi*lo (drop lo*hi).
// EPI: 0 plain, 1 softplus(x + b1[col] + b2[col])
#define TILE_B 16384
#define GEMM_SMEM (8 * TILE_B)   // 131072

template<int EPI, int NMMA>
__global__ __launch_bounds__(256)
void gemm_fp16x(const __half* __restrict__ Ahi, const __half* __restrict__ Alo,
                const __half* __restrict__ Bhi, const __half* __restrict__ Blo,
                float* __restrict__ C, int M, int N, int K,
                const float* __restrict__ b1, const float* __restrict__ b2)
{
    extern __shared__ char smem[];
    const uint32_t sb = smem_u32(smem);

    const int tid  = threadIdx.x;
    const int wid  = tid >> 5;
    const int lane = tid & 31;
    const int wm   = wid & 1;     // rows wm*64
    const int wn   = wid >> 1;    // cols wn*32
    const int g    = lane >> 3;   // ldmatrix lane group 0..3
    const int lr   = lane & 7;

    const int row0 = blockIdx.y * 128;
    const int col0 = blockIdx.x * 128;

    const __half* srcs[4] = {
        Ahi + (size_t)row0 * K, Alo + (size_t)row0 * K,
        Bhi + (size_t)col0 * K, Blo + (size_t)col0 * K };

    float acc[4][4][4];
    #pragma unroll
    for (int mt = 0; mt < 4; ++mt)
        #pragma unroll
        for (int nt = 0; nt < 4; ++nt)
            #pragma unroll
            for (int r = 0; r < 4; ++r) acc[mt][nt][r] = 0.0f;

    auto load_stage = [&](int s, int kc) {
        #pragma unroll
        for (int t = 0; t < 4; ++t) {
            uint32_t dst = sb + (uint32_t)(s * 4 + t) * TILE_B;
            const __half* src = srcs[t] + kc;
            #pragma unroll
            for (int i = 0; i < 4; ++i) {
                int c = tid + i * 256;
                int r = c >> 3, ch = c & 7;
                cp16(dst + r * 128 + ((ch ^ (r & 7)) << 4),
                     src + (size_t)r * K + ch * 8);
            }
        }
    };

    const int KT = K / 64;
    load_stage(0, 0);
    cp_commit();

    for (int kt = 0; kt < KT; ++kt) {
        if (kt + 1 < KT) {
            load_stage((kt + 1) & 1, (kt + 1) * 64);
            cp_commit();
            cp_wait<1>();
        } else {
            cp_wait<0>();
        }
        __syncthreads();

        const uint32_t st = sb + (uint32_t)(kt & 1) * 4 * TILE_B;
        const uint32_t sAh = st, sAl = st + TILE_B;
        const uint32_t sBh = st + 2 * TILE_B, sBl = st + 3 * TILE_B;

        #pragma unroll
        for (int k16 = 0; k16 < 4; ++k16) {
            const int c0 = k16 * 2;
            const int arow_off = ((g & 1) << 3) + lr;
            const int ach = c0 + (g >> 1);
            const int brow_off = ((g >> 1) << 3) + lr;
            const int bch = c0 + (g & 1);

            uint32_t ah[4][4], al[4][4];
            #pragma unroll
            for (int mt = 0; mt < 4; ++mt) {
                int row = wm * 64 + mt * 16 + arow_off;
                uint32_t off = row * 128 + (((ach ^ (row & 7))) << 4);
                ldm_x4(sAh + off, ah[mt]);
                if (NMMA == 3) ldm_x4(sAl + off, al[mt]);
            }
            uint32_t bh[4][2], bl[4][2];
            #pragma unroll
            for (int nn = 0; nn < 2; ++nn) {
                int row = wn * 32 + nn * 16 + brow_off;
                uint32_t off = row * 128 + (((bch ^ (row & 7))) << 4);
                uint32_t t4[4];
                ldm_x4(sBh + off, t4);
                bh[nn*2][0] = t4[0]; bh[nn*2][1] = t4[1];
                bh[nn*2+1][0] = t4[2]; bh[nn*2+1][1] = t4[3];
                ldm_x4(sBl + off, t4);
                bl[nn*2][0] = t4[0]; bl[nn*2][1] = t4[1];
                bl[nn*2+1][0] = t4[2]; bl[nn*2+1][1] = t4[3];
            }
            #pragma unroll
            for (int mt = 0; mt < 4; ++mt)
                #pragma unroll
                for (int nt = 0; nt < 4; ++nt) {
                    mma_fp16(acc[mt][nt], ah[mt], bh[nt][0], bh[nt][1]);
                    mma_fp16(acc[mt][nt], ah[mt], bl[nt][0], bl[nt][1]);
                    if (NMMA == 3)
                        mma_fp16(acc[mt][nt], al[mt], bh[nt][0], bh[nt][1]);
                }
        }
        __syncthreads();
    }

    // epilogue: direct register -> gmem (float2 per pair)
    const int qr = lane >> 2;
    const int qc = (lane & 3) * 2;
    #pragma unroll
    for (int mt = 0; mt < 4; ++mt) {
        #pragma unroll
        for (int nt = 0; nt < 4; ++nt) {
            int gr = row0 + wm * 64 + mt * 16 + qr;
            int gc = col0 + wn * 32 + nt * 8 + qc;
            float v0 = acc[mt][nt][0], v1 = acc[mt][nt][1];
            float v2 = acc[mt][nt][2], v3 = acc[mt][nt][3];
            if (EPI == 1) {
                float e0 = b1[gc] + b2[gc];
                float e1 = b1[gc + 1] + b2[gc + 1];
                v0 = softplusf(v0 + e0); v1 = softplusf(v1 + e1);
                v2 = softplusf(v2 + e0); v3 = softplusf(v3 + e1);
            }
            *(float2*)&C[(size_t)gr * N + gc]       = make_float2(v0, v1);
            *(float2*)&C[(size_t)(gr + 8) * N + gc] = make_float2(v2, v3);
        }
    }
}

// ---------------- depthwise causal conv(4) + bias + SiLU (+ fp16 split) ----------------
__global__ __launch_bounds__(256)
void conv_silu_kernel(const float* __restrict__ xz,
                      const float* __restrict__ cw,
                      const float* __restrict__ cb,
                      float* __restrict__ u,
                      __half* __restrict__ uhi,
                      __half* __restrict__ ulo)
{
    int idx = blockIdx.x * blockDim.x + threadIdx.x;
    if (idx >= NTOK * INNER) return;
    int c = idx % INNER;
    int t = idx / INNER;
    int l = t & (SEQLEN - 1);

    float acc = cb[c];
    #pragma unroll
    for (int k = 0; k < D_CONV; ++k) {
        int ll = l - (D_CONV - 1) + k;
        if (ll >= 0)
            acc = fmaf(cw[c * D_CONV + k],
                       xz[(size_t)(t - (D_CONV - 1) + k) * N2 + c], acc);
    }
    float v = siluf(acc);
    u[idx] = v;
    __half h = __float2half_rn(v);
    uhi[idx] = h;
    ulo[idx] = __float2half_rn(v - __half2float(h));
}

// ---------------- scan pass 1: per-chunk local scan (h0 = 0) ----------------
// Fast path: if all A_log[d,:] are equal (true for this model: A_log == 0),
// exp(dt*A[n]) is identical across n -> 1 exp per step instead of 16.
__global__ __launch_bounds__(256)
void scan_pass1(const float* __restrict__ dt, const float* __restrict__ u,
                const float* __restrict__ A_log, const float* __restrict__ Bp,
                float* __restrict__ hend, float* __restrict__ sdtb)
{
    int idx = blockIdx.x * blockDim.x + threadIdx.x;
    int d = idx % INNER;
    int c = (idx / INNER) & (NCHUNK - 1);
    int b = idx / (INNER * NCHUNK);

    float a0 = A_log[d * D_STATE];
    bool uni = true;
    float Av[D_STATE], Bv[D_STATE], h[D_STATE];
    #pragma unroll
    for (int n = 0; n < D_STATE; ++n) {
        float al = A_log[d * D_STATE + n];
        uni = uni && (al == a0);
        Av[n] = -__expf(al);
        Bv[n] = Bp[d * D_STATE + n];
        h[n]  = 0.0f;
    }
    float sdt = 0.0f;
    int t0 = b * SEQLEN + c * CHUNK;

    if (uni) {
        const float Av0 = Av[0];
        for (int j = 0; j < CHUNK; ++j) {
            size_t off = (size_t)(t0 + j) * INNER + d;
            float dtv = dt[off];
            float uv  = u[off];
            sdt += dtv;
            float du = dtv * uv;
            float e  = __expf(dtv * Av0);
            #pragma unroll
            for (int n = 0; n < D_STATE; ++n)
                h[n] = fmaf(e, h[n], du * Bv[n]);
        }
    } else {
        for (int j = 0; j < CHUNK; ++j) {
            size_t off = (size_t)(t0 + j) * INNER + d;
            float dtv = dt[off];
            float uv  = u[off];
            sdt += dtv;
            float du = dtv * uv;
            #pragma unroll
            for (int n = 0; n < D_STATE; ++n)
                h[n] = fmaf(__expf(dtv * Av[n]), h[n], du * Bv[n]);
        }
    }
    int bc = b * NCHUNK + c;
    #pragma unroll
    for (int n = 0; n < D_STATE; ++n)
        hend[(size_t)(bc * D_STATE + n) * INNER + d] = h[n];
    sdtb[(size_t)bc * INNER + d] = sdt;
}

// ---------------- scan fixup: serial prefix over chunks ----------------
__global__ __launch_bounds__(256)
void scan_fix(const float* __restrict__ A_log,
              const float* __restrict__ hend, const float* __restrict__ sdtb,
              float* __restrict__ h0buf)
{
    int idx = blockIdx.x * blockDim.x + threadIdx.x;
    if (idx >= BATCH * INNER) return;
    int d = idx % INNER;
    int b = idx / INNER;

    float a0 = A_log[d * D_STATE];
    bool uni = true;
    float Av[D_STATE], h[D_STATE];
    #pragma unroll
    for (int n = 0; n < D_STATE; ++n) {
        float al = A_log[d * D_STATE + n];
        uni = uni && (al == a0);
        Av[n] = -__expf(al);
        h[n] = 0.0f;
    }
    for (int c = 0; c < NCHUNK; ++c) {
        int bc = b * NCHUNK + c;
        #pragma unroll
        for (int n = 0; n < D_STATE; ++n)
            h0buf[(size_t)(bc * D_STATE + n) * INNER + d] = h[n];
        float s = sdtb[(size_t)bc * INNER + d];
        if (uni) {
            float e = __expf(Av[0] * s);
            #pragma unroll
            for (int n = 0; n < D_STATE; ++n)
                h[n] = fmaf(e, h[n],
                            hend[(size_t)(bc * D_STATE + n) * INNER + d]);
        } else {
            #pragma unroll
            for (int n = 0; n < D_STATE; ++n)
                h[n] = fmaf(__expf(Av[n] * s), h[n],
                            hend[(size_t)(bc * D_STATE + n) * INNER + d]);
        }
    }
}

// ---------------- scan pass 2: correct h0, emit gated output (fp16 split) ----------------
__global__ __launch_bounds__(256)
void scan_pass2(const float* __restrict__ dt, const float* __restrict__ u,
                const float* __restrict__ xz,
                const float* __restrict__ A_log, const float* __restrict__ Bp,
                const float* __restrict__ Cp, const float* __restrict__ Dp,
                const float* __restrict__ h0buf,
                __half* __restrict__ yghi, __half* __restrict__ yglo)
{
    int idx = blockIdx.x * blockDim.x + threadIdx.x;
    int d = idx % INNER;
    int c = (idx / INNER) & (NCHUNK - 1);
    int b = idx / (INNER * NCHUNK);
    int bc = b * NCHUNK + c;

    float a0 = A_log[d * D_STATE];
    bool uni = true;
    float Av[D_STATE], Bv[D_STATE], Cv[D_STATE], h[D_STATE];
    #pragma unroll
    for (int n = 0; n < D_STATE; ++n) {
        float al = A_log[d * D_STATE + n];
        uni = uni && (al == a0);
        Av[n] = -__expf(al);
        Bv[n] = Bp[d * D_STATE + n];
        Cv[n] = Cp[d * D_STATE + n];
        h[n]  = h0buf[(size_t)(bc * D_STATE + n) * INNER + d];
    }
    float Dv = Dp[d];

    int t0 = b * SEQLEN + c * CHUNK;
    if (uni) {
        const float Av0 = Av[0];
        for (int j = 0; j < CHUNK; ++j) {
            int t = t0 + j;
            size_t off = (size_t)t * INNER + d;
            float dtv = dt[off];
            float uv  = u[off];
            float du  = dtv * uv;
            float e   = __expf(dtv * Av0);
            float y = 0.0f;
            #pragma unroll
            for (int n = 0; n < D_STATE; ++n) {
                h[n] = fmaf(e, h[n], du * Bv[n]);
                y = fmaf(h[n], Cv[n], y);
            }
            float z = xz[(size_t)t * N2 + INNER + d];
            float v = (y + Dv * uv) * siluf(z);
            __half hh = __float2half_rn(v);
            yghi[off] = hh;
            yglo[off] = __float2half_rn(v - __half2float(hh));
        }
    } else {
        for (int j = 0; j < CHUNK; ++j) {
            int t = t0 + j;
            size_t off = (size_t)t * INNER + d;
            float dtv = dt[off];
            float uv  = u[off];
            float du  = dtv * uv;
            float y = 0.0f;
            #pragma unroll
            for (int n = 0; n < D_STATE; ++n) {
                h[n] = fmaf(__expf(dtv * Av[n]), h[n], du * Bv[n]);
                y = fmaf(h[n], Cv[n], y);
            }
            float z = xz[(size_t)t * N2 + INNER + d];
            float v = (y + Dv * uv) * siluf(z);
            __half hh = __float2half_rn(v);
            yghi[off] = hh;
            yglo[off] = __float2half_rn(v - __half2float(hh));
        }
    }
}

// ---------------- launcher ----------------
extern "C" void kernel_launch(void* const* d_in, const int* in_sizes, int n_in,
                              void* d_out, int out_size)
{
    const float* hidden    = (const float*)d_in[0];
    const float* in_proj_w = (const float*)d_in[1];
    const float* out_proj_w= (const float*)d_in[2];
    const float* dt_proj_w = (const float*)d_in[3];
    const float* dt_proj_b = (const float*)d_in[4];
    const float* conv_w    = (const float*)d_in[5];
    const float* conv_b    = (const float*)d_in[6];
    const float* A_log     = (const float*)d_in[7];
    const float* B_param   = (const float*)d_in[8];
    const float* C_param   = (const float*)d_in[9];
    const float* D_param   = (const float*)d_in[10];
    const float* dt_bias   = (const float*)d_in[11];
    float* out = (float*)d_out;

    float *xz, *u, *dtb, *hend, *h0, *sdt;
    __half *hid_hi, *hid_lo, *wi_hi, *wi_lo, *wd_hi, *wd_lo, *wo_hi, *wo_lo;
    __half *u_hi, *u_lo, *yg_hi, *yg_lo;
    cudaGetSymbolAddress((void**)&xz,     g_xz);
    cudaGetSymbolAddress((void**)&u,      g_u);
    cudaGetSymbolAddress((void**)&dtb,    g_dt);
    cudaGetSymbolAddress((void**)&hend,   g_hend);
    cudaGetSymbolAddress((void**)&h0,     g_h0);
    cudaGetSymbolAddress((void**)&sdt,    g_sdt);
    cudaGetSymbolAddress((void**)&hid_hi, g_hid_hi);
    cudaGetSymbolAddress((void**)&hid_lo, g_hid_lo);
    cudaGetSymbolAddress((void**)&wi_hi,  g_wi_hi);
    cudaGetSymbolAddress((void**)&wi_lo,  g_wi_lo);
    cudaGetSymbolAddress((void**)&wd_hi,  g_wd_hi);
    cudaGetSymbolAddress((void**)&wd_lo,  g_wd_lo);
    cudaGetSymbolAddress((void**)&wo_hi,  g_wo_hi);
    cudaGetSymbolAddress((void**)&wo_lo,  g_wo_lo);
    cudaGetSymbolAddress((void**)&u_hi,   g_u_hi);
    cudaGetSymbolAddress((void**)&u_lo,   g_u_lo);
    cudaGetSymbolAddress((void**)&yg_hi,  g_yg_hi);
    cudaGetSymbolAddress((void**)&yg_lo,  g_yg_lo);

    cudaFuncSetAttribute(gemm_fp16x<0,2>,
                         cudaFuncAttributeMaxDynamicSharedMemorySize, GEMM_SMEM);
    cudaFuncSetAttribute(gemm_fp16x<1,2>,
                         cudaFuncAttributeMaxDynamicSharedMemorySize, GEMM_SMEM);
    cudaFuncSetAttribute(gemm_fp16x<0,3>,
                         cudaFuncAttributeMaxDynamicSharedMemorySize, GEMM_SMEM);

    // 0) fp16 splits of inputs/weights
    split_kernel<<<(NTOK * D_MODEL + 255) / 256, 256>>>(hidden, hid_hi, hid_lo, NTOK * D_MODEL);
    split_kernel<<<(N2 * D_MODEL + 255) / 256, 256>>>(in_proj_w, wi_hi, wi_lo, N2 * D_MODEL);
    split_kernel<<<(INNER * INNER + 255) / 256, 256>>>(dt_proj_w, wd_hi, wd_lo, INNER * INNER);
    split_kernel<<<(D_MODEL * INNER + 255) / 256, 256>>>(out_proj_w, wo_hi, wo_lo, D_MODEL * INNER);

    // 1) in_proj (x2): xz[4096,3072]
    {
        dim3 grid(N2 / 128, NTOK / 128);
        gemm_fp16x<0,2><<<grid, 256, GEMM_SMEM>>>(hid_hi, hid_lo, wi_hi, wi_lo,
                                                  xz, NTOK, N2, D_MODEL, nullptr, nullptr);
    }
    // 2) depthwise conv + SiLU -> u (+ split)
    conv_silu_kernel<<<NTOK * INNER / 256, 256>>>(xz, conv_w, conv_b, u, u_hi, u_lo);
    // 3) dt_proj + softplus (x2)
    {
        dim3 grid(INNER / 128, NTOK / 128);
        gemm_fp16x<1,2><<<grid, 256, GEMM_SMEM>>>(u_hi, u_lo, wd_hi, wd_lo,
                                                  dtb, NTOK, INNER, INNER,
                                                  dt_proj_b, dt_bias);
    }
    // 4) chunked selective scan
    {
        int n1 = BATCH * NCHUNK * INNER;
        scan_pass1<<<n1 / 256, 256>>>(dtb, u, A_log, B_param, hend, sdt);
        scan_fix<<<(BATCH * INNER + 255) / 256, 256>>>(A_log, hend, sdt, h0);
        scan_pass2<<<n1 / 256, 256>>>(dtb, u, xz, A_log, B_param, C_param,
                                      D_param, h0, yg_hi, yg_lo);
    }
    // 5) out_proj (x3): out[4096,768]
    {
        dim3 grid(D_MODEL / 128, NTOK / 128);
        gemm_fp16x<0,3><<<grid, 256, GEMM_SMEM>>>(yg_hi, yg_lo, wo_hi, wo_lo,
                                                  out, NTOK, D_MODEL, INNER, nullptr, nullptr);
    }
}

// round 9
// speedup vs baseline: 4.0702x; 1.2527x over previous
#include <cuda_runtime.h>
#include <cuda_fp16.h>
#include <math.h>
#include <stdint.h>

// ---------------- problem constants ----------------
#define D_MODEL 768
#define D_STATE 16
#define D_CONV  4
#define INNER   1536
#define N2      (2*INNER)     // 3072
#define BATCH   2
#define SEQLEN  2048
#define NTOK    (BATCH*SEQLEN)  // 4096
#define NCHUNK  64
#define CHUNK   (SEQLEN/NCHUNK) // 32

// ---------------- scratch (static device globals; no allocation) ----------------
__device__ float g_xz  [NTOK * N2];
__device__ float g_u   [NTOK * INNER];
__device__ float g_dt  [NTOK * INNER];
__device__ float g_hend[BATCH*NCHUNK*D_STATE*INNER];
__device__ float g_h0  [BATCH*NCHUNK*D_STATE*INNER];
__device__ float g_sdt [BATCH*NCHUNK*INNER];

// fp16 splits (only the operands actually consumed)
__device__ __half g_hid_hi[NTOK * D_MODEL];
__device__ __half g_wi_hi [N2 * D_MODEL];
__device__ __half g_wi_lo [N2 * D_MODEL];
__device__ __half g_wd_hi [INNER * INNER];
__device__ __half g_wo_hi [D_MODEL * INNER];
__device__ __half g_wo_lo [D_MODEL * INNER];
__device__ __half g_u_hi  [NTOK * INNER];
__device__ __half g_yg_hi [NTOK * INNER];

// ---------------- helpers ----------------
__device__ __forceinline__ float siluf(float x) {
    return x * (1.0f / (1.0f + __expf(-x)));
}
__device__ __forceinline__ float softplusf(float x) {
    return fmaxf(x, 0.0f) + log1pf(__expf(-fabsf(x)));
}
__device__ __forceinline__ uint32_t smem_u32(const void* p) {
    uint32_t a;
    asm("{ .reg .u64 t; cvta.to.shared.u64 t, %1; cvt.u32.u64 %0, t; }"
        : "=r"(a) : "l"(p));
    return a;
}
__device__ __forceinline__ void cp16(uint32_t s, const void* g) {
    asm volatile("cp.async.cg.shared.global [%0], [%1], 16;\n" :: "r"(s), "l"(g));
}
__device__ __forceinline__ void cp_commit() {
    asm volatile("cp.async.commit_group;\n");
}
template<int N> __device__ __forceinline__ void cp_wait() {
    asm volatile("cp.async.wait_group %0;\n" :: "n"(N));
}
__device__ __forceinline__ void ldm_x4(uint32_t a, uint32_t* r) {
    asm volatile("ldmatrix.sync.aligned.m8n8.x4.shared.b16 {%0,%1,%2,%3}, [%4];"
                 : "=r"(r[0]), "=r"(r[1]), "=r"(r[2]), "=r"(r[3]) : "r"(a));
}
__device__ __forceinline__ void mma_fp16(float* d, const uint32_t* a,
                                         uint32_t b0, uint32_t b1) {
    asm volatile(
        "mma.sync.aligned.m16n8k16.row.col.f32.f16.f16.f32 "
        "{%0,%1,%2,%3}, {%4,%5,%6,%7}, {%8,%9}, {%0,%1,%2,%3};\n"
        : "+f"(d[0]), "+f"(d[1]), "+f"(d[2]), "+f"(d[3])
        : "r"(a[0]), "r"(a[1]), "r"(a[2]), "r"(a[3]), "r"(b0), "r"(b1));
}
__device__ __forceinline__ void store_h4(__half* p, float4 v) {
    __half2 a = __floats2half2_rn(v.x, v.y);
    __half2 b = __floats2half2_rn(v.z, v.w);
    uint2 o;
    o.x = *(uint32_t*)&a;
    o.y = *(uint32_t*)&b;
    *(uint2*)p = o;
}

// ---------------- merged split kernel ----------------
// hidden -> hi only; wi -> hi+lo; wd -> hi only; wo -> hi+lo. float4 per thread.
#define SPL_N0 (NTOK*D_MODEL)
#define SPL_N1 (N2*D_MODEL)
#define SPL_N2 (INNER*INNER)
#define SPL_N3 (D_MODEL*INNER)
#define SPL_TOT4 ((SPL_N0+SPL_N1+SPL_N2+SPL_N3)/4)

__device__ __forceinline__ void cvt4_hi(const float* s, __half* h) {
    float4 v = *(const float4*)s;
    store_h4(h, v);
}
__device__ __forceinline__ void cvt4_hilo(const float* s, __half* h, __half* l) {
    float4 v = *(const float4*)s;
    __half2 a = __floats2half2_rn(v.x, v.y);
    __half2 b = __floats2half2_rn(v.z, v.w);
    uint2 o; o.x = *(uint32_t*)&a; o.y = *(uint32_t*)&b;
    *(uint2*)h = o;
    float2 fa = __half22float2(a), fb = __half22float2(b);
    float4 r = make_float4(v.x - fa.x, v.y - fa.y, v.z - fb.x, v.w - fb.y);
    store_h4(l, r);
}

__global__ __launch_bounds__(256)
void split_all(const float* __restrict__ hidden, const float* __restrict__ wi,
               const float* __restrict__ wd, const float* __restrict__ wo,
               __half* __restrict__ hid_hi,
               __half* __restrict__ wi_hi, __half* __restrict__ wi_lo,
               __half* __restrict__ wd_hi,
               __half* __restrict__ wo_hi, __half* __restrict__ wo_lo)
{
    int idx = (blockIdx.x * blockDim.x + threadIdx.x) * 4;
    if (idx < SPL_N0) {
        cvt4_hi(hidden + idx, hid_hi + idx);
    } else if ((idx -= SPL_N0) < SPL_N1) {
        cvt4_hilo(wi + idx, wi_hi + idx, wi_lo + idx);
    } else if ((idx -= SPL_N1) < SPL_N2) {
        cvt4_hi(wd + idx, wd_hi + idx);
    } else if ((idx -= SPL_N2) < SPL_N3) {
        cvt4_hilo(wo + idx, wo_hi + idx, wo_lo + idx);
    }
}

// ---------------- fp16xN NT GEMM: C[M,N] = A[M,K]*B[N,K]^T ----------------
// BM=BN=128, BK=64 halves (128B rows). 8 warps, warptile 64x32.
// NMMA=3: AhBh+AhBl+AlBh. NMMA=2: AhBh+AhBl (A-lo not staged).
// NMMA=1: AhBh only (no lo tiles staged at all).
// EPI: 0 plain, 1 softplus(x + b1[col] + b2[col])
#define TILE_B 16384

template<int EPI, int NMMA>
__global__ __launch_bounds__(256)
void gemm_fp16x(const __half* __restrict__ Ahi, const __half* __restrict__ Alo,
                const __half* __restrict__ Bhi, const __half* __restrict__ Blo,
                float* __restrict__ C, int M, int N, int K,
                const float* __restrict__ b1, const float* __restrict__ b2)
{
    constexpr int NT = (NMMA == 3) ? 4 : (NMMA == 2) ? 3 : 2;
    extern __shared__ char smem[];
    const uint32_t sb = smem_u32(smem);

    const int tid  = threadIdx.x;
    const int wid  = tid >> 5;
    const int lane = tid & 31;
    const int wm   = wid & 1;     // rows wm*64
    const int wn   = wid >> 1;    // cols wn*32
    const int g    = lane >> 3;   // ldmatrix lane group 0..3
    const int lr   = lane & 7;

    const int row0 = blockIdx.y * 128;
    const int col0 = blockIdx.x * 128;

    const __half* srcs[NT];
    {
        int nt = 0;
        srcs[nt++] = Ahi + (size_t)row0 * K;
        if (NMMA == 3) srcs[nt++] = Alo + (size_t)row0 * K;
        srcs[nt++] = Bhi + (size_t)col0 * K;
        if (NMMA >= 2) srcs[nt++] = Blo + (size_t)col0 * K;
    }

    float acc[4][4][4];
    #pragma unroll
    for (int mt = 0; mt < 4; ++mt)
        #pragma unroll
        for (int nt = 0; nt < 4; ++nt)
            #pragma unroll
            for (int r = 0; r < 4; ++r) acc[mt][nt][r] = 0.0f;

    auto load_stage = [&](int s, int kc) {
        #pragma unroll
        for (int t = 0; t < NT; ++t) {
            uint32_t dst = sb + (uint32_t)(s * NT + t) * TILE_B;
            const __half* src = srcs[t] + kc;
            #pragma unroll
            for (int i = 0; i < 4; ++i) {
                int c = tid + i * 256;
                int r = c >> 3, ch = c & 7;
                cp16(dst + r * 128 + ((ch ^ (r & 7)) << 4),
                     src + (size_t)r * K + ch * 8);
            }
        }
    };

    const int KT = K / 64;
    load_stage(0, 0);
    cp_commit();

    for (int kt = 0; kt < KT; ++kt) {
        if (kt + 1 < KT) {
            load_stage((kt + 1) & 1, (kt + 1) * 64);
            cp_commit();
            cp_wait<1>();
        } else {
            cp_wait<0>();
        }
        __syncthreads();

        const uint32_t st  = sb + (uint32_t)(kt & 1) * NT * TILE_B;
        const uint32_t sAh = st;
        const uint32_t sAl = st + TILE_B;                       // valid iff NMMA==3
        const uint32_t sBh = st + (NMMA == 3 ? 2 : 1) * TILE_B;
        const uint32_t sBl = sBh + TILE_B;                      // valid iff NMMA>=2

        #pragma unroll
        for (int k16 = 0; k16 < 4; ++k16) {
            const int c0 = k16 * 2;
            const int arow_off = ((g & 1) << 3) + lr;
            const int ach = c0 + (g >> 1);
            const int brow_off = ((g >> 1) << 3) + lr;
            const int bch = c0 + (g & 1);

            uint32_t ah[4][4], al[4][4];
            #pragma unroll
            for (int mt = 0; mt < 4; ++mt) {
                int row = wm * 64 + mt * 16 + arow_off;
                uint32_t off = row * 128 + (((ach ^ (row & 7))) << 4);
                ldm_x4(sAh + off, ah[mt]);
                if (NMMA == 3) ldm_x4(sAl + off, al[mt]);
            }
            uint32_t bh[4][2], bl[4][2];
            #pragma unroll
            for (int nn = 0; nn < 2; ++nn) {
                int row = wn * 32 + nn * 16 + brow_off;
                uint32_t off = row * 128 + (((bch ^ (row & 7))) << 4);
                uint32_t t4[4];
                ldm_x4(sBh + off, t4);
                bh[nn*2][0] = t4[0]; bh[nn*2][1] = t4[1];
                bh[nn*2+1][0] = t4[2]; bh[nn*2+1][1] = t4[3];
                if (NMMA >= 2) {
                    ldm_x4(sBl + off, t4);
                    bl[nn*2][0] = t4[0]; bl[nn*2][1] = t4[1];
                    bl[nn*2+1][0] = t4[2]; bl[nn*2+1][1] = t4[3];
                }
            }
            #pragma unroll
            for (int mt = 0; mt < 4; ++mt)
                #pragma unroll
                for (int nt = 0; nt < 4; ++nt) {
                    mma_fp16(acc[mt][nt], ah[mt], bh[nt][0], bh[nt][1]);
                    if (NMMA >= 2)
                        mma_fp16(acc[mt][nt], ah[mt], bl[nt][0], bl[nt][1]);
                    if (NMMA == 3)
                        mma_fp16(acc[mt][nt], al[mt], bh[nt][0], bh[nt][1]);
                }
        }
        __syncthreads();
    }

    // epilogue: direct register -> gmem (float2 per pair)
    const int qr = lane >> 2;
    const int qc = (lane & 3) * 2;
    #pragma unroll
    for (int mt = 0; mt < 4; ++mt) {
        #pragma unroll
        for (int nt = 0; nt < 4; ++nt) {
            int gr = row0 + wm * 64 + mt * 16 + qr;
            int gc = col0 + wn * 32 + nt * 8 + qc;
            float v0 = acc[mt][nt][0], v1 = acc[mt][nt][1];
            float v2 = acc[mt][nt][2], v3 = acc[mt][nt][3];
            if (EPI == 1) {
                float e0 = b1[gc] + b2[gc];
                float e1 = b1[gc + 1] + b2[gc + 1];
                v0 = softplusf(v0 + e0); v1 = softplusf(v1 + e1);
                v2 = softplusf(v2 + e0); v3 = softplusf(v3 + e1);
            }
            *(float2*)&C[(size_t)gr * N + gc]       = make_float2(v0, v1);
            *(float2*)&C[(size_t)(gr + 8) * N + gc] = make_float2(v2, v3);
        }
    }
}

// ---------------- depthwise causal conv(4) + bias + SiLU, 4 channels/thread ----------------
__global__ __launch_bounds__(256)
void conv_silu_kernel(const float* __restrict__ xz,
                      const float* __restrict__ cw,
                      const float* __restrict__ cb,
                      float* __restrict__ u,
                      __half* __restrict__ uhi)
{
    int idx4 = blockIdx.x * blockDim.x + threadIdx.x;
    int base = idx4 * 4;
    if (base >= NTOK * INNER) return;
    int c = base % INNER;
    int t = base / INNER;
    int l = t & (SEQLEN - 1);

    float4 acc = *(const float4*)(cb + c);
    float4 w0 = *(const float4*)(cw + (c + 0) * D_CONV);
    float4 w1 = *(const float4*)(cw + (c + 1) * D_CONV);
    float4 w2 = *(const float4*)(cw + (c + 2) * D_CONV);
    float4 w3 = *(const float4*)(cw + (c + 3) * D_CONV);
    const float* pw0 = (const float*)&w0;
    const float* pw1 = (const float*)&w1;
    const float* pw2 = (const float*)&w2;
    const float* pw3 = (const float*)&w3;

    #pragma unroll
    for (int k = 0; k < D_CONV; ++k) {
        int ll = l - (D_CONV - 1) + k;
        if (ll >= 0) {
            float4 x = *(const float4*)(xz + (size_t)(t - (D_CONV - 1) + k) * N2 + c);
            acc.x = fmaf(pw0[k], x.x, acc.x);
            acc.y = fmaf(pw1[k], x.y, acc.y);
            acc.z = fmaf(pw2[k], x.z, acc.z);
            acc.w = fmaf(pw3[k], x.w, acc.w);
        }
    }
    float4 v = make_float4(siluf(acc.x), siluf(acc.y), siluf(acc.z), siluf(acc.w));
    *(float4*)(u + base) = v;
    store_h4(uhi + base, v);
}

// ---------------- scan pass 1: per-chunk local scan (h0 = 0) ----------------
__global__ __launch_bounds__(256)
void scan_pass1(const float* __restrict__ dt, const float* __restrict__ u,
                const float* __restrict__ A_log, const float* __restrict__ Bp,
                float* __restrict__ hend, float* __restrict__ sdtb)
{
    int idx = blockIdx.x * blockDim.x + threadIdx.x;
    int d = idx % INNER;
    int c = (idx / INNER) & (NCHUNK - 1);
    int b = idx / (INNER * NCHUNK);

    float a0 = A_log[d * D_STATE];
    bool uni = true;
    float Av[D_STATE], Bv[D_STATE], h[D_STATE];
    #pragma unroll
    for (int n = 0; n < D_STATE; ++n) {
        float al = A_log[d * D_STATE + n];
        uni = uni && (al == a0);
        Av[n] = -__expf(al);
        Bv[n] = Bp[d * D_STATE + n];
        h[n]  = 0.0f;
    }
    float sdt = 0.0f;
    int t0 = b * SEQLEN + c * CHUNK;

    if (uni) {
        const float Av0 = Av[0];
        for (int j = 0; j < CHUNK; ++j) {
            size_t off = (size_t)(t0 + j) * INNER + d;
            float dtv = dt[off];
            float uv  = u[off];
            sdt += dtv;
            float du = dtv * uv;
            float e  = __expf(dtv * Av0);
            #pragma unroll
            for (int n = 0; n < D_STATE; ++n)
                h[n] = fmaf(e, h[n], du * Bv[n]);
        }
    } else {
        for (int j = 0; j < CHUNK; ++j) {
            size_t off = (size_t)(t0 + j) * INNER + d;
            float dtv = dt[off];
            float uv  = u[off];
            sdt += dtv;
            float du = dtv * uv;
            #pragma unroll
            for (int n = 0; n < D_STATE; ++n)
                h[n] = fmaf(__expf(dtv * Av[n]), h[n], du * Bv[n]);
        }
    }
    int bc = b * NCHUNK + c;
    #pragma unroll
    for (int n = 0; n < D_STATE; ++n)
        hend[(size_t)(bc * D_STATE + n) * INNER + d] = h[n];
    sdtb[(size_t)bc * INNER + d] = sdt;
}

// ---------------- scan fixup: serial prefix over chunks ----------------
__global__ __launch_bounds__(256)
void scan_fix(const float* __restrict__ A_log,
              const float* __restrict__ hend, const float* __restrict__ sdtb,
              float* __restrict__ h0buf)
{
    int idx = blockIdx.x * blockDim.x + threadIdx.x;
    if (idx >= BATCH * INNER) return;
    int d = idx % INNER;
    int b = idx / INNER;

    float a0 = A_log[d * D_STATE];
    bool uni = true;
    float Av[D_STATE], h[D_STATE];
    #pragma unroll
    for (int n = 0; n < D_STATE; ++n) {
        float al = A_log[d * D_STATE + n];
        uni = uni && (al == a0);
        Av[n] = -__expf(al);
        h[n] = 0.0f;
    }
    for (int c = 0; c < NCHUNK; ++c) {
        int bc = b * NCHUNK + c;
        #pragma unroll
        for (int n = 0; n < D_STATE; ++n)
            h0buf[(size_t)(bc * D_STATE + n) * INNER + d] = h[n];
        float s = sdtb[(size_t)bc * INNER + d];
        if (uni) {
            float e = __expf(Av[0] * s);
            #pragma unroll
            for (int n = 0; n < D_STATE; ++n)
                h[n] = fmaf(e, h[n],
                            hend[(size_t)(bc * D_STATE + n) * INNER + d]);
        } else {
            #pragma unroll
            for (int n = 0; n < D_STATE; ++n)
                h[n] = fmaf(__expf(Av[n] * s), h[n],
                            hend[(size_t)(bc * D_STATE + n) * INNER + d]);
        }
    }
}

// ---------------- scan pass 2: correct h0, emit gated output (fp16 hi) ----------------
__global__ __launch_bounds__(256)
void scan_pass2(const float* __restrict__ dt, const float* __restrict__ u,
                const float* __restrict__ xz,
                const float* __restrict__ A_log, const float* __restrict__ Bp,
                const float* __restrict__ Cp, const float* __restrict__ Dp,
                const float* __restrict__ h0buf,
                __half* __restrict__ yghi)
{
    int idx = blockIdx.x * blockDim.x + threadIdx.x;
    int d = idx % INNER;
    int c = (idx / INNER) & (NCHUNK - 1);
    int b = idx / (INNER * NCHUNK);
    int bc = b * NCHUNK + c;

    float a0 = A_log[d * D_STATE];
    bool uni = true;
    float Av[D_STATE], Bv[D_STATE], Cv[D_STATE], h[D_STATE];
    #pragma unroll
    for (int n = 0; n < D_STATE; ++n) {
        float al = A_log[d * D_STATE + n];
        uni = uni && (al == a0);
        Av[n] = -__expf(al);
        Bv[n] = Bp[d * D_STATE + n];
        Cv[n] = Cp[d * D_STATE + n];
        h[n]  = h0buf[(size_t)(bc * D_STATE + n) * INNER + d];
    }
    float Dv = Dp[d];

    int t0 = b * SEQLEN + c * CHUNK;
    if (uni) {
        const float Av0 = Av[0];
        for (int j = 0; j < CHUNK; ++j) {
            int t = t0 + j;
            size_t off = (size_t)t * INNER + d;
            float dtv = dt[off];
            float uv  = u[off];
            float du  = dtv * uv;
            float e   = __expf(dtv * Av0);
            float y = 0.0f;
            #pragma unroll
            for (int n = 0; n < D_STATE; ++n) {
                h[n] = fmaf(e, h[n], du * Bv[n]);
                y = fmaf(h[n], Cv[n], y);
            }
            float z = xz[(size_t)t * N2 + INNER + d];
            float v = (y + Dv * uv) * siluf(z);
            yghi[off] = __float2half_rn(v);
        }
    } else {
        for (int j = 0; j < CHUNK; ++j) {
            int t = t0 + j;
            size_t off = (size_t)t * INNER + d;
            float dtv = dt[off];
            float uv  = u[off];
            float du  = dtv * uv;
            float y = 0.0f;
            #pragma unroll
            for (int n = 0; n < D_STATE; ++n) {
                h[n] = fmaf(__expf(dtv * Av[n]), h[n], du * Bv[n]);
                y = fmaf(h[n], Cv[n], y);
            }
            float z = xz[(size_t)t * N2 + INNER + d];
            float v = (y + Dv * uv) * siluf(z);
            yghi[off] = __float2half_rn(v);
        }
    }
}

// ---------------- launcher ----------------
extern "C" void kernel_launch(void* const* d_in, const int* in_sizes, int n_in,
                              void* d_out, int out_size)
{
    const float* hidden    = (const float*)d_in[0];
    const float* in_proj_w = (const float*)d_in[1];
    const float* out_proj_w= (const float*)d_in[2];
    const float* dt_proj_w = (const float*)d_in[3];
    const float* dt_proj_b = (const float*)d_in[4];
    const float* conv_w    = (const float*)d_in[5];
    const float* conv_b    = (const float*)d_in[6];
    const float* A_log     = (const float*)d_in[7];
    const float* B_param   = (const float*)d_in[8];
    const float* C_param   = (const float*)d_in[9];
    const float* D_param   = (const float*)d_in[10];
    const float* dt_bias   = (const float*)d_in[11];
    float* out = (float*)d_out;

    float *xz, *u, *dtb, *hend, *h0, *sdt;
    __half *hid_hi, *wi_hi, *wi_lo, *wd_hi, *wo_hi, *wo_lo, *u_hi, *yg_hi;
    cudaGetSymbolAddress((void**)&xz,     g_xz);
    cudaGetSymbolAddress((void**)&u,      g_u);
    cudaGetSymbolAddress((void**)&dtb,    g_dt);
    cudaGetSymbolAddress((void**)&hend,   g_hend);
    cudaGetSymbolAddress((void**)&h0,     g_h0);
    cudaGetSymbolAddress((void**)&sdt,    g_sdt);
    cudaGetSymbolAddress((void**)&hid_hi, g_hid_hi);
    cudaGetSymbolAddress((void**)&wi_hi,  g_wi_hi);
    cudaGetSymbolAddress((void**)&wi_lo,  g_wi_lo);
    cudaGetSymbolAddress((void**)&wd_hi,  g_wd_hi);
    cudaGetSymbolAddress((void**)&wo_hi,  g_wo_hi);
    cudaGetSymbolAddress((void**)&wo_lo,  g_wo_lo);
    cudaGetSymbolAddress((void**)&u_hi,   g_u_hi);
    cudaGetSymbolAddress((void**)&yg_hi,  g_yg_hi);

    const int SMEM_X2 = 2 * 3 * TILE_B;   // 98304
    const int SMEM_X1 = 2 * 2 * TILE_B;   // 65536
    cudaFuncSetAttribute(gemm_fp16x<0,2>,
                         cudaFuncAttributeMaxDynamicSharedMemorySize, SMEM_X2);
    cudaFuncSetAttribute(gemm_fp16x<1,1>,
                         cudaFuncAttributeMaxDynamicSharedMemorySize, SMEM_X1);

    // 0) fp16 splits (single merged kernel)
    split_all<<<SPL_TOT4 / 256, 256>>>(hidden, in_proj_w, dt_proj_w, out_proj_w,
                                       hid_hi, wi_hi, wi_lo, wd_hi, wo_hi, wo_lo);

    // 1) in_proj (x2): xz[4096,3072] = hid * wi^T
    {
        dim3 grid(N2 / 128, NTOK / 128);
        gemm_fp16x<0,2><<<grid, 256, SMEM_X2>>>(hid_hi, hid_hi, wi_hi, wi_lo,
                                                xz, NTOK, N2, D_MODEL, nullptr, nullptr);
    }
    // 2) depthwise conv + SiLU -> u (+ fp16 hi)
    conv_silu_kernel<<<NTOK * INNER / 4 / 256, 256>>>(xz, conv_w, conv_b, u, u_hi);
    // 3) dt_proj + softplus (x1)
    {
        dim3 grid(INNER / 128, NTOK / 128);
        gemm_fp16x<1,1><<<grid, 256, SMEM_X1>>>(u_hi, u_hi, wd_hi, wd_hi,
                                                dtb, NTOK, INNER, INNER,
                                                dt_proj_b, dt_bias);
    }
    // 4) chunked selective scan
    {
        int n1 = BATCH * NCHUNK * INNER;
        scan_pass1<<<n1 / 256, 256>>>(dtb, u, A_log, B_param, hend, sdt);
        scan_fix<<<(BATCH * INNER + 255) / 256, 256>>>(A_log, hend, sdt, h0);
        scan_pass2<<<n1 / 256, 256>>>(dtb, u, xz, A_log, B_param, C_param,
                                      D_param, h0, yg_hi);
    }
    // 5) out_proj (x2): out[4096,768] = yg * wo^T
    {
        dim3 grid(D_MODEL / 128, NTOK / 128);
        gemm_fp16x<0,2><<<grid, 256, SMEM_X2>>>(yg_hi, yg_hi, wo_hi, wo_lo,
                                                out, NTOK, D_MODEL, INNER, nullptr, nullptr);
    }
}

// round 10
// speedup vs baseline: 4.7832x; 1.1752x over previous
#include <cuda_runtime.h>
#include <cuda_fp16.h>
#include <math.h>
#include <stdint.h>

// ---------------- problem constants ----------------
#define D_MODEL 768
#define D_STATE 16
#define D_CONV  4
#define INNER   1536
#define N2      (2*INNER)     // 3072
#define BATCH   2
#define SEQLEN  2048
#define NTOK    (BATCH*SEQLEN)  // 4096
#define NCHUNK  64
#define CHUNK   (SEQLEN/NCHUNK) // 32

// ---------------- scratch (static device globals; no allocation) ----------------
__device__ float g_xz  [NTOK * N2];
__device__ float g_u   [NTOK * INNER];
__device__ float g_dt  [NTOK * INNER];
__device__ float g_hend[BATCH*NCHUNK*D_STATE*INNER];
__device__ float g_h0  [BATCH*NCHUNK*D_STATE*INNER];
__device__ float g_sdt [BATCH*NCHUNK*INNER];

// fp16 splits
__device__ __half g_hid_hi[NTOK * D_MODEL];
__device__ __half g_wi_hi [N2 * D_MODEL];
__device__ __half g_wi_lo [N2 * D_MODEL];
__device__ __half g_wd_hi [INNER * INNER];
__device__ __half g_wo_hi [D_MODEL * INNER];
__device__ __half g_wo_lo [D_MODEL * INNER];
__device__ __half g_u_hi  [NTOK * INNER];
__device__ __half g_yg_hi [NTOK * INNER];

// ---------------- helpers ----------------
__device__ __forceinline__ float siluf(float x) {
    return x * (1.0f / (1.0f + __expf(-x)));
}
__device__ __forceinline__ float softplusf(float x) {
    return fmaxf(x, 0.0f) + log1pf(__expf(-fabsf(x)));
}
__device__ __forceinline__ uint32_t smem_u32(const void* p) {
    uint32_t a;
    asm("{ .reg .u64 t; cvta.to.shared.u64 t, %1; cvt.u32.u64 %0, t; }"
        : "=r"(a) : "l"(p));
    return a;
}
__device__ __forceinline__ void cp16(uint32_t s, const void* g) {
    asm volatile("cp.async.cg.shared.global [%0], [%1], 16;\n" :: "r"(s), "l"(g));
}
__device__ __forceinline__ void cp_commit() {
    asm volatile("cp.async.commit_group;\n");
}
template<int N> __device__ __forceinline__ void cp_wait() {
    asm volatile("cp.async.wait_group %0;\n" :: "n"(N));
}
__device__ __forceinline__ void ldm_x4(uint32_t a, uint32_t* r) {
    asm volatile("ldmatrix.sync.aligned.m8n8.x4.shared.b16 {%0,%1,%2,%3}, [%4];"
                 : "=r"(r[0]), "=r"(r[1]), "=r"(r[2]), "=r"(r[3]) : "r"(a));
}
__device__ __forceinline__ void mma_fp16(float* d, const uint32_t* a,
                                         uint32_t b0, uint32_t b1) {
    asm volatile(
        "mma.sync.aligned.m16n8k16.row.col.f32.f16.f16.f32 "
        "{%0,%1,%2,%3}, {%4,%5,%6,%7}, {%8,%9}, {%0,%1,%2,%3};\n"
        : "+f"(d[0]), "+f"(d[1]), "+f"(d[2]), "+f"(d[3])
        : "r"(a[0]), "r"(a[1]), "r"(a[2]), "r"(a[3]), "r"(b0), "r"(b1));
}
__device__ __forceinline__ void store_h4(__half* p, float4 v) {
    __half2 a = __floats2half2_rn(v.x, v.y);
    __half2 b = __floats2half2_rn(v.z, v.w);
    uint2 o;
    o.x = *(uint32_t*)&a;
    o.y = *(uint32_t*)&b;
    *(uint2*)p = o;
}

// ---------------- merged split kernel ----------------
#define SPL_N0 (NTOK*D_MODEL)
#define SPL_N1 (N2*D_MODEL)
#define SPL_N2 (INNER*INNER)
#define SPL_N3 (D_MODEL*INNER)
#define SPL_TOT4 ((SPL_N0+SPL_N1+SPL_N2+SPL_N3)/4)

__device__ __forceinline__ void cvt4_hi(const float* s, __half* h) {
    float4 v = *(const float4*)s;
    store_h4(h, v);
}
__device__ __forceinline__ void cvt4_hilo(const float* s, __half* h, __half* l) {
    float4 v = *(const float4*)s;
    __half2 a = __floats2half2_rn(v.x, v.y);
    __half2 b = __floats2half2_rn(v.z, v.w);
    uint2 o; o.x = *(uint32_t*)&a; o.y = *(uint32_t*)&b;
    *(uint2*)h = o;
    float2 fa = __half22float2(a), fb = __half22float2(b);
    float4 r = make_float4(v.x - fa.x, v.y - fa.y, v.z - fb.x, v.w - fb.y);
    store_h4(l, r);
}

__global__ __launch_bounds__(256)
void split_all(const float* __restrict__ hidden, const float* __restrict__ wi,
               const float* __restrict__ wd, const float* __restrict__ wo,
               __half* __restrict__ hid_hi,
               __half* __restrict__ wi_hi, __half* __restrict__ wi_lo,
               __half* __restrict__ wd_hi,
               __half* __restrict__ wo_hi, __half* __restrict__ wo_lo)
{
    int idx = (blockIdx.x * blockDim.x + threadIdx.x) * 4;
    if (idx < SPL_N0) {
        cvt4_hi(hidden + idx, hid_hi + idx);
    } else if ((idx -= SPL_N0) < SPL_N1) {
        cvt4_hilo(wi + idx, wi_hi + idx, wi_lo + idx);
    } else if ((idx -= SPL_N1) < SPL_N2) {
        cvt4_hi(wd + idx, wd_hi + idx);
    } else if ((idx -= SPL_N2) < SPL_N3) {
        cvt4_hilo(wo + idx, wo_hi + idx, wo_lo + idx);
    }
}

// ---------------- fp16xN NT GEMM (128x128 tiles) ----------------
// NMMA=2: AhBh+AhBl (A-lo not staged). NMMA=1: AhBh only.
// EPI: 0 plain, 1 softplus(x + b1[col] + b2[col])
#define TILE_B 16384

template<int EPI, int NMMA>
__global__ __launch_bounds__(256)
void gemm_fp16x(const __half* __restrict__ Ahi, const __half* __restrict__ Bhi,
                const __half* __restrict__ Blo,
                float* __restrict__ C, int M, int N, int K,
                const float* __restrict__ b1, const float* __restrict__ b2)
{
    constexpr int NT = (NMMA == 2) ? 3 : 2;
    extern __shared__ char smem[];
    const uint32_t sb = smem_u32(smem);

    const int tid  = threadIdx.x;
    const int wid  = tid >> 5;
    const int lane = tid & 31;
    const int wm   = wid & 1;
    const int wn   = wid >> 1;
    const int g    = lane >> 3;
    const int lr   = lane & 7;

    const int row0 = blockIdx.y * 128;
    const int col0 = blockIdx.x * 128;

    const __half* srcs[NT];
    {
        int nt = 0;
        srcs[nt++] = Ahi + (size_t)row0 * K;
        srcs[nt++] = Bhi + (size_t)col0 * K;
        if (NMMA >= 2) srcs[nt++] = Blo + (size_t)col0 * K;
    }

    float acc[4][4][4];
    #pragma unroll
    for (int mt = 0; mt < 4; ++mt)
        #pragma unroll
        for (int nt = 0; nt < 4; ++nt)
            #pragma unroll
            for (int r = 0; r < 4; ++r) acc[mt][nt][r] = 0.0f;

    auto load_stage = [&](int s, int kc) {
        #pragma unroll
        for (int t = 0; t < NT; ++t) {
            uint32_t dst = sb + (uint32_t)(s * NT + t) * TILE_B;
            const __half* src = srcs[t] + kc;
            #pragma unroll
            for (int i = 0; i < 4; ++i) {
                int c = tid + i * 256;
                int r = c >> 3, ch = c & 7;
                cp16(dst + r * 128 + ((ch ^ (r & 7)) << 4),
                     src + (size_t)r * K + ch * 8);
            }
        }
    };

    const int KT = K / 64;
    load_stage(0, 0);
    cp_commit();

    for (int kt = 0; kt < KT; ++kt) {
        if (kt + 1 < KT) {
            load_stage((kt + 1) & 1, (kt + 1) * 64);
            cp_commit();
            cp_wait<1>();
        } else {
            cp_wait<0>();
        }
        __syncthreads();

        const uint32_t st  = sb + (uint32_t)(kt & 1) * NT * TILE_B;
        const uint32_t sAh = st;
        const uint32_t sBh = st + TILE_B;
        const uint32_t sBl = sBh + TILE_B;   // valid iff NMMA>=2

        #pragma unroll
        for (int k16 = 0; k16 < 4; ++k16) {
            const int c0 = k16 * 2;
            const int arow_off = ((g & 1) << 3) + lr;
            const int ach = c0 + (g >> 1);
            const int brow_off = ((g >> 1) << 3) + lr;
            const int bch = c0 + (g & 1);

            uint32_t ah[4][4];
            #pragma unroll
            for (int mt = 0; mt < 4; ++mt) {
                int row = wm * 64 + mt * 16 + arow_off;
                uint32_t off = row * 128 + (((ach ^ (row & 7))) << 4);
                ldm_x4(sAh + off, ah[mt]);
            }
            uint32_t bh[4][2], bl[4][2];
            #pragma unroll
            for (int nn = 0; nn < 2; ++nn) {
                int row = wn * 32 + nn * 16 + brow_off;
                uint32_t off = row * 128 + (((bch ^ (row & 7))) << 4);
                uint32_t t4[4];
                ldm_x4(sBh + off, t4);
                bh[nn*2][0] = t4[0]; bh[nn*2][1] = t4[1];
                bh[nn*2+1][0] = t4[2]; bh[nn*2+1][1] = t4[3];
                if (NMMA >= 2) {
                    ldm_x4(sBl + off, t4);
                    bl[nn*2][0] = t4[0]; bl[nn*2][1] = t4[1];
                    bl[nn*2+1][0] = t4[2]; bl[nn*2+1][1] = t4[3];
                }
            }
            #pragma unroll
            for (int mt = 0; mt < 4; ++mt)
                #pragma unroll
                for (int nt = 0; nt < 4; ++nt) {
                    mma_fp16(acc[mt][nt], ah[mt], bh[nt][0], bh[nt][1]);
                    if (NMMA >= 2)
                        mma_fp16(acc[mt][nt], ah[mt], bl[nt][0], bl[nt][1]);
                }
        }
        __syncthreads();
    }

    const int qr = lane >> 2;
    const int qc = (lane & 3) * 2;
    #pragma unroll
    for (int mt = 0; mt < 4; ++mt) {
        #pragma unroll
        for (int nt = 0; nt < 4; ++nt) {
            int gr = row0 + wm * 64 + mt * 16 + qr;
            int gc = col0 + wn * 32 + nt * 8 + qc;
            float v0 = acc[mt][nt][0], v1 = acc[mt][nt][1];
            float v2 = acc[mt][nt][2], v3 = acc[mt][nt][3];
            if (EPI == 1) {
                float e0 = b1[gc] + b2[gc];
                float e1 = b1[gc + 1] + b2[gc + 1];
                v0 = softplusf(v0 + e0); v1 = softplusf(v1 + e1);
                v2 = softplusf(v2 + e0); v3 = softplusf(v3 + e1);
            }
            *(float2*)&C[(size_t)gr * N + gc]       = make_float2(v0, v1);
            *(float2*)&C[(size_t)(gr + 8) * N + gc] = make_float2(v2, v3);
        }
    }
}

// ---------------- out_proj GEMM: 64x64 tiles, x2, 3-stage, 3 CTAs/SM ----------------
// warp layout: 2x4 of 32x16 warptiles. smem/stage = 3*8192 = 24576.
#define OTILE 8192
#define OSTAGE 24576
#define OSMEM (3 * OSTAGE)   // 73728

__global__ __launch_bounds__(256, 3)
void gemm_out64(const __half* __restrict__ Ahi, const __half* __restrict__ Bhi,
                const __half* __restrict__ Blo,
                float* __restrict__ C, int M, int N, int K)
{
    extern __shared__ char smem[];
    const uint32_t sb = smem_u32(smem);

    const int tid  = threadIdx.x;
    const int wid  = tid >> 5;
    const int lane = tid & 31;
    const int wm   = wid & 1;     // rows wm*32
    const int wn   = wid >> 1;    // cols wn*16
    const int g    = lane >> 3;
    const int lr   = lane & 7;

    const int row0 = blockIdx.y * 64;
    const int col0 = blockIdx.x * 64;

    const __half* sA  = Ahi + (size_t)row0 * K;
    const __half* sBh = Bhi + (size_t)col0 * K;
    const __half* sBl = Blo + (size_t)col0 * K;

    float acc[2][2][4];
    #pragma unroll
    for (int mt = 0; mt < 2; ++mt)
        #pragma unroll
        for (int nt = 0; nt < 2; ++nt)
            #pragma unroll
            for (int r = 0; r < 4; ++r) acc[mt][nt][r] = 0.0f;

    auto load_stage = [&](int s, int kc) {
        uint32_t base = sb + (uint32_t)s * OSTAGE;
        const __half* gp[3] = { sA + kc, sBh + kc, sBl + kc };
        #pragma unroll
        for (int t = 0; t < 3; ++t) {
            uint32_t dst = base + (uint32_t)t * OTILE;
            const __half* src = gp[t];
            #pragma unroll
            for (int i = 0; i < 2; ++i) {
                int c = tid + i * 256;
                int r = c >> 3, ch = c & 7;
                cp16(dst + r * 128 + ((ch ^ (r & 7)) << 4),
                     src + (size_t)r * K + ch * 8);
            }
        }
    };

    const int KT = K / 64;   // 24
    load_stage(0, 0); cp_commit();
    load_stage(1, 64); cp_commit();

    int st = 0;
    for (int kt = 0; kt < KT; ++kt) {
        if (kt + 1 < KT) cp_wait<1>(); else cp_wait<0>();
        __syncthreads();
        if (kt + 2 < KT) {
            int ns = st + 2; if (ns >= 3) ns -= 3;
            load_stage(ns, (kt + 2) * 64);
            cp_commit();
        }

        const uint32_t base = sb + (uint32_t)st * OSTAGE;
        const uint32_t mA  = base;
        const uint32_t mBh = base + OTILE;
        const uint32_t mBl = base + 2 * OTILE;

        #pragma unroll
        for (int k16 = 0; k16 < 4; ++k16) {
            const int c0 = k16 * 2;
            const int arow_off = ((g & 1) << 3) + lr;
            const int ach = c0 + (g >> 1);
            const int brow_off = ((g >> 1) << 3) + lr;
            const int bch = c0 + (g & 1);

            uint32_t ah[2][4];
            #pragma unroll
            for (int mt = 0; mt < 2; ++mt) {
                int row = wm * 32 + mt * 16 + arow_off;
                uint32_t off = row * 128 + (((ach ^ (row & 7))) << 4);
                ldm_x4(mA + off, ah[mt]);
            }
            uint32_t bh[2][2], bl[2][2];
            {
                int row = wn * 16 + brow_off;
                uint32_t off = row * 128 + (((bch ^ (row & 7))) << 4);
                uint32_t t4[4];
                ldm_x4(mBh + off, t4);
                bh[0][0] = t4[0]; bh[0][1] = t4[1];
                bh[1][0] = t4[2]; bh[1][1] = t4[3];
                ldm_x4(mBl + off, t4);
                bl[0][0] = t4[0]; bl[0][1] = t4[1];
                bl[1][0] = t4[2]; bl[1][1] = t4[3];
            }
            #pragma unroll
            for (int mt = 0; mt < 2; ++mt)
                #pragma unroll
                for (int nt = 0; nt < 2; ++nt) {
                    mma_fp16(acc[mt][nt], ah[mt], bh[nt][0], bh[nt][1]);
                    mma_fp16(acc[mt][nt], ah[mt], bl[nt][0], bl[nt][1]);
                }
        }
        if (++st == 3) st = 0;
    }

    const int qr = lane >> 2;
    const int qc = (lane & 3) * 2;
    #pragma unroll
    for (int mt = 0; mt < 2; ++mt) {
        #pragma unroll
        for (int nt = 0; nt < 2; ++nt) {
            int gr = row0 + wm * 32 + mt * 16 + qr;
            int gc = col0 + wn * 16 + nt * 8 + qc;
            *(float2*)&C[(size_t)gr * N + gc] =
                make_float2(acc[mt][nt][0], acc[mt][nt][1]);
            *(float2*)&C[(size_t)(gr + 8) * N + gc] =
                make_float2(acc[mt][nt][2], acc[mt][nt][3]);
        }
    }
}

// ---------------- depthwise causal conv(4) + bias + SiLU ----------------
__global__ __launch_bounds__(256)
void conv_silu_kernel(const float* __restrict__ xz,
                      const float* __restrict__ cw,
                      const float* __restrict__ cb,
                      float* __restrict__ u,
                      __half* __restrict__ uhi)
{
    int idx4 = blockIdx.x * blockDim.x + threadIdx.x;
    int base = idx4 * 4;
    if (base >= NTOK * INNER) return;
    int c = base % INNER;
    int t = base / INNER;
    int l = t & (SEQLEN - 1);

    float4 acc = *(const float4*)(cb + c);
    float4 w0 = *(const float4*)(cw + (c + 0) * D_CONV);
    float4 w1 = *(const float4*)(cw + (c + 1) * D_CONV);
    float4 w2 = *(const float4*)(cw + (c + 2) * D_CONV);
    float4 w3 = *(const float4*)(cw + (c + 3) * D_CONV);
    const float* pw0 = (const float*)&w0;
    const float* pw1 = (const float*)&w1;
    const float* pw2 = (const float*)&w2;
    const float* pw3 = (const float*)&w3;

    #pragma unroll
    for (int k = 0; k < D_CONV; ++k) {
        int ll = l - (D_CONV - 1) + k;
        if (ll >= 0) {
            float4 x = *(const float4*)(xz + (size_t)(t - (D_CONV - 1) + k) * N2 + c);
            acc.x = fmaf(pw0[k], x.x, acc.x);
            acc.y = fmaf(pw1[k], x.y, acc.y);
            acc.z = fmaf(pw2[k], x.z, acc.z);
            acc.w = fmaf(pw3[k], x.w, acc.w);
        }
    }
    float4 v = make_float4(siluf(acc.x), siluf(acc.y), siluf(acc.z), siluf(acc.w));
    *(float4*)(u + base) = v;
    store_h4(uhi + base, v);
}

// ---------------- scan pass 1 ----------------
__global__ __launch_bounds__(256)
void scan_pass1(const float* __restrict__ dt, const float* __restrict__ u,
                const float* __restrict__ A_log, const float* __restrict__ Bp,
                float* __restrict__ hend, float* __restrict__ sdtb)
{
    int idx = blockIdx.x * blockDim.x + threadIdx.x;
    int d = idx % INNER;
    int c = (idx / INNER) & (NCHUNK - 1);
    int b = idx / (INNER * NCHUNK);

    float a0 = A_log[d * D_STATE];
    bool uni = true;
    float Av[D_STATE], Bv[D_STATE], h[D_STATE];
    #pragma unroll
    for (int n = 0; n < D_STATE; ++n) {
        float al = A_log[d * D_STATE + n];
        uni = uni && (al == a0);
        Av[n] = -__expf(al);
        Bv[n] = Bp[d * D_STATE + n];
        h[n]  = 0.0f;
    }
    float sdt = 0.0f;
    int t0 = b * SEQLEN + c * CHUNK;

    if (uni) {
        const float Av0 = Av[0];
        for (int j = 0; j < CHUNK; ++j) {
            size_t off = (size_t)(t0 + j) * INNER + d;
            float dtv = dt[off];
            float uv  = u[off];
            sdt += dtv;
            float du = dtv * uv;
            float e  = __expf(dtv * Av0);
            #pragma unroll
            for (int n = 0; n < D_STATE; ++n)
                h[n] = fmaf(e, h[n], du * Bv[n]);
        }
    } else {
        for (int j = 0; j < CHUNK; ++j) {
            size_t off = (size_t)(t0 + j) * INNER + d;
            float dtv = dt[off];
            float uv  = u[off];
            sdt += dtv;
            float du = dtv * uv;
            #pragma unroll
            for (int n = 0; n < D_STATE; ++n)
                h[n] = fmaf(__expf(dtv * Av[n]), h[n], du * Bv[n]);
        }
    }
    int bc = b * NCHUNK + c;
    #pragma unroll
    for (int n = 0; n < D_STATE; ++n)
        hend[(size_t)(bc * D_STATE + n) * INNER + d] = h[n];
    sdtb[(size_t)bc * INNER + d] = sdt;
}

// ---------------- scan fixup: parallel over (b, n, d); serial over chunks ----------------
__global__ __launch_bounds__(256)
void scan_fix(const float* __restrict__ A_log,
              const float* __restrict__ hend, const float* __restrict__ sdtb,
              float* __restrict__ h0buf)
{
    int idx = blockIdx.x * blockDim.x + threadIdx.x;
    if (idx >= BATCH * INNER * D_STATE) return;
    int d = idx % INNER;
    int n = (idx / INNER) % D_STATE;
    int b = idx / (INNER * D_STATE);

    float Av = -__expf(A_log[d * D_STATE + n]);
    float h = 0.0f;
    const size_t nd = (size_t)n * INNER + d;
    for (int c = 0; c < NCHUNK; ++c) {
        int bc = b * NCHUNK + c;
        h0buf[(size_t)bc * D_STATE * INNER + nd] = h;
        float s = sdtb[(size_t)bc * INNER + d];
        h = fmaf(__expf(Av * s), h, hend[(size_t)bc * D_STATE * INNER + nd]);
    }
}

// ---------------- scan pass 2 ----------------
__global__ __launch_bounds__(256)
void scan_pass2(const float* __restrict__ dt, const float* __restrict__ u,
                const float* __restrict__ xz,
                const float* __restrict__ A_log, const float* __restrict__ Bp,
                const float* __restrict__ Cp, const float* __restrict__ Dp,
                const float* __restrict__ h0buf,
                __half* __restrict__ yghi)
{
    int idx = blockIdx.x * blockDim.x + threadIdx.x;
    int d = idx % INNER;
    int c = (idx / INNER) & (NCHUNK - 1);
    int b = idx / (INNER * NCHUNK);
    int bc = b * NCHUNK + c;

    float a0 = A_log[d * D_STATE];
    bool uni = true;
    float Av[D_STATE], Bv[D_STATE], Cv[D_STATE], h[D_STATE];
    #pragma unroll
    for (int n = 0; n < D_STATE; ++n) {
        float al = A_log[d * D_STATE + n];
        uni = uni && (al == a0);
        Av[n] = -__expf(al);
        Bv[n] = Bp[d * D_STATE + n];
        Cv[n] = Cp[d * D_STATE + n];
        h[n]  = h0buf[(size_t)(bc * D_STATE + n) * INNER + d];
    }
    float Dv = Dp[d];

    int t0 = b * SEQLEN + c * CHUNK;
    if (uni) {
        const float Av0 = Av[0];
        for (int j = 0; j < CHUNK; ++j) {
            int t = t0 + j;
            size_t off = (size_t)t * INNER + d;
            float dtv = dt[off];
            float uv  = u[off];
            float du  = dtv * uv;
            float e   = __expf(dtv * Av0);
            float y = 0.0f;
            #pragma unroll
            for (int n = 0; n < D_STATE; ++n) {
                h[n] = fmaf(e, h[n], du * Bv[n]);
                y = fmaf(h[n], Cv[n], y);
            }
            float z = xz[(size_t)t * N2 + INNER + d];
            float v = (y + Dv * uv) * siluf(z);
            yghi[off] = __float2half_rn(v);
        }
    } else {
        for (int j = 0; j < CHUNK; ++j) {
            int t = t0 + j;
            size_t off = (size_t)t * INNER + d;
            float dtv = dt[off];
            float uv  = u[off];
            float du  = dtv * uv;
            float y = 0.0f;
            #pragma unroll
            for (int n = 0; n < D_STATE; ++n) {
                h[n] = fmaf(__expf(dtv * Av[n]), h[n], du * Bv[n]);
                y = fmaf(h[n], Cv[n], y);
            }
            float z = xz[(size_t)t * N2 + INNER + d];
            float v = (y + Dv * uv) * siluf(z);
            yghi[off] = __float2half_rn(v);
        }
    }
}

// ---------------- launcher ----------------
extern "C" void kernel_launch(void* const* d_in, const int* in_sizes, int n_in,
                              void* d_out, int out_size)
{
    const float* hidden    = (const float*)d_in[0];
    const float* in_proj_w = (const float*)d_in[1];
    const float* out_proj_w= (const float*)d_in[2];
    const float* dt_proj_w = (const float*)d_in[3];
    const float* dt_proj_b = (const float*)d_in[4];
    const float* conv_w    = (const float*)d_in[5];
    const float* conv_b    = (const float*)d_in[6];
    const float* A_log     = (const float*)d_in[7];
    const float* B_param   = (const float*)d_in[8];
    const float* C_param   = (const float*)d_in[9];
    const float* D_param   = (const float*)d_in[10];
    const float* dt_bias   = (const float*)d_in[11];
    float* out = (float*)d_out;

    float *xz, *u, *dtb, *hend, *h0, *sdt;
    __half *hid_hi, *wi_hi, *wi_lo, *wd_hi, *wo_hi, *wo_lo, *u_hi, *yg_hi;
    cudaGetSymbolAddress((void**)&xz,     g_xz);
    cudaGetSymbolAddress((void**)&u,      g_u);
    cudaGetSymbolAddress((void**)&dtb,    g_dt);
    cudaGetSymbolAddress((void**)&hend,   g_hend);
    cudaGetSymbolAddress((void**)&h0,     g_h0);
    cudaGetSymbolAddress((void**)&sdt,    g_sdt);
    cudaGetSymbolAddress((void**)&hid_hi, g_hid_hi);
    cudaGetSymbolAddress((void**)&wi_hi,  g_wi_hi);
    cudaGetSymbolAddress((void**)&wi_lo,  g_wi_lo);
    cudaGetSymbolAddress((void**)&wd_hi,  g_wd_hi);
    cudaGetSymbolAddress((void**)&wo_hi,  g_wo_hi);
    cudaGetSymbolAddress((void**)&wo_lo,  g_wo_lo);
    cudaGetSymbolAddress((void**)&u_hi,   g_u_hi);
    cudaGetSymbolAddress((void**)&yg_hi,  g_yg_hi);

    const int SMEM_X2 = 2 * 3 * TILE_B;   // 98304
    const int SMEM_X1 = 2 * 2 * TILE_B;   // 65536
    cudaFuncSetAttribute(gemm_fp16x<0,2>,
                         cudaFuncAttributeMaxDynamicSharedMemorySize, SMEM_X2);
    cudaFuncSetAttribute(gemm_fp16x<0,1>,
                         cudaFuncAttributeMaxDynamicSharedMemorySize, SMEM_X1);
    cudaFuncSetAttribute(gemm_fp16x<1,1>,
                         cudaFuncAttributeMaxDynamicSharedMemorySize, SMEM_X1);
    cudaFuncSetAttribute(gemm_out64,
                         cudaFuncAttributeMaxDynamicSharedMemorySize, OSMEM);

    // 0) fp16 splits
    split_all<<<SPL_TOT4 / 256, 256>>>(hidden, in_proj_w, dt_proj_w, out_proj_w,
                                       hid_hi, wi_hi, wi_lo, wd_hi, wo_hi, wo_lo);

    // 1a) in_proj proj half (x2): cols 0..1535 of xz
    {
        dim3 grid(INNER / 128, NTOK / 128);
        gemm_fp16x<0,2><<<grid, 256, SMEM_X2>>>(hid_hi, wi_hi, wi_lo,
                                                xz, NTOK, N2, D_MODEL,
                                                nullptr, nullptr);
    }
    // 1b) in_proj gate half (x1): cols 1536..3071 of xz
    {
        dim3 grid(INNER / 128, NTOK / 128);
        gemm_fp16x<0,1><<<grid, 256, SMEM_X1>>>(hid_hi,
                                                wi_hi + (size_t)INNER * D_MODEL,
                                                nullptr,
                                                xz + INNER, NTOK, N2, D_MODEL,
                                                nullptr, nullptr);
    }
    // 2) depthwise conv + SiLU -> u (+ fp16 hi)
    conv_silu_kernel<<<NTOK * INNER / 4 / 256, 256>>>(xz, conv_w, conv_b, u, u_hi);
    // 3) dt_proj + softplus (x1)
    {
        dim3 grid(INNER / 128, NTOK / 128);
        gemm_fp16x<1,1><<<grid, 256, SMEM_X1>>>(u_hi, wd_hi, nullptr,
                                                dtb, NTOK, INNER, INNER,
                                                dt_proj_b, dt_bias);
    }
    // 4) chunked selective scan
    {
        int n1 = BATCH * NCHUNK * INNER;
        scan_pass1<<<n1 / 256, 256>>>(dtb, u, A_log, B_param, hend, sdt);
        scan_fix<<<(BATCH * INNER * D_STATE) / 256, 256>>>(A_log, hend, sdt, h0);
        scan_pass2<<<n1 / 256, 256>>>(dtb, u, xz, A_log, B_param, C_param,
                                      D_param, h0, yg_hi);
    }
    // 5) out_proj (x2, 64x64 tiles)
    {
        dim3 grid(D_MODEL / 64, NTOK / 64);
        gemm_out64<<<grid, 256, OSMEM>>>(yg_hi, wo_hi, wo_lo,
                                         out, NTOK, D_MODEL, INNER);
    }
}

// round 11
// speedup vs baseline: 5.1610x; 1.0790x over previous
#include <cuda_runtime.h>
#include <cuda_fp16.h>
#include <math.h>
#include <stdint.h>

// ---------------- problem constants ----------------
#define D_MODEL 768
#define D_STATE 16
#define D_CONV  4
#define INNER   1536
#define N2      (2*INNER)     // 3072
#define BATCH   2
#define SEQLEN  2048
#define NTOK    (BATCH*SEQLEN)  // 4096
#define NCHUNK  64
#define CHUNK   (SEQLEN/NCHUNK) // 32
#define CT      8               // conv timesteps per thread

// ---------------- scratch (static device globals; no allocation) ----------------
__device__ float g_xz  [NTOK * N2];
__device__ float g_u   [NTOK * INNER];
__device__ float g_dt  [NTOK * INNER];
__device__ float g_hend[BATCH*NCHUNK*D_STATE*INNER];
__device__ float g_h0  [BATCH*NCHUNK*D_STATE*INNER];
__device__ float g_sdt [BATCH*NCHUNK*INNER];

// fp16 splits
__device__ __half g_hid_hi[NTOK * D_MODEL];
__device__ __half g_wi_hi [N2 * D_MODEL];
__device__ __half g_wi_lo [N2 * D_MODEL];
__device__ __half g_wd_hi [INNER * INNER];
__device__ __half g_wo_hi [D_MODEL * INNER];
__device__ __half g_u_hi  [NTOK * INNER];
__device__ __half g_yg_hi [NTOK * INNER];

// ---------------- helpers ----------------
__device__ __forceinline__ float siluf(float x) {
    return x * (1.0f / (1.0f + __expf(-x)));
}
__device__ __forceinline__ float softplusf(float x) {
    return fmaxf(x, 0.0f) + log1pf(__expf(-fabsf(x)));
}
__device__ __forceinline__ uint32_t smem_u32(const void* p) {
    uint32_t a;
    asm("{ .reg .u64 t; cvta.to.shared.u64 t, %1; cvt.u32.u64 %0, t; }"
        : "=r"(a) : "l"(p));
    return a;
}
__device__ __forceinline__ void cp16(uint32_t s, const void* g) {
    asm volatile("cp.async.cg.shared.global [%0], [%1], 16;\n" :: "r"(s), "l"(g));
}
__device__ __forceinline__ void cp_commit() {
    asm volatile("cp.async.commit_group;\n");
}
template<int N> __device__ __forceinline__ void cp_wait() {
    asm volatile("cp.async.wait_group %0;\n" :: "n"(N));
}
__device__ __forceinline__ void ldm_x4(uint32_t a, uint32_t* r) {
    asm volatile("ldmatrix.sync.aligned.m8n8.x4.shared.b16 {%0,%1,%2,%3}, [%4];"
                 : "=r"(r[0]), "=r"(r[1]), "=r"(r[2]), "=r"(r[3]) : "r"(a));
}
__device__ __forceinline__ void mma_fp16(float* d, const uint32_t* a,
                                         uint32_t b0, uint32_t b1) {
    asm volatile(
        "mma.sync.aligned.m16n8k16.row.col.f32.f16.f16.f32 "
        "{%0,%1,%2,%3}, {%4,%5,%6,%7}, {%8,%9}, {%0,%1,%2,%3};\n"
        : "+f"(d[0]), "+f"(d[1]), "+f"(d[2]), "+f"(d[3])
        : "r"(a[0]), "r"(a[1]), "r"(a[2]), "r"(a[3]), "r"(b0), "r"(b1));
}
__device__ __forceinline__ void store_h4(__half* p, float4 v) {
    __half2 a = __floats2half2_rn(v.x, v.y);
    __half2 b = __floats2half2_rn(v.z, v.w);
    uint2 o;
    o.x = *(uint32_t*)&a;
    o.y = *(uint32_t*)&b;
    *(uint2*)p = o;
}

// ---------------- merged split kernel ----------------
#define SPL_N0 (NTOK*D_MODEL)
#define SPL_N1 (N2*D_MODEL)
#define SPL_N2 (INNER*INNER)
#define SPL_N3 (D_MODEL*INNER)
#define SPL_TOT4 ((SPL_N0+SPL_N1+SPL_N2+SPL_N3)/4)

__device__ __forceinline__ void cvt4_hi(const float* s, __half* h) {
    float4 v = *(const float4*)s;
    store_h4(h, v);
}
__device__ __forceinline__ void cvt4_hilo(const float* s, __half* h, __half* l) {
    float4 v = *(const float4*)s;
    __half2 a = __floats2half2_rn(v.x, v.y);
    __half2 b = __floats2half2_rn(v.z, v.w);
    uint2 o; o.x = *(uint32_t*)&a; o.y = *(uint32_t*)&b;
    *(uint2*)h = o;
    float2 fa = __half22float2(a), fb = __half22float2(b);
    float4 r = make_float4(v.x - fa.x, v.y - fa.y, v.z - fb.x, v.w - fb.y);
    store_h4(l, r);
}

__global__ __launch_bounds__(256)
void split_all(const float* __restrict__ hidden, const float* __restrict__ wi,
               const float* __restrict__ wd, const float* __restrict__ wo,
               __half* __restrict__ hid_hi,
               __half* __restrict__ wi_hi, __half* __restrict__ wi_lo,
               __half* __restrict__ wd_hi,
               __half* __restrict__ wo_hi)
{
    int idx = (blockIdx.x * blockDim.x + threadIdx.x) * 4;
    if (idx < SPL_N0) {
        cvt4_hi(hidden + idx, hid_hi + idx);
    } else if ((idx -= SPL_N0) < SPL_N1) {
        cvt4_hilo(wi + idx, wi_hi + idx, wi_lo + idx);
    } else if ((idx -= SPL_N1) < SPL_N2) {
        cvt4_hi(wd + idx, wd_hi + idx);
    } else if ((idx -= SPL_N2) < SPL_N3) {
        cvt4_hi(wo + idx, wo_hi + idx);
    }
}

// ---------------- fp16xN NT GEMM (128x128 tiles) ----------------
#define TILE_B 16384

template<int EPI, int NMMA>
__global__ __launch_bounds__(256)
void gemm_fp16x(const __half* __restrict__ Ahi, const __half* __restrict__ Bhi,
                const __half* __restrict__ Blo,
                float* __restrict__ C, int M, int N, int K,
                const float* __restrict__ b1, const float* __restrict__ b2)
{
    constexpr int NT = (NMMA == 2) ? 3 : 2;
    extern __shared__ char smem[];
    const uint32_t sb = smem_u32(smem);

    const int tid  = threadIdx.x;
    const int wid  = tid >> 5;
    const int lane = tid & 31;
    const int wm   = wid & 1;
    const int wn   = wid >> 1;
    const int g    = lane >> 3;
    const int lr   = lane & 7;

    const int row0 = blockIdx.y * 128;
    const int col0 = blockIdx.x * 128;

    const __half* srcs[NT];
    {
        int nt = 0;
        srcs[nt++] = Ahi + (size_t)row0 * K;
        srcs[nt++] = Bhi + (size_t)col0 * K;
        if (NMMA >= 2) srcs[nt++] = Blo + (size_t)col0 * K;
    }

    float acc[4][4][4];
    #pragma unroll
    for (int mt = 0; mt < 4; ++mt)
        #pragma unroll
        for (int nt = 0; nt < 4; ++nt)
            #pragma unroll
            for (int r = 0; r < 4; ++r) acc[mt][nt][r] = 0.0f;

    auto load_stage = [&](int s, int kc) {
        #pragma unroll
        for (int t = 0; t < NT; ++t) {
            uint32_t dst = sb + (uint32_t)(s * NT + t) * TILE_B;
            const __half* src = srcs[t] + kc;
            #pragma unroll
            for (int i = 0; i < 4; ++i) {
                int c = tid + i * 256;
                int r = c >> 3, ch = c & 7;
                cp16(dst + r * 128 + ((ch ^ (r & 7)) << 4),
                     src + (size_t)r * K + ch * 8);
            }
        }
    };

    const int KT = K / 64;
    load_stage(0, 0);
    cp_commit();

    for (int kt = 0; kt < KT; ++kt) {
        if (kt + 1 < KT) {
            load_stage((kt + 1) & 1, (kt + 1) * 64);
            cp_commit();
            cp_wait<1>();
        } else {
            cp_wait<0>();
        }
        __syncthreads();

        const uint32_t st  = sb + (uint32_t)(kt & 1) * NT * TILE_B;
        const uint32_t sAh = st;
        const uint32_t sBh = st + TILE_B;
        const uint32_t sBl = sBh + TILE_B;

        #pragma unroll
        for (int k16 = 0; k16 < 4; ++k16) {
            const int c0 = k16 * 2;
            const int arow_off = ((g & 1) << 3) + lr;
            const int ach = c0 + (g >> 1);
            const int brow_off = ((g >> 1) << 3) + lr;
            const int bch = c0 + (g & 1);

            uint32_t ah[4][4];
            #pragma unroll
            for (int mt = 0; mt < 4; ++mt) {
                int row = wm * 64 + mt * 16 + arow_off;
                uint32_t off = row * 128 + (((ach ^ (row & 7))) << 4);
                ldm_x4(sAh + off, ah[mt]);
            }
            uint32_t bh[4][2], bl[4][2];
            #pragma unroll
            for (int nn = 0; nn < 2; ++nn) {
                int row = wn * 32 + nn * 16 + brow_off;
                uint32_t off = row * 128 + (((bch ^ (row & 7))) << 4);
                uint32_t t4[4];
                ldm_x4(sBh + off, t4);
                bh[nn*2][0] = t4[0]; bh[nn*2][1] = t4[1];
                bh[nn*2+1][0] = t4[2]; bh[nn*2+1][1] = t4[3];
                if (NMMA >= 2) {
                    ldm_x4(sBl + off, t4);
                    bl[nn*2][0] = t4[0]; bl[nn*2][1] = t4[1];
                    bl[nn*2+1][0] = t4[2]; bl[nn*2+1][1] = t4[3];
                }
            }
            #pragma unroll
            for (int mt = 0; mt < 4; ++mt)
                #pragma unroll
                for (int nt = 0; nt < 4; ++nt) {
                    mma_fp16(acc[mt][nt], ah[mt], bh[nt][0], bh[nt][1]);
                    if (NMMA >= 2)
                        mma_fp16(acc[mt][nt], ah[mt], bl[nt][0], bl[nt][1]);
                }
        }
        __syncthreads();
    }

    const int qr = lane >> 2;
    const int qc = (lane & 3) * 2;
    #pragma unroll
    for (int mt = 0; mt < 4; ++mt) {
        #pragma unroll
        for (int nt = 0; nt < 4; ++nt) {
            int gr = row0 + wm * 64 + mt * 16 + qr;
            int gc = col0 + wn * 32 + nt * 8 + qc;
            float v0 = acc[mt][nt][0], v1 = acc[mt][nt][1];
            float v2 = acc[mt][nt][2], v3 = acc[mt][nt][3];
            if (EPI == 1) {
                float e0 = b1[gc] + b2[gc];
                float e1 = b1[gc + 1] + b2[gc + 1];
                v0 = softplusf(v0 + e0); v1 = softplusf(v1 + e1);
                v2 = softplusf(v2 + e0); v3 = softplusf(v3 + e1);
            }
            *(float2*)&C[(size_t)gr * N + gc]       = make_float2(v0, v1);
            *(float2*)&C[(size_t)(gr + 8) * N + gc] = make_float2(v2, v3);
        }
    }
}

// ---------------- out_proj GEMM: 64x64 tiles, x1, 3-stage, 3 CTAs/SM ----------------
#define OTILE 8192
#define ONT 2
#define OSTAGE (ONT * OTILE)   // 16384
#define OSMEM (3 * OSTAGE)     // 49152

__global__ __launch_bounds__(256, 3)
void gemm_out64(const __half* __restrict__ Ahi, const __half* __restrict__ Bhi,
                float* __restrict__ C, int M, int N, int K)
{
    extern __shared__ char smem[];
    const uint32_t sb = smem_u32(smem);

    const int tid  = threadIdx.x;
    const int wid  = tid >> 5;
    const int lane = tid & 31;
    const int wm   = wid & 1;     // rows wm*32
    const int wn   = wid >> 1;    // cols wn*16
    const int g    = lane >> 3;
    const int lr   = lane & 7;

    const int row0 = blockIdx.y * 64;
    const int col0 = blockIdx.x * 64;

    const __half* sA  = Ahi + (size_t)row0 * K;
    const __half* sBh = Bhi + (size_t)col0 * K;

    float acc[2][2][4];
    #pragma unroll
    for (int mt = 0; mt < 2; ++mt)
        #pragma unroll
        for (int nt = 0; nt < 2; ++nt)
            #pragma unroll
            for (int r = 0; r < 4; ++r) acc[mt][nt][r] = 0.0f;

    auto load_stage = [&](int s, int kc) {
        uint32_t base = sb + (uint32_t)s * OSTAGE;
        const __half* gp[2] = { sA + kc, sBh + kc };
        #pragma unroll
        for (int t = 0; t < 2; ++t) {
            uint32_t dst = base + (uint32_t)t * OTILE;
            const __half* src = gp[t];
            #pragma unroll
            for (int i = 0; i < 2; ++i) {
                int c = tid + i * 256;
                int r = c >> 3, ch = c & 7;
                cp16(dst + r * 128 + ((ch ^ (r & 7)) << 4),
                     src + (size_t)r * K + ch * 8);
            }
        }
    };

    const int KT = K / 64;   // 24
    load_stage(0, 0); cp_commit();
    load_stage(1, 64); cp_commit();

    int st = 0;
    for (int kt = 0; kt < KT; ++kt) {
        if (kt + 1 < KT) cp_wait<1>(); else cp_wait<0>();
        __syncthreads();
        if (kt + 2 < KT) {
            int ns = st + 2; if (ns >= 3) ns -= 3;
            load_stage(ns, (kt + 2) * 64);
            cp_commit();
        }

        const uint32_t base = sb + (uint32_t)st * OSTAGE;
        const uint32_t mA  = base;
        const uint32_t mBh = base + OTILE;

        #pragma unroll
        for (int k16 = 0; k16 < 4; ++k16) {
            const int c0 = k16 * 2;
            const int arow_off = ((g & 1) << 3) + lr;
            const int ach = c0 + (g >> 1);
            const int brow_off = ((g >> 1) << 3) + lr;
            const int bch = c0 + (g & 1);

            uint32_t ah[2][4];
            #pragma unroll
            for (int mt = 0; mt < 2; ++mt) {
                int row = wm * 32 + mt * 16 + arow_off;
                uint32_t off = row * 128 + (((ach ^ (row & 7))) << 4);
                ldm_x4(mA + off, ah[mt]);
            }
            uint32_t bh[2][2];
            {
                int row = wn * 16 + brow_off;
                uint32_t off = row * 128 + (((bch ^ (row & 7))) << 4);
                uint32_t t4[4];
                ldm_x4(mBh + off, t4);
                bh[0][0] = t4[0]; bh[0][1] = t4[1];
                bh[1][0] = t4[2]; bh[1][1] = t4[3];
            }
            #pragma unroll
            for (int mt = 0; mt < 2; ++mt)
                #pragma unroll
                for (int nt = 0; nt < 2; ++nt)
                    mma_fp16(acc[mt][nt], ah[mt], bh[nt][0], bh[nt][1]);
        }
        if (++st == 3) st = 0;
    }

    const int qr = lane >> 2;
    const int qc = (lane & 3) * 2;
    #pragma unroll
    for (int mt = 0; mt < 2; ++mt) {
        #pragma unroll
        for (int nt = 0; nt < 2; ++nt) {
            int gr = row0 + wm * 32 + mt * 16 + qr;
            int gc = col0 + wn * 16 + nt * 8 + qc;
            *(float2*)&C[(size_t)gr * N + gc] =
                make_float2(acc[mt][nt][0], acc[mt][nt][1]);
            *(float2*)&C[(size_t)(gr + 8) * N + gc] =
                make_float2(acc[mt][nt][2], acc[mt][nt][3]);
        }
    }
}

// ---------------- conv: 4 channels x 8 timesteps per thread, sliding window ----------------
__global__ __launch_bounds__(256)
void conv_silu_kernel(const float* __restrict__ xz,
                      const float* __restrict__ cw,
                      const float* __restrict__ cb,
                      float* __restrict__ u,
                      __half* __restrict__ uhi)
{
    const int nc4 = INNER / 4;           // 384
    int gid = blockIdx.x * blockDim.x + threadIdx.x;
    if (gid >= nc4 * (NTOK / CT)) return;
    int c4 = gid % nc4;
    int tb = gid / nc4;
    int c  = c4 * 4;
    int t0 = tb * CT;
    int l0 = t0 & (SEQLEN - 1);

    float4 bias = *(const float4*)(cb + c);
    float4 w0 = *(const float4*)(cw + (c + 0) * D_CONV);
    float4 w1 = *(const float4*)(cw + (c + 1) * D_CONV);
    float4 w2 = *(const float4*)(cw + (c + 2) * D_CONV);
    float4 w3 = *(const float4*)(cw + (c + 3) * D_CONV);
    const float* pw0 = (const float*)&w0;
    const float* pw1 = (const float*)&w1;
    const float* pw2 = (const float*)&w2;
    const float* pw3 = (const float*)&w3;

    const float4 zero = make_float4(0.f, 0.f, 0.f, 0.f);
    auto ldrow = [&](int t) -> float4 {
        return *(const float4*)(xz + (size_t)t * N2 + c);
    };

    float4 x0 = (l0 >= 3) ? ldrow(t0 - 3) : zero;
    float4 x1 = (l0 >= 2) ? ldrow(t0 - 2) : zero;
    float4 x2 = (l0 >= 1) ? ldrow(t0 - 1) : zero;

    #pragma unroll
    for (int j = 0; j < CT; ++j) {
        float4 x3 = ldrow(t0 + j);
        float4 acc = bias;
        acc.x = fmaf(pw0[0], x0.x, acc.x); acc.x = fmaf(pw0[1], x1.x, acc.x);
        acc.x = fmaf(pw0[2], x2.x, acc.x); acc.x = fmaf(pw0[3], x3.x, acc.x);
        acc.y = fmaf(pw1[0], x0.y, acc.y); acc.y = fmaf(pw1[1], x1.y, acc.y);
        acc.y = fmaf(pw1[2], x2.y, acc.y); acc.y = fmaf(pw1[3], x3.y, acc.y);
        acc.z = fmaf(pw2[0], x0.z, acc.z); acc.z = fmaf(pw2[1], x1.z, acc.z);
        acc.z = fmaf(pw2[2], x2.z, acc.z); acc.z = fmaf(pw2[3], x3.z, acc.z);
        acc.w = fmaf(pw3[0], x0.w, acc.w); acc.w = fmaf(pw3[1], x1.w, acc.w);
        acc.w = fmaf(pw3[2], x2.w, acc.w); acc.w = fmaf(pw3[3], x3.w, acc.w);

        float4 v = make_float4(siluf(acc.x), siluf(acc.y), siluf(acc.z), siluf(acc.w));
        size_t base = (size_t)(t0 + j) * INNER + c;
        *(float4*)(u + base) = v;
        store_h4(uhi + base, v);

        x0 = x1; x1 = x2; x2 = x3;
    }
}

// ---------------- scan pass 1 ----------------
__global__ __launch_bounds__(256)
void scan_pass1(const float* __restrict__ dt, const float* __restrict__ u,
                const float* __restrict__ A_log, const float* __restrict__ Bp,
                float* __restrict__ hend, float* __restrict__ sdtb)
{
    int idx = blockIdx.x * blockDim.x + threadIdx.x;
    int d = idx % INNER;
    int c = (idx / INNER) & (NCHUNK - 1);
    int b = idx / (INNER * NCHUNK);

    float a0 = A_log[d * D_STATE];
    bool uni = true;
    float Av[D_STATE], Bv[D_STATE], h[D_STATE];
    #pragma unroll
    for (int n = 0; n < D_STATE; ++n) {
        float al = A_log[d * D_STATE + n];
        uni = uni && (al == a0);
        Av[n] = -__expf(al);
        Bv[n] = Bp[d * D_STATE + n];
        h[n]  = 0.0f;
    }
    float sdt = 0.0f;
    int t0 = b * SEQLEN + c * CHUNK;

    if (uni) {
        const float Av0 = Av[0];
        for (int j = 0; j < CHUNK; ++j) {
            size_t off = (size_t)(t0 + j) * INNER + d;
            float dtv = dt[off];
            float uv  = u[off];
            sdt += dtv;
            float du = dtv * uv;
            float e  = __expf(dtv * Av0);
            #pragma unroll
            for (int n = 0; n < D_STATE; ++n)
                h[n] = fmaf(e, h[n], du * Bv[n]);
        }
    } else {
        for (int j = 0; j < CHUNK; ++j) {
            size_t off = (size_t)(t0 + j) * INNER + d;
            float dtv = dt[off];
            float uv  = u[off];
            sdt += dtv;
            float du = dtv * uv;
            #pragma unroll
            for (int n = 0; n < D_STATE; ++n)
                h[n] = fmaf(__expf(dtv * Av[n]), h[n], du * Bv[n]);
        }
    }
    int bc = b * NCHUNK + c;
    #pragma unroll
    for (int n = 0; n < D_STATE; ++n)
        hend[(size_t)(bc * D_STATE + n) * INNER + d] = h[n];
    sdtb[(size_t)bc * INNER + d] = sdt;
}

// ---------------- scan fixup ----------------
__global__ __launch_bounds__(256)
void scan_fix(const float* __restrict__ A_log,
              const float* __restrict__ hend, const float* __restrict__ sdtb,
              float* __restrict__ h0buf)
{
    int idx = blockIdx.x * blockDim.x + threadIdx.x;
    if (idx >= BATCH * INNER * D_STATE) return;
    int d = idx % INNER;
    int n = (idx / INNER) % D_STATE;
    int b = idx / (INNER * D_STATE);

    float Av = -__expf(A_log[d * D_STATE + n]);
    float h = 0.0f;
    const size_t nd = (size_t)n * INNER + d;
    for (int c = 0; c < NCHUNK; ++c) {
        int bc = b * NCHUNK + c;
        h0buf[(size_t)bc * D_STATE * INNER + nd] = h;
        float s = sdtb[(size_t)bc * INNER + d];
        h = fmaf(__expf(Av * s), h, hend[(size_t)bc * D_STATE * INNER + nd]);
    }
}

// ---------------- scan pass 2 ----------------
__global__ __launch_bounds__(256)
void scan_pass2(const float* __restrict__ dt, const float* __restrict__ u,
                const float* __restrict__ xz,
                const float* __restrict__ A_log, const float* __restrict__ Bp,
                const float* __restrict__ Cp, const float* __restrict__ Dp,
                const float* __restrict__ h0buf,
                __half* __restrict__ yghi)
{
    int idx = blockIdx.x * blockDim.x + threadIdx.x;
    int d = idx % INNER;
    int c = (idx / INNER) & (NCHUNK - 1);
    int b = idx / (INNER * NCHUNK);
    int bc = b * NCHUNK + c;

    float a0 = A_log[d * D_STATE];
    bool uni = true;
    float Av[D_STATE], Bv[D_STATE], Cv[D_STATE], h[D_STATE];
    #pragma unroll
    for (int n = 0; n < D_STATE; ++n) {
        float al = A_log[d * D_STATE + n];
        uni = uni && (al == a0);
        Av[n] = -__expf(al);
        Bv[n] = Bp[d * D_STATE + n];
        Cv[n] = Cp[d * D_STATE + n];
        h[n]  = h0buf[(size_t)(bc * D_STATE + n) * INNER + d];
    }
    float Dv = Dp[d];

    int t0 = b * SEQLEN + c * CHUNK;
    if (uni) {
        const float Av0 = Av[0];
        for (int j = 0; j < CHUNK; ++j) {
            int t = t0 + j;
            size_t off = (size_t)t * INNER + d;
            float dtv = dt[off];
            float uv  = u[off];
            float du  = dtv * uv;
            float e   = __expf(dtv * Av0);
            float y = 0.0f;
            #pragma unroll
            for (int n = 0; n < D_STATE; ++n) {
                h[n] = fmaf(e, h[n], du * Bv[n]);
                y = fmaf(h[n], Cv[n], y);
            }
            float z = xz[(size_t)t * N2 + INNER + d];
            float v = (y + Dv * uv) * siluf(z);
            yghi[off] = __float2half_rn(v);
        }
    } else {
        for (int j = 0; j < CHUNK; ++j) {
            int t = t0 + j;
            size_t off = (size_t)t * INNER + d;
            float dtv = dt[off];
            float uv  = u[off];
            float du  = dtv * uv;
            float y = 0.0f;
            #pragma unroll
            for (int n = 0; n < D_STATE; ++n) {
                h[n] = fmaf(__expf(dtv * Av[n]), h[n], du * Bv[n]);
                y = fmaf(h[n], Cv[n], y);
            }
            float z = xz[(size_t)t * N2 + INNER + d];
            float v = (y + Dv * uv) * siluf(z);
            yghi[off] = __float2half_rn(v);
        }
    }
}

// ---------------- launcher ----------------
extern "C" void kernel_launch(void* const* d_in, const int* in_sizes, int n_in,
                              void* d_out, int out_size)
{
    const float* hidden    = (const float*)d_in[0];
    const float* in_proj_w = (const float*)d_in[1];
    const float* out_proj_w= (const float*)d_in[2];
    const float* dt_proj_w = (const float*)d_in[3];
    const float* dt_proj_b = (const float*)d_in[4];
    const float* conv_w    = (const float*)d_in[5];
    const float* conv_b    = (const float*)d_in[6];
    const float* A_log     = (const float*)d_in[7];
    const float* B_param   = (const float*)d_in[8];
    const float* C_param   = (const float*)d_in[9];
    const float* D_param   = (const float*)d_in[10];
    const float* dt_bias   = (const float*)d_in[11];
    float* out = (float*)d_out;

    float *xz, *u, *dtb, *hend, *h0, *sdt;
    __half *hid_hi, *wi_hi, *wi_lo, *wd_hi, *wo_hi, *u_hi, *yg_hi;
    cudaGetSymbolAddress((void**)&xz,     g_xz);
    cudaGetSymbolAddress((void**)&u,      g_u);
    cudaGetSymbolAddress((void**)&dtb,    g_dt);
    cudaGetSymbolAddress((void**)&hend,   g_hend);
    cudaGetSymbolAddress((void**)&h0,     g_h0);
    cudaGetSymbolAddress((void**)&sdt,    g_sdt);
    cudaGetSymbolAddress((void**)&hid_hi, g_hid_hi);
    cudaGetSymbolAddress((void**)&wi_hi,  g_wi_hi);
    cudaGetSymbolAddress((void**)&wi_lo,  g_wi_lo);
    cudaGetSymbolAddress((void**)&wd_hi,  g_wd_hi);
    cudaGetSymbolAddress((void**)&wo_hi,  g_wo_hi);
    cudaGetSymbolAddress((void**)&u_hi,   g_u_hi);
    cudaGetSymbolAddress((void**)&yg_hi,  g_yg_hi);

    const int SMEM_X2 = 2 * 3 * TILE_B;   // 98304
    const int SMEM_X1 = 2 * 2 * TILE_B;   // 65536
    cudaFuncSetAttribute(gemm_fp16x<0,2>,
                         cudaFuncAttributeMaxDynamicSharedMemorySize, SMEM_X2);
    cudaFuncSetAttribute(gemm_fp16x<0,1>,
                         cudaFuncAttributeMaxDynamicSharedMemorySize, SMEM_X1);
    cudaFuncSetAttribute(gemm_fp16x<1,1>,
                         cudaFuncAttributeMaxDynamicSharedMemorySize, SMEM_X1);
    cudaFuncSetAttribute(gemm_out64,
                         cudaFuncAttributeMaxDynamicSharedMemorySize, OSMEM);

    // 0) fp16 splits
    split_all<<<SPL_TOT4 / 256, 256>>>(hidden, in_proj_w, dt_proj_w, out_proj_w,
                                       hid_hi, wi_hi, wi_lo, wd_hi, wo_hi);

    // 1a) in_proj proj half (x2): cols 0..1535 of xz
    {
        dim3 grid(INNER / 128, NTOK / 128);
        gemm_fp16x<0,2><<<grid, 256, SMEM_X2>>>(hid_hi, wi_hi, wi_lo,
                                                xz, NTOK, N2, D_MODEL,
                                                nullptr, nullptr);
    }
    // 1b) in_proj gate half (x1): cols 1536..3071 of xz
    {
        dim3 grid(INNER / 128, NTOK / 128);
        gemm_fp16x<0,1><<<grid, 256, SMEM_X1>>>(hid_hi,
                                                wi_hi + (size_t)INNER * D_MODEL,
                                                nullptr,
                                                xz + INNER, NTOK, N2, D_MODEL,
                                                nullptr, nullptr);
    }
    // 2) depthwise conv + SiLU -> u (+ fp16 hi)
    conv_silu_kernel<<<(INNER / 4) * (NTOK / CT) / 256, 256>>>(xz, conv_w, conv_b, u, u_hi);
    // 3) dt_proj + softplus (x1)
    {
        dim3 grid(INNER / 128, NTOK / 128);
        gemm_fp16x<1,1><<<grid, 256, SMEM_X1>>>(u_hi, wd_hi, nullptr,
                                                dtb, NTOK, INNER, INNER,
                                                dt_proj_b, dt_bias);
    }
    // 4) chunked selective scan
    {
        int n1 = BATCH * NCHUNK * INNER;
        scan_pass1<<<n1 / 256, 256>>>(dtb, u, A_log, B_param, hend, sdt);
        scan_fix<<<(BATCH * INNER * D_STATE) / 256, 256>>>(A_log, hend, sdt, h0);
        scan_pass2<<<n1 / 256, 256>>>(dtb, u, xz, A_log, B_param, C_param,
                                      D_param, h0, yg_hi);
    }
    // 5) out_proj (x1, 64x64 tiles)
    {
        dim3 grid(D_MODEL / 64, NTOK / 64);
        gemm_out64<<<grid, 256, OSMEM>>>(yg_hi, wo_hi, out, NTOK, D_MODEL, INNER);
    }
}

// round 12
// speedup vs baseline: 5.4994x; 1.0656x over previous
#include <cuda_runtime.h>
#include <cuda_fp16.h>
#include <math.h>
#include <stdint.h>

// ---------------- problem constants ----------------
#define D_MODEL 768
#define D_STATE 16
#define D_CONV  4
#define INNER   1536
#define N2      (2*INNER)     // 3072
#define BATCH   2
#define SEQLEN  2048
#define NTOK    (BATCH*SEQLEN)  // 4096
#define NCHUNK  64
#define CHUNK   (SEQLEN/NCHUNK) // 32
#define CT      8               // conv timesteps per thread

// ---------------- scratch (static device globals; no allocation) ----------------
__device__ float g_xz  [NTOK * N2];
__device__ float g_hend[BATCH*NCHUNK*D_STATE*INNER];   // general fallback
__device__ float g_h0  [BATCH*NCHUNK*D_STATE*INNER];   // general fallback
__device__ float g_hend_s[BATCH*NCHUNK*INNER];         // scalar fast path
__device__ float g_h0_s  [BATCH*NCHUNK*INNER];         // scalar fast path
__device__ float g_sdt [BATCH*NCHUNK*INNER];

// fp16 tensors
__device__ __half g_hid_hi[NTOK * D_MODEL];
__device__ __half g_wi_hi [N2 * D_MODEL];
__device__ __half g_wi_lo [N2 * D_MODEL];
__device__ __half g_wd_hi [INNER * INNER];
__device__ __half g_wo_hi [D_MODEL * INNER];
__device__ __half g_u_hi  [NTOK * INNER];
__device__ __half g_dt_h  [NTOK * INNER];
__device__ __half g_yg_hi [NTOK * INNER];

// ---------------- helpers ----------------
__device__ __forceinline__ float siluf(float x) {
    return x * (1.0f / (1.0f + __expf(-x)));
}
__device__ __forceinline__ float softplusf(float x) {
    return fmaxf(x, 0.0f) + log1pf(__expf(-fabsf(x)));
}
__device__ __forceinline__ uint32_t smem_u32(const void* p) {
    uint32_t a;
    asm("{ .reg .u64 t; cvta.to.shared.u64 t, %1; cvt.u32.u64 %0, t; }"
        : "=r"(a) : "l"(p));
    return a;
}
__device__ __forceinline__ void cp16(uint32_t s, const void* g) {
    asm volatile("cp.async.cg.shared.global [%0], [%1], 16;\n" :: "r"(s), "l"(g));
}
__device__ __forceinline__ void cp_commit() {
    asm volatile("cp.async.commit_group;\n");
}
template<int N> __device__ __forceinline__ void cp_wait() {
    asm volatile("cp.async.wait_group %0;\n" :: "n"(N));
}
__device__ __forceinline__ void ldm_x4(uint32_t a, uint32_t* r) {
    asm volatile("ldmatrix.sync.aligned.m8n8.x4.shared.b16 {%0,%1,%2,%3}, [%4];"
                 : "=r"(r[0]), "=r"(r[1]), "=r"(r[2]), "=r"(r[3]) : "r"(a));
}
__device__ __forceinline__ void mma_fp16(float* d, const uint32_t* a,
                                         uint32_t b0, uint32_t b1) {
    asm volatile(
        "mma.sync.aligned.m16n8k16.row.col.f32.f16.f16.f32 "
        "{%0,%1,%2,%3}, {%4,%5,%6,%7}, {%8,%9}, {%0,%1,%2,%3};\n"
        : "+f"(d[0]), "+f"(d[1]), "+f"(d[2]), "+f"(d[3])
        : "r"(a[0]), "r"(a[1]), "r"(a[2]), "r"(a[3]), "r"(b0), "r"(b1));
}
__device__ __forceinline__ void store_h4(__half* p, float4 v) {
    __half2 a = __floats2half2_rn(v.x, v.y);
    __half2 b = __floats2half2_rn(v.z, v.w);
    uint2 o;
    o.x = *(uint32_t*)&a;
    o.y = *(uint32_t*)&b;
    *(uint2*)p = o;
}

// ---------------- merged split kernel ----------------
#define SPL_N0 (NTOK*D_MODEL)
#define SPL_N1 (N2*D_MODEL)
#define SPL_N2 (INNER*INNER)
#define SPL_N3 (D_MODEL*INNER)
#define SPL_TOT4 ((SPL_N0+SPL_N1+SPL_N2+SPL_N3)/4)

__device__ __forceinline__ void cvt4_hi(const float* s, __half* h) {
    float4 v = *(const float4*)s;
    store_h4(h, v);
}
__device__ __forceinline__ void cvt4_hilo(const float* s, __half* h, __half* l) {
    float4 v = *(const float4*)s;
    __half2 a = __floats2half2_rn(v.x, v.y);
    __half2 b = __floats2half2_rn(v.z, v.w);
    uint2 o; o.x = *(uint32_t*)&a; o.y = *(uint32_t*)&b;
    *(uint2*)h = o;
    float2 fa = __half22float2(a), fb = __half22float2(b);
    float4 r = make_float4(v.x - fa.x, v.y - fa.y, v.z - fb.x, v.w - fb.y);
    store_h4(l, r);
}

__global__ __launch_bounds__(256)
void split_all(const float* __restrict__ hidden, const float* __restrict__ wi,
               const float* __restrict__ wd, const float* __restrict__ wo,
               __half* __restrict__ hid_hi,
               __half* __restrict__ wi_hi, __half* __restrict__ wi_lo,
               __half* __restrict__ wd_hi,
               __half* __restrict__ wo_hi)
{
    int idx = (blockIdx.x * blockDim.x + threadIdx.x) * 4;
    if (idx < SPL_N0) {
        cvt4_hi(hidden + idx, hid_hi + idx);
    } else if ((idx -= SPL_N0) < SPL_N1) {
        cvt4_hilo(wi + idx, wi_hi + idx, wi_lo + idx);
    } else if ((idx -= SPL_N1) < SPL_N2) {
        cvt4_hi(wd + idx, wd_hi + idx);
    } else if ((idx -= SPL_N2) < SPL_N3) {
        cvt4_hi(wo + idx, wo_hi + idx);
    }
}

// ---------------- fp16xN NT GEMM (128x128 tiles) ----------------
// EPI: 0 plain fp32 store, 1 softplus(x+b1+b2) -> fp16 store
#define TILE_B 16384

template<int EPI, int NMMA>
__global__ __launch_bounds__(256)
void gemm_fp16x(const __half* __restrict__ Ahi, const __half* __restrict__ Bhi,
                const __half* __restrict__ Blo,
                void* __restrict__ Cv, int M, int N, int K,
                const float* __restrict__ b1, const float* __restrict__ b2)
{
    constexpr int NT = (NMMA == 2) ? 3 : 2;
    extern __shared__ char smem[];
    const uint32_t sb = smem_u32(smem);

    const int tid  = threadIdx.x;
    const int wid  = tid >> 5;
    const int lane = tid & 31;
    const int wm   = wid & 1;
    const int wn   = wid >> 1;
    const int g    = lane >> 3;
    const int lr   = lane & 7;

    const int row0 = blockIdx.y * 128;
    const int col0 = blockIdx.x * 128;

    const __half* srcs[NT];
    {
        int nt = 0;
        srcs[nt++] = Ahi + (size_t)row0 * K;
        srcs[nt++] = Bhi + (size_t)col0 * K;
        if (NMMA >= 2) srcs[nt++] = Blo + (size_t)col0 * K;
    }

    float acc[4][4][4];
    #pragma unroll
    for (int mt = 0; mt < 4; ++mt)
        #pragma unroll
        for (int nt = 0; nt < 4; ++nt)
            #pragma unroll
            for (int r = 0; r < 4; ++r) acc[mt][nt][r] = 0.0f;

    auto load_stage = [&](int s, int kc) {
        #pragma unroll
        for (int t = 0; t < NT; ++t) {
            uint32_t dst = sb + (uint32_t)(s * NT + t) * TILE_B;
            const __half* src = srcs[t] + kc;
            #pragma unroll
            for (int i = 0; i < 4; ++i) {
                int c = tid + i * 256;
                int r = c >> 3, ch = c & 7;
                cp16(dst + r * 128 + ((ch ^ (r & 7)) << 4),
                     src + (size_t)r * K + ch * 8);
            }
        }
    };

    const int KT = K / 64;
    load_stage(0, 0);
    cp_commit();

    for (int kt = 0; kt < KT; ++kt) {
        if (kt + 1 < KT) {
            load_stage((kt + 1) & 1, (kt + 1) * 64);
            cp_commit();
            cp_wait<1>();
        } else {
            cp_wait<0>();
        }
        __syncthreads();

        const uint32_t st  = sb + (uint32_t)(kt & 1) * NT * TILE_B;
        const uint32_t sAh = st;
        const uint32_t sBh = st + TILE_B;
        const uint32_t sBl = sBh + TILE_B;

        #pragma unroll
        for (int k16 = 0; k16 < 4; ++k16) {
            const int c0 = k16 * 2;
            const int arow_off = ((g & 1) << 3) + lr;
            const int ach = c0 + (g >> 1);
            const int brow_off = ((g >> 1) << 3) + lr;
            const int bch = c0 + (g & 1);

            uint32_t ah[4][4];
            #pragma unroll
            for (int mt = 0; mt < 4; ++mt) {
                int row = wm * 64 + mt * 16 + arow_off;
                uint32_t off = row * 128 + (((ach ^ (row & 7))) << 4);
                ldm_x4(sAh + off, ah[mt]);
            }
            uint32_t bh[4][2], bl[4][2];
            #pragma unroll
            for (int nn = 0; nn < 2; ++nn) {
                int row = wn * 32 + nn * 16 + brow_off;
                uint32_t off = row * 128 + (((bch ^ (row & 7))) << 4);
                uint32_t t4[4];
                ldm_x4(sBh + off, t4);
                bh[nn*2][0] = t4[0]; bh[nn*2][1] = t4[1];
                bh[nn*2+1][0] = t4[2]; bh[nn*2+1][1] = t4[3];
                if (NMMA >= 2) {
                    ldm_x4(sBl + off, t4);
                    bl[nn*2][0] = t4[0]; bl[nn*2][1] = t4[1];
                    bl[nn*2+1][0] = t4[2]; bl[nn*2+1][1] = t4[3];
                }
            }
            #pragma unroll
            for (int mt = 0; mt < 4; ++mt)
                #pragma unroll
                for (int nt = 0; nt < 4; ++nt) {
                    mma_fp16(acc[mt][nt], ah[mt], bh[nt][0], bh[nt][1]);
                    if (NMMA >= 2)
                        mma_fp16(acc[mt][nt], ah[mt], bl[nt][0], bl[nt][1]);
                }
        }
        __syncthreads();
    }

    const int qr = lane >> 2;
    const int qc = (lane & 3) * 2;
    #pragma unroll
    for (int mt = 0; mt < 4; ++mt) {
        #pragma unroll
        for (int nt = 0; nt < 4; ++nt) {
            int gr = row0 + wm * 64 + mt * 16 + qr;
            int gc = col0 + wn * 32 + nt * 8 + qc;
            float v0 = acc[mt][nt][0], v1 = acc[mt][nt][1];
            float v2 = acc[mt][nt][2], v3 = acc[mt][nt][3];
            if (EPI == 1) {
                __half* Ch = (__half*)Cv;
                float e0 = b1[gc] + b2[gc];
                float e1 = b1[gc + 1] + b2[gc + 1];
                *(__half2*)&Ch[(size_t)gr * N + gc] =
                    __floats2half2_rn(softplusf(v0 + e0), softplusf(v1 + e1));
                *(__half2*)&Ch[(size_t)(gr + 8) * N + gc] =
                    __floats2half2_rn(softplusf(v2 + e0), softplusf(v3 + e1));
            } else {
                float* C = (float*)Cv;
                *(float2*)&C[(size_t)gr * N + gc]       = make_float2(v0, v1);
                *(float2*)&C[(size_t)(gr + 8) * N + gc] = make_float2(v2, v3);
            }
        }
    }
}

// ---------------- out_proj GEMM: 64x64 tiles, x1, 3-stage, 3 CTAs/SM ----------------
#define OTILE 8192
#define ONT 2
#define OSTAGE (ONT * OTILE)
#define OSMEM (3 * OSTAGE)     // 49152

__global__ __launch_bounds__(256, 3)
void gemm_out64(const __half* __restrict__ Ahi, const __half* __restrict__ Bhi,
                float* __restrict__ C, int M, int N, int K)
{
    extern __shared__ char smem[];
    const uint32_t sb = smem_u32(smem);

    const int tid  = threadIdx.x;
    const int wid  = tid >> 5;
    const int lane = tid & 31;
    const int wm   = wid & 1;
    const int wn   = wid >> 1;
    const int g    = lane >> 3;
    const int lr   = lane & 7;

    const int row0 = blockIdx.y * 64;
    const int col0 = blockIdx.x * 64;

    const __half* sA  = Ahi + (size_t)row0 * K;
    const __half* sBh = Bhi + (size_t)col0 * K;

    float acc[2][2][4];
    #pragma unroll
    for (int mt = 0; mt < 2; ++mt)
        #pragma unroll
        for (int nt = 0; nt < 2; ++nt)
            #pragma unroll
            for (int r = 0; r < 4; ++r) acc[mt][nt][r] = 0.0f;

    auto load_stage = [&](int s, int kc) {
        uint32_t base = sb + (uint32_t)s * OSTAGE;
        const __half* gp[2] = { sA + kc, sBh + kc };
        #pragma unroll
        for (int t = 0; t < 2; ++t) {
            uint32_t dst = base + (uint32_t)t * OTILE;
            const __half* src = gp[t];
            #pragma unroll
            for (int i = 0; i < 2; ++i) {
                int c = tid + i * 256;
                int r = c >> 3, ch = c & 7;
                cp16(dst + r * 128 + ((ch ^ (r & 7)) << 4),
                     src + (size_t)r * K + ch * 8);
            }
        }
    };

    const int KT = K / 64;   // 24
    load_stage(0, 0); cp_commit();
    load_stage(1, 64); cp_commit();

    int st = 0;
    for (int kt = 0; kt < KT; ++kt) {
        if (kt + 1 < KT) cp_wait<1>(); else cp_wait<0>();
        __syncthreads();
        if (kt + 2 < KT) {
            int ns = st + 2; if (ns >= 3) ns -= 3;
            load_stage(ns, (kt + 2) * 64);
            cp_commit();
        }

        const uint32_t base = sb + (uint32_t)st * OSTAGE;
        const uint32_t mA  = base;
        const uint32_t mBh = base + OTILE;

        #pragma unroll
        for (int k16 = 0; k16 < 4; ++k16) {
            const int c0 = k16 * 2;
            const int arow_off = ((g & 1) << 3) + lr;
            const int ach = c0 + (g >> 1);
            const int brow_off = ((g >> 1) << 3) + lr;
            const int bch = c0 + (g & 1);

            uint32_t ah[2][4];
            #pragma unroll
            for (int mt = 0; mt < 2; ++mt) {
                int row = wm * 32 + mt * 16 + arow_off;
                uint32_t off = row * 128 + (((ach ^ (row & 7))) << 4);
                ldm_x4(mA + off, ah[mt]);
            }
            uint32_t bh[2][2];
            {
                int row = wn * 16 + brow_off;
                uint32_t off = row * 128 + (((bch ^ (row & 7))) << 4);
                uint32_t t4[4];
                ldm_x4(mBh + off, t4);
                bh[0][0] = t4[0]; bh[0][1] = t4[1];
                bh[1][0] = t4[2]; bh[1][1] = t4[3];
            }
            #pragma unroll
            for (int mt = 0; mt < 2; ++mt)
                #pragma unroll
                for (int nt = 0; nt < 2; ++nt)
                    mma_fp16(acc[mt][nt], ah[mt], bh[nt][0], bh[nt][1]);
        }
        if (++st == 3) st = 0;
    }

    const int qr = lane >> 2;
    const int qc = (lane & 3) * 2;
    #pragma unroll
    for (int mt = 0; mt < 2; ++mt) {
        #pragma unroll
        for (int nt = 0; nt < 2; ++nt) {
            int gr = row0 + wm * 32 + mt * 16 + qr;
            int gc = col0 + wn * 16 + nt * 8 + qc;
            *(float2*)&C[(size_t)gr * N + gc] =
                make_float2(acc[mt][nt][0], acc[mt][nt][1]);
            *(float2*)&C[(size_t)(gr + 8) * N + gc] =
                make_float2(acc[mt][nt][2], acc[mt][nt][3]);
        }
    }
}

// ---------------- conv: 4 channels x 8 timesteps, sliding window, fp16 out ----------------
__global__ __launch_bounds__(256)
void conv_silu_kernel(const float* __restrict__ xz,
                      const float* __restrict__ cw,
                      const float* __restrict__ cb,
                      __half* __restrict__ uhi)
{
    const int nc4 = INNER / 4;
    int gid = blockIdx.x * blockDim.x + threadIdx.x;
    if (gid >= nc4 * (NTOK / CT)) return;
    int c4 = gid % nc4;
    int tb = gid / nc4;
    int c  = c4 * 4;
    int t0 = tb * CT;
    int l0 = t0 & (SEQLEN - 1);

    float4 bias = *(const float4*)(cb + c);
    float4 w0 = *(const float4*)(cw + (c + 0) * D_CONV);
    float4 w1 = *(const float4*)(cw + (c + 1) * D_CONV);
    float4 w2 = *(const float4*)(cw + (c + 2) * D_CONV);
    float4 w3 = *(const float4*)(cw + (c + 3) * D_CONV);
    const float* pw0 = (const float*)&w0;
    const float* pw1 = (const float*)&w1;
    const float* pw2 = (const float*)&w2;
    const float* pw3 = (const float*)&w3;

    const float4 zero = make_float4(0.f, 0.f, 0.f, 0.f);
    auto ldrow = [&](int t) -> float4 {
        return *(const float4*)(xz + (size_t)t * N2 + c);
    };

    float4 x0 = (l0 >= 3) ? ldrow(t0 - 3) : zero;
    float4 x1 = (l0 >= 2) ? ldrow(t0 - 2) : zero;
    float4 x2 = (l0 >= 1) ? ldrow(t0 - 1) : zero;

    #pragma unroll
    for (int j = 0; j < CT; ++j) {
        float4 x3 = ldrow(t0 + j);
        float4 acc = bias;
        acc.x = fmaf(pw0[0], x0.x, acc.x); acc.x = fmaf(pw0[1], x1.x, acc.x);
        acc.x = fmaf(pw0[2], x2.x, acc.x); acc.x = fmaf(pw0[3], x3.x, acc.x);
        acc.y = fmaf(pw1[0], x0.y, acc.y); acc.y = fmaf(pw1[1], x1.y, acc.y);
        acc.y = fmaf(pw1[2], x2.y, acc.y); acc.y = fmaf(pw1[3], x3.y, acc.y);
        acc.z = fmaf(pw2[0], x0.z, acc.z); acc.z = fmaf(pw2[1], x1.z, acc.z);
        acc.z = fmaf(pw2[2], x2.z, acc.z); acc.z = fmaf(pw2[3], x3.z, acc.z);
        acc.w = fmaf(pw3[0], x0.w, acc.w); acc.w = fmaf(pw3[1], x1.w, acc.w);
        acc.w = fmaf(pw3[2], x2.w, acc.w); acc.w = fmaf(pw3[3], x3.w, acc.w);

        float4 v = make_float4(siluf(acc.x), siluf(acc.y), siluf(acc.z), siluf(acc.w));
        store_h4(uhi + (size_t)(t0 + j) * INNER + c, v);

        x0 = x1; x1 = x2; x2 = x3;
    }
}

// ---------------- scan pass 1 (scalar fast path for uniform A) ----------------
__global__ __launch_bounds__(256)
void scan_pass1(const __half* __restrict__ dt, const __half* __restrict__ u,
                const float* __restrict__ A_log, const float* __restrict__ Bp,
                float* __restrict__ hend, float* __restrict__ hend_s,
                float* __restrict__ sdtb)
{
    int idx = blockIdx.x * blockDim.x + threadIdx.x;
    int d = idx % INNER;
    int c = (idx / INNER) & (NCHUNK - 1);
    int b = idx / (INNER * NCHUNK);
    int bc = b * NCHUNK + c;
    int t0 = b * SEQLEN + c * CHUNK;

    float a0 = A_log[d * D_STATE];
    bool uni = true;
    #pragma unroll
    for (int n = 1; n < D_STATE; ++n)
        uni = uni && (A_log[d * D_STATE + n] == a0);

    float sdt = 0.0f;
    if (uni) {
        const float Av0 = -__expf(a0);
        float w = 0.0f;
        for (int j = 0; j < CHUNK; ++j) {
            size_t off = (size_t)(t0 + j) * INNER + d;
            float dtv = __half2float(dt[off]);
            float uv  = __half2float(u[off]);
            sdt += dtv;
            w = fmaf(__expf(dtv * Av0), w, dtv * uv);
        }
        hend_s[(size_t)bc * INNER + d] = w;
    } else {
        float Av[D_STATE], Bv[D_STATE], h[D_STATE];
        #pragma unroll
        for (int n = 0; n < D_STATE; ++n) {
            Av[n] = -__expf(A_log[d * D_STATE + n]);
            Bv[n] = Bp[d * D_STATE + n];
            h[n]  = 0.0f;
        }
        for (int j = 0; j < CHUNK; ++j) {
            size_t off = (size_t)(t0 + j) * INNER + d;
            float dtv = __half2float(dt[off]);
            float uv  = __half2float(u[off]);
            sdt += dtv;
            float du = dtv * uv;
            #pragma unroll
            for (int n = 0; n < D_STATE; ++n)
                h[n] = fmaf(__expf(dtv * Av[n]), h[n], du * Bv[n]);
        }
        #pragma unroll
        for (int n = 0; n < D_STATE; ++n)
            hend[(size_t)(bc * D_STATE + n) * INNER + d] = h[n];
    }
    sdtb[(size_t)bc * INNER + d] = sdt;
}

// ---------------- scan fixup ----------------
__global__ __launch_bounds__(256)
void scan_fix(const float* __restrict__ A_log,
              const float* __restrict__ hend, const float* __restrict__ hend_s,
              const float* __restrict__ sdtb,
              float* __restrict__ h0buf, float* __restrict__ h0_s)
{
    int idx = blockIdx.x * blockDim.x + threadIdx.x;
    if (idx >= BATCH * INNER * D_STATE) return;
    int d = idx % INNER;
    int n = (idx / INNER) % D_STATE;
    int b = idx / (INNER * D_STATE);

    float a0 = A_log[d * D_STATE];
    bool uni = true;
    #pragma unroll
    for (int k = 1; k < D_STATE; ++k)
        uni = uni && (A_log[d * D_STATE + k] == a0);

    if (uni) {
        if (n != 0) return;
        float Av = -__expf(a0);
        float w = 0.0f;
        for (int c = 0; c < NCHUNK; ++c) {
            int bc = b * NCHUNK + c;
            h0_s[(size_t)bc * INNER + d] = w;
            float s = sdtb[(size_t)bc * INNER + d];
            w = fmaf(__expf(Av * s), w, hend_s[(size_t)bc * INNER + d]);
        }
    } else {
        float Av = -__expf(A_log[d * D_STATE + n]);
        float h = 0.0f;
        const size_t nd = (size_t)n * INNER + d;
        for (int c = 0; c < NCHUNK; ++c) {
            int bc = b * NCHUNK + c;
            h0buf[(size_t)bc * D_STATE * INNER + nd] = h;
            float s = sdtb[(size_t)bc * INNER + d];
            h = fmaf(__expf(Av * s), h, hend[(size_t)bc * D_STATE * INNER + nd]);
        }
    }
}

// ---------------- scan pass 2 (scalar fast path) ----------------
__global__ __launch_bounds__(256)
void scan_pass2(const __half* __restrict__ dt, const __half* __restrict__ u,
                const float* __restrict__ xz,
                const float* __restrict__ A_log, const float* __restrict__ Bp,
                const float* __restrict__ Cp, const float* __restrict__ Dp,
                const float* __restrict__ h0buf, const float* __restrict__ h0_s,
                __half* __restrict__ yghi)
{
    int idx = blockIdx.x * blockDim.x + threadIdx.x;
    int d = idx % INNER;
    int c = (idx / INNER) & (NCHUNK - 1);
    int b = idx / (INNER * NCHUNK);
    int bc = b * NCHUNK + c;
    int t0 = b * SEQLEN + c * CHUNK;
    float Dv = Dp[d];

    float a0 = A_log[d * D_STATE];
    bool uni = true;
    #pragma unroll
    for (int n = 1; n < D_STATE; ++n)
        uni = uni && (A_log[d * D_STATE + n] == a0);

    if (uni) {
        const float Av0 = -__expf(a0);
        float bcsum = 0.0f;
        #pragma unroll
        for (int n = 0; n < D_STATE; ++n)
            bcsum = fmaf(Bp[d * D_STATE + n], Cp[d * D_STATE + n], bcsum);
        float w = h0_s[(size_t)bc * INNER + d];
        for (int j = 0; j < CHUNK; ++j) {
            int t = t0 + j;
            size_t off = (size_t)t * INNER + d;
            float dtv = __half2float(dt[off]);
            float uv  = __half2float(u[off]);
            w = fmaf(__expf(dtv * Av0), w, dtv * uv);
            float z = xz[(size_t)t * N2 + INNER + d];
            float v = fmaf(bcsum, w, Dv * uv) * siluf(z);
            yghi[off] = __float2half_rn(v);
        }
    } else {
        float Av[D_STATE], Bv[D_STATE], Cv[D_STATE], h[D_STATE];
        #pragma unroll
        for (int n = 0; n < D_STATE; ++n) {
            Av[n] = -__expf(A_log[d * D_STATE + n]);
            Bv[n] = Bp[d * D_STATE + n];
            Cv[n] = Cp[d * D_STATE + n];
            h[n]  = h0buf[(size_t)(bc * D_STATE + n) * INNER + d];
        }
        for (int j = 0; j < CHUNK; ++j) {
            int t = t0 + j;
            size_t off = (size_t)t * INNER + d;
            float dtv = __half2float(dt[off]);
            float uv  = __half2float(u[off]);
            float du  = dtv * uv;
            float y = 0.0f;
            #pragma unroll
            for (int n = 0; n < D_STATE; ++n) {
                h[n] = fmaf(__expf(dtv * Av[n]), h[n], du * Bv[n]);
                y = fmaf(h[n], Cv[n], y);
            }
            float z = xz[(size_t)t * N2 + INNER + d];
            float v = (y + Dv * uv) * siluf(z);
            yghi[off] = __float2half_rn(v);
        }
    }
}

// ---------------- launcher ----------------
extern "C" void kernel_launch(void* const* d_in, const int* in_sizes, int n_in,
                              void* d_out, int out_size)
{
    const float* hidden    = (const float*)d_in[0];
    const float* in_proj_w = (const float*)d_in[1];
    const float* out_proj_w= (const float*)d_in[2];
    const float* dt_proj_w = (const float*)d_in[3];
    const float* dt_proj_b = (const float*)d_in[4];
    const float* conv_w    = (const float*)d_in[5];
    const float* conv_b    = (const float*)d_in[6];
    const float* A_log     = (const float*)d_in[7];
    const float* B_param   = (const float*)d_in[8];
    const float* C_param   = (const float*)d_in[9];
    const float* D_param   = (const float*)d_in[10];
    const float* dt_bias   = (const float*)d_in[11];
    float* out = (float*)d_out;

    float *xz, *hend, *h0, *hend_s, *h0_s, *sdt;
    __half *hid_hi, *wi_hi, *wi_lo, *wd_hi, *wo_hi, *u_hi, *dt_h, *yg_hi;
    cudaGetSymbolAddress((void**)&xz,     g_xz);
    cudaGetSymbolAddress((void**)&hend,   g_hend);
    cudaGetSymbolAddress((void**)&h0,     g_h0);
    cudaGetSymbolAddress((void**)&hend_s, g_hend_s);
    cudaGetSymbolAddress((void**)&h0_s,   g_h0_s);
    cudaGetSymbolAddress((void**)&sdt,    g_sdt);
    cudaGetSymbolAddress((void**)&hid_hi, g_hid_hi);
    cudaGetSymbolAddress((void**)&wi_hi,  g_wi_hi);
    cudaGetSymbolAddress((void**)&wi_lo,  g_wi_lo);
    cudaGetSymbolAddress((void**)&wd_hi,  g_wd_hi);
    cudaGetSymbolAddress((void**)&wo_hi,  g_wo_hi);
    cudaGetSymbolAddress((void**)&u_hi,   g_u_hi);
    cudaGetSymbolAddress((void**)&dt_h,   g_dt_h);
    cudaGetSymbolAddress((void**)&yg_hi,  g_yg_hi);

    const int SMEM_X2 = 2 * 3 * TILE_B;   // 98304
    const int SMEM_X1 = 2 * 2 * TILE_B;   // 65536
    cudaFuncSetAttribute(gemm_fp16x<0,2>,
                         cudaFuncAttributeMaxDynamicSharedMemorySize, SMEM_X2);
    cudaFuncSetAttribute(gemm_fp16x<0,1>,
                         cudaFuncAttributeMaxDynamicSharedMemorySize, SMEM_X1);
    cudaFuncSetAttribute(gemm_fp16x<1,1>,
                         cudaFuncAttributeMaxDynamicSharedMemorySize, SMEM_X1);
    cudaFuncSetAttribute(gemm_out64,
                         cudaFuncAttributeMaxDynamicSharedMemorySize, OSMEM);

    // 0) fp16 splits
    split_all<<<SPL_TOT4 / 256, 256>>>(hidden, in_proj_w, dt_proj_w, out_proj_w,
                                       hid_hi, wi_hi, wi_lo, wd_hi, wo_hi);

    // 1a) in_proj proj half (x2)
    {
        dim3 grid(INNER / 128, NTOK / 128);
        gemm_fp16x<0,2><<<grid, 256, SMEM_X2>>>(hid_hi, wi_hi, wi_lo,
                                                xz, NTOK, N2, D_MODEL,
                                                nullptr, nullptr);
    }
    // 1b) in_proj gate half (x1)
    {
        dim3 grid(INNER / 128, NTOK / 128);
        gemm_fp16x<0,1><<<grid, 256, SMEM_X1>>>(hid_hi,
                                                wi_hi + (size_t)INNER * D_MODEL,
                                                nullptr,
                                                xz + INNER, NTOK, N2, D_MODEL,
                                                nullptr, nullptr);
    }
    // 2) depthwise conv + SiLU -> u_hi (fp16)
    conv_silu_kernel<<<(INNER / 4) * (NTOK / CT) / 256, 256>>>(xz, conv_w, conv_b, u_hi);
    // 3) dt_proj + softplus (x1) -> fp16
    {
        dim3 grid(INNER / 128, NTOK / 128);
        gemm_fp16x<1,1><<<grid, 256, SMEM_X1>>>(u_hi, wd_hi, nullptr,
                                                dt_h, NTOK, INNER, INNER,
                                                dt_proj_b, dt_bias);
    }
    // 4) chunked selective scan (scalar fast path; exact for uniform A)
    {
        int n1 = BATCH * NCHUNK * INNER;
        scan_pass1<<<n1 / 256, 256>>>(dt_h, u_hi, A_log, B_param,
                                      hend, hend_s, sdt);
        scan_fix<<<(BATCH * INNER * D_STATE) / 256, 256>>>(A_log, hend, hend_s,
                                                           sdt, h0, h0_s);
        scan_pass2<<<n1 / 256, 256>>>(dt_h, u_hi, xz, A_log, B_param, C_param,
                                      D_param, h0, h0_s, yg_hi);
    }
    // 5) out_proj (x1, 64x64 tiles)
    {
        dim3 grid(D_MODEL / 64, NTOK / 64);
        gemm_out64<<<grid, 256, OSMEM>>>(yg_hi, wo_hi, out, NTOK, D_MODEL, INNER);
    }
}

// round 13
// speedup vs baseline: 6.5817x; 1.1968x over previous
#include <cuda_runtime.h>
#include <cuda_fp16.h>
#include <math.h>
#include <stdint.h>

// ---------------- problem constants ----------------
#define D_MODEL 768
#define D_STATE 16
#define D_CONV  4
#define INNER   1536
#define N2      (2*INNER)     // 3072
#define BATCH   2
#define SEQLEN  2048
#define NTOK    (BATCH*SEQLEN)  // 4096
#define NCHUNK  64
#define CHUNK   (SEQLEN/NCHUNK) // 32
#define CT      8               // conv timesteps per thread

// ---------------- scratch (static device globals; no allocation) ----------------
__device__ float g_xp  [NTOK * INNER];                 // in_proj proj half (fp32, conv input)
__device__ float g_hend[BATCH*NCHUNK*D_STATE*INNER];   // general fallback
__device__ float g_h0  [BATCH*NCHUNK*D_STATE*INNER];   // general fallback
__device__ float g_hend_s[BATCH*NCHUNK*INNER];         // scalar fast path
__device__ float g_h0_s  [BATCH*NCHUNK*INNER];         // scalar fast path
__device__ float g_sdt [BATCH*NCHUNK*INNER];

// fp16 tensors
__device__ __half g_z_h   [NTOK * INNER];              // in_proj gate half (fp16)
__device__ __half g_hid_hi[NTOK * D_MODEL];
__device__ __half g_wi_hi [N2 * D_MODEL];
__device__ __half g_wd_hi [INNER * INNER];
__device__ __half g_wo_hi [D_MODEL * INNER];
__device__ __half g_u_hi  [NTOK * INNER];
__device__ __half g_dt_h  [NTOK * INNER];
__device__ __half g_yg_hi [NTOK * INNER];

// ---------------- helpers ----------------
__device__ __forceinline__ float siluf(float x) {
    return x * (1.0f / (1.0f + __expf(-x)));
}
__device__ __forceinline__ float softplusf(float x) {
    return fmaxf(x, 0.0f) + log1pf(__expf(-fabsf(x)));
}
__device__ __forceinline__ uint32_t smem_u32(const void* p) {
    uint32_t a;
    asm("{ .reg .u64 t; cvta.to.shared.u64 t, %1; cvt.u32.u64 %0, t; }"
        : "=r"(a) : "l"(p));
    return a;
}
__device__ __forceinline__ void cp16(uint32_t s, const void* g) {
    asm volatile("cp.async.cg.shared.global [%0], [%1], 16;\n" :: "r"(s), "l"(g));
}
__device__ __forceinline__ void cp_commit() {
    asm volatile("cp.async.commit_group;\n");
}
template<int N> __device__ __forceinline__ void cp_wait() {
    asm volatile("cp.async.wait_group %0;\n" :: "n"(N));
}
__device__ __forceinline__ void ldm_x4(uint32_t a, uint32_t* r) {
    asm volatile("ldmatrix.sync.aligned.m8n8.x4.shared.b16 {%0,%1,%2,%3}, [%4];"
                 : "=r"(r[0]), "=r"(r[1]), "=r"(r[2]), "=r"(r[3]) : "r"(a));
}
__device__ __forceinline__ void mma_fp16(float* d, const uint32_t* a,
                                         uint32_t b0, uint32_t b1) {
    asm volatile(
        "mma.sync.aligned.m16n8k16.row.col.f32.f16.f16.f32 "
        "{%0,%1,%2,%3}, {%4,%5,%6,%7}, {%8,%9}, {%0,%1,%2,%3};\n"
        : "+f"(d[0]), "+f"(d[1]), "+f"(d[2]), "+f"(d[3])
        : "r"(a[0]), "r"(a[1]), "r"(a[2]), "r"(a[3]), "r"(b0), "r"(b1));
}
__device__ __forceinline__ void store_h4(__half* p, float4 v) {
    __half2 a = __floats2half2_rn(v.x, v.y);
    __half2 b = __floats2half2_rn(v.z, v.w);
    uint2 o;
    o.x = *(uint32_t*)&a;
    o.y = *(uint32_t*)&b;
    *(uint2*)p = o;
}

// ---------------- merged split kernel (all plain fp32 -> fp16) ----------------
#define SPL_N0 (NTOK*D_MODEL)
#define SPL_N1 (N2*D_MODEL)
#define SPL_N2 (INNER*INNER)
#define SPL_N3 (D_MODEL*INNER)
#define SPL_TOT4 ((SPL_N0+SPL_N1+SPL_N2+SPL_N3)/4)

__device__ __forceinline__ void cvt4_hi(const float* s, __half* h) {
    float4 v = *(const float4*)s;
    store_h4(h, v);
}

__global__ __launch_bounds__(256)
void split_all(const float* __restrict__ hidden, const float* __restrict__ wi,
               const float* __restrict__ wd, const float* __restrict__ wo,
               __half* __restrict__ hid_hi, __half* __restrict__ wi_hi,
               __half* __restrict__ wd_hi, __half* __restrict__ wo_hi)
{
    int idx = (blockIdx.x * blockDim.x + threadIdx.x) * 4;
    if (idx < SPL_N0) {
        cvt4_hi(hidden + idx, hid_hi + idx);
    } else if ((idx -= SPL_N0) < SPL_N1) {
        cvt4_hi(wi + idx, wi_hi + idx);
    } else if ((idx -= SPL_N1) < SPL_N2) {
        cvt4_hi(wd + idx, wd_hi + idx);
    } else if ((idx -= SPL_N2) < SPL_N3) {
        cvt4_hi(wo + idx, wo_hi + idx);
    }
}

// ---------------- fp16 x1 NT GEMM (128x128 tiles) ----------------
// EPI 1: softplus(x+b1+b2) -> fp16 store into C2 (row stride INNER)
// EPI 2: in_proj mixed: cols < INNER -> fp32 into Cv (stride INNER);
//        cols >= INNER -> fp16 into C2 (stride INNER)
#define TILE_B 16384
#define SMEM_X1 (2 * 2 * TILE_B)   // 65536

template<int EPI>
__global__ __launch_bounds__(256)
void gemm_fp16x(const __half* __restrict__ Ahi, const __half* __restrict__ Bhi,
                float* __restrict__ Cv, __half* __restrict__ C2,
                int M, int K,
                const float* __restrict__ b1, const float* __restrict__ b2)
{
    extern __shared__ char smem[];
    const uint32_t sb = smem_u32(smem);

    const int tid  = threadIdx.x;
    const int wid  = tid >> 5;
    const int lane = tid & 31;
    const int wm   = wid & 1;
    const int wn   = wid >> 1;
    const int g    = lane >> 3;
    const int lr   = lane & 7;

    const int row0 = blockIdx.y * 128;
    const int col0 = blockIdx.x * 128;

    const __half* srcA = Ahi + (size_t)row0 * K;
    const __half* srcB = Bhi + (size_t)col0 * K;

    float acc[4][4][4];
    #pragma unroll
    for (int mt = 0; mt < 4; ++mt)
        #pragma unroll
        for (int nt = 0; nt < 4; ++nt)
            #pragma unroll
            for (int r = 0; r < 4; ++r) acc[mt][nt][r] = 0.0f;

    auto load_stage = [&](int s, int kc) {
        const __half* gp[2] = { srcA + kc, srcB + kc };
        #pragma unroll
        for (int t = 0; t < 2; ++t) {
            uint32_t dst = sb + (uint32_t)(s * 2 + t) * TILE_B;
            const __half* src = gp[t];
            #pragma unroll
            for (int i = 0; i < 4; ++i) {
                int c = tid + i * 256;
                int r = c >> 3, ch = c & 7;
                cp16(dst + r * 128 + ((ch ^ (r & 7)) << 4),
                     src + (size_t)r * K + ch * 8);
            }
        }
    };

    const int KT = K / 64;
    load_stage(0, 0);
    cp_commit();

    for (int kt = 0; kt < KT; ++kt) {
        if (kt + 1 < KT) {
            load_stage((kt + 1) & 1, (kt + 1) * 64);
            cp_commit();
            cp_wait<1>();
        } else {
            cp_wait<0>();
        }
        __syncthreads();

        const uint32_t st  = sb + (uint32_t)(kt & 1) * 2 * TILE_B;
        const uint32_t sAh = st;
        const uint32_t sBh = st + TILE_B;

        #pragma unroll
        for (int k16 = 0; k16 < 4; ++k16) {
            const int c0 = k16 * 2;
            const int arow_off = ((g & 1) << 3) + lr;
            const int ach = c0 + (g >> 1);
            const int brow_off = ((g >> 1) << 3) + lr;
            const int bch = c0 + (g & 1);

            uint32_t ah[4][4];
            #pragma unroll
            for (int mt = 0; mt < 4; ++mt) {
                int row = wm * 64 + mt * 16 + arow_off;
                uint32_t off = row * 128 + (((ach ^ (row & 7))) << 4);
                ldm_x4(sAh + off, ah[mt]);
            }
            uint32_t bh[4][2];
            #pragma unroll
            for (int nn = 0; nn < 2; ++nn) {
                int row = wn * 32 + nn * 16 + brow_off;
                uint32_t off = row * 128 + (((bch ^ (row & 7))) << 4);
                uint32_t t4[4];
                ldm_x4(sBh + off, t4);
                bh[nn*2][0] = t4[0]; bh[nn*2][1] = t4[1];
                bh[nn*2+1][0] = t4[2]; bh[nn*2+1][1] = t4[3];
            }
            #pragma unroll
            for (int mt = 0; mt < 4; ++mt)
                #pragma unroll
                for (int nt = 0; nt < 4; ++nt)
                    mma_fp16(acc[mt][nt], ah[mt], bh[nt][0], bh[nt][1]);
        }
        __syncthreads();
    }

    const int qr = lane >> 2;
    const int qc = (lane & 3) * 2;
    #pragma unroll
    for (int mt = 0; mt < 4; ++mt) {
        #pragma unroll
        for (int nt = 0; nt < 4; ++nt) {
            int gr = row0 + wm * 64 + mt * 16 + qr;
            int gc = col0 + wn * 32 + nt * 8 + qc;
            float v0 = acc[mt][nt][0], v1 = acc[mt][nt][1];
            float v2 = acc[mt][nt][2], v3 = acc[mt][nt][3];
            if (EPI == 1) {
                float e0 = b1[gc] + b2[gc];
                float e1 = b1[gc + 1] + b2[gc + 1];
                *(__half2*)&C2[(size_t)gr * INNER + gc] =
                    __floats2half2_rn(softplusf(v0 + e0), softplusf(v1 + e1));
                *(__half2*)&C2[(size_t)(gr + 8) * INNER + gc] =
                    __floats2half2_rn(softplusf(v2 + e0), softplusf(v3 + e1));
            } else {  // EPI == 2
                if (gc < INNER) {
                    *(float2*)&Cv[(size_t)gr * INNER + gc]       = make_float2(v0, v1);
                    *(float2*)&Cv[(size_t)(gr + 8) * INNER + gc] = make_float2(v2, v3);
                } else {
                    int g2 = gc - INNER;
                    *(__half2*)&C2[(size_t)gr * INNER + g2] =
                        __floats2half2_rn(v0, v1);
                    *(__half2*)&C2[(size_t)(gr + 8) * INNER + g2] =
                        __floats2half2_rn(v2, v3);
                }
            }
        }
    }
}

// ---------------- out_proj GEMM: 64x64 tiles, x1, 3-stage, 3 CTAs/SM ----------------
#define OTILE 8192
#define OSTAGE (2 * OTILE)
#define OSMEM (3 * OSTAGE)     // 49152

__global__ __launch_bounds__(256, 3)
void gemm_out64(const __half* __restrict__ Ahi, const __half* __restrict__ Bhi,
                float* __restrict__ C, int M, int N, int K)
{
    extern __shared__ char smem[];
    const uint32_t sb = smem_u32(smem);

    const int tid  = threadIdx.x;
    const int wid  = tid >> 5;
    const int lane = tid & 31;
    const int wm   = wid & 1;
    const int wn   = wid >> 1;
    const int g    = lane >> 3;
    const int lr   = lane & 7;

    const int row0 = blockIdx.y * 64;
    const int col0 = blockIdx.x * 64;

    const __half* sA  = Ahi + (size_t)row0 * K;
    const __half* sBh = Bhi + (size_t)col0 * K;

    float acc[2][2][4];
    #pragma unroll
    for (int mt = 0; mt < 2; ++mt)
        #pragma unroll
        for (int nt = 0; nt < 2; ++nt)
            #pragma unroll
            for (int r = 0; r < 4; ++r) acc[mt][nt][r] = 0.0f;

    auto load_stage = [&](int s, int kc) {
        uint32_t base = sb + (uint32_t)s * OSTAGE;
        const __half* gp[2] = { sA + kc, sBh + kc };
        #pragma unroll
        for (int t = 0; t < 2; ++t) {
            uint32_t dst = base + (uint32_t)t * OTILE;
            const __half* src = gp[t];
            #pragma unroll
            for (int i = 0; i < 2; ++i) {
                int c = tid + i * 256;
                int r = c >> 3, ch = c & 7;
                cp16(dst + r * 128 + ((ch ^ (r & 7)) << 4),
                     src + (size_t)r * K + ch * 8);
            }
        }
    };

    const int KT = K / 64;   // 24
    load_stage(0, 0); cp_commit();
    load_stage(1, 64); cp_commit();

    int st = 0;
    for (int kt = 0; kt < KT; ++kt) {
        if (kt + 1 < KT) cp_wait<1>(); else cp_wait<0>();
        __syncthreads();
        if (kt + 2 < KT) {
            int ns = st + 2; if (ns >= 3) ns -= 3;
            load_stage(ns, (kt + 2) * 64);
            cp_commit();
        }

        const uint32_t base = sb + (uint32_t)st * OSTAGE;
        const uint32_t mA  = base;
        const uint32_t mBh = base + OTILE;

        #pragma unroll
        for (int k16 = 0; k16 < 4; ++k16) {
            const int c0 = k16 * 2;
            const int arow_off = ((g & 1) << 3) + lr;
            const int ach = c0 + (g >> 1);
            const int brow_off = ((g >> 1) << 3) + lr;
            const int bch = c0 + (g & 1);

            uint32_t ah[2][4];
            #pragma unroll
            for (int mt = 0; mt < 2; ++mt) {
                int row = wm * 32 + mt * 16 + arow_off;
                uint32_t off = row * 128 + (((ach ^ (row & 7))) << 4);
                ldm_x4(mA + off, ah[mt]);
            }
            uint32_t bh[2][2];
            {
                int row = wn * 16 + brow_off;
                uint32_t off = row * 128 + (((bch ^ (row & 7))) << 4);
                uint32_t t4[4];
                ldm_x4(mBh + off, t4);
                bh[0][0] = t4[0]; bh[0][1] = t4[1];
                bh[1][0] = t4[2]; bh[1][1] = t4[3];
            }
            #pragma unroll
            for (int mt = 0; mt < 2; ++mt)
                #pragma unroll
                for (int nt = 0; nt < 2; ++nt)
                    mma_fp16(acc[mt][nt], ah[mt], bh[nt][0], bh[nt][1]);
        }
        if (++st == 3) st = 0;
    }

    const int qr = lane >> 2;
    const int qc = (lane & 3) * 2;
    #pragma unroll
    for (int mt = 0; mt < 2; ++mt) {
        #pragma unroll
        for (int nt = 0; nt < 2; ++nt) {
            int gr = row0 + wm * 32 + mt * 16 + qr;
            int gc = col0 + wn * 16 + nt * 8 + qc;
            *(float2*)&C[(size_t)gr * N + gc] =
                make_float2(acc[mt][nt][0], acc[mt][nt][1]);
            *(float2*)&C[(size_t)(gr + 8) * N + gc] =
                make_float2(acc[mt][nt][2], acc[mt][nt][3]);
        }
    }
}

// ---------------- conv: 4 channels x 8 timesteps, sliding window, fp16 out ----------------
__global__ __launch_bounds__(256)
void conv_silu_kernel(const float* __restrict__ xp,
                      const float* __restrict__ cw,
                      const float* __restrict__ cb,
                      __half* __restrict__ uhi)
{
    const int nc4 = INNER / 4;
    int gid = blockIdx.x * blockDim.x + threadIdx.x;
    if (gid >= nc4 * (NTOK / CT)) return;
    int c4 = gid % nc4;
    int tb = gid / nc4;
    int c  = c4 * 4;
    int t0 = tb * CT;
    int l0 = t0 & (SEQLEN - 1);

    float4 bias = *(const float4*)(cb + c);
    float4 w0 = *(const float4*)(cw + (c + 0) * D_CONV);
    float4 w1 = *(const float4*)(cw + (c + 1) * D_CONV);
    float4 w2 = *(const float4*)(cw + (c + 2) * D_CONV);
    float4 w3 = *(const float4*)(cw + (c + 3) * D_CONV);
    const float* pw0 = (const float*)&w0;
    const float* pw1 = (const float*)&w1;
    const float* pw2 = (const float*)&w2;
    const float* pw3 = (const float*)&w3;

    const float4 zero = make_float4(0.f, 0.f, 0.f, 0.f);
    auto ldrow = [&](int t) -> float4 {
        return *(const float4*)(xp + (size_t)t * INNER + c);
    };

    float4 x0 = (l0 >= 3) ? ldrow(t0 - 3) : zero;
    float4 x1 = (l0 >= 2) ? ldrow(t0 - 2) : zero;
    float4 x2 = (l0 >= 1) ? ldrow(t0 - 1) : zero;

    #pragma unroll
    for (int j = 0; j < CT; ++j) {
        float4 x3 = ldrow(t0 + j);
        float4 acc = bias;
        acc.x = fmaf(pw0[0], x0.x, acc.x); acc.x = fmaf(pw0[1], x1.x, acc.x);
        acc.x = fmaf(pw0[2], x2.x, acc.x); acc.x = fmaf(pw0[3], x3.x, acc.x);
        acc.y = fmaf(pw1[0], x0.y, acc.y); acc.y = fmaf(pw1[1], x1.y, acc.y);
        acc.y = fmaf(pw1[2], x2.y, acc.y); acc.y = fmaf(pw1[3], x3.y, acc.y);
        acc.z = fmaf(pw2[0], x0.z, acc.z); acc.z = fmaf(pw2[1], x1.z, acc.z);
        acc.z = fmaf(pw2[2], x2.z, acc.z); acc.z = fmaf(pw2[3], x3.z, acc.z);
        acc.w = fmaf(pw3[0], x0.w, acc.w); acc.w = fmaf(pw3[1], x1.w, acc.w);
        acc.w = fmaf(pw3[2], x2.w, acc.w); acc.w = fmaf(pw3[3], x3.w, acc.w);

        float4 v = make_float4(siluf(acc.x), siluf(acc.y), siluf(acc.z), siluf(acc.w));
        store_h4(uhi + (size_t)(t0 + j) * INNER + c, v);

        x0 = x1; x1 = x2; x2 = x3;
    }
}

// ---------------- scan pass 1 (scalar fast path for uniform A) ----------------
__global__ __launch_bounds__(256)
void scan_pass1(const __half* __restrict__ dt, const __half* __restrict__ u,
                const float* __restrict__ A_log, const float* __restrict__ Bp,
                float* __restrict__ hend, float* __restrict__ hend_s,
                float* __restrict__ sdtb)
{
    int idx = blockIdx.x * blockDim.x + threadIdx.x;
    int d = idx % INNER;
    int c = (idx / INNER) & (NCHUNK - 1);
    int b = idx / (INNER * NCHUNK);
    int bc = b * NCHUNK + c;
    int t0 = b * SEQLEN + c * CHUNK;

    float a0 = A_log[d * D_STATE];
    bool uni = true;
    #pragma unroll
    for (int n = 1; n < D_STATE; ++n)
        uni = uni && (A_log[d * D_STATE + n] == a0);

    float sdt = 0.0f;
    if (uni) {
        const float Av0 = -__expf(a0);
        float w = 0.0f;
        for (int j = 0; j < CHUNK; ++j) {
            size_t off = (size_t)(t0 + j) * INNER + d;
            float dtv = __half2float(dt[off]);
            float uv  = __half2float(u[off]);
            sdt += dtv;
            w = fmaf(__expf(dtv * Av0), w, dtv * uv);
        }
        hend_s[(size_t)bc * INNER + d] = w;
    } else {
        float Av[D_STATE], Bv[D_STATE], h[D_STATE];
        #pragma unroll
        for (int n = 0; n < D_STATE; ++n) {
            Av[n] = -__expf(A_log[d * D_STATE + n]);
            Bv[n] = Bp[d * D_STATE + n];
            h[n]  = 0.0f;
        }
        for (int j = 0; j < CHUNK; ++j) {
            size_t off = (size_t)(t0 + j) * INNER + d;
            float dtv = __half2float(dt[off]);
            float uv  = __half2float(u[off]);
            sdt += dtv;
            float du = dtv * uv;
            #pragma unroll
            for (int n = 0; n < D_STATE; ++n)
                h[n] = fmaf(__expf(dtv * Av[n]), h[n], du * Bv[n]);
        }
        #pragma unroll
        for (int n = 0; n < D_STATE; ++n)
            hend[(size_t)(bc * D_STATE + n) * INNER + d] = h[n];
    }
    sdtb[(size_t)bc * INNER + d] = sdt;
}

// ---------------- scan fixup ----------------
__global__ __launch_bounds__(256)
void scan_fix(const float* __restrict__ A_log,
              const float* __restrict__ hend, const float* __restrict__ hend_s,
              const float* __restrict__ sdtb,
              float* __restrict__ h0buf, float* __restrict__ h0_s)
{
    int idx = blockIdx.x * blockDim.x + threadIdx.x;
    if (idx >= BATCH * INNER * D_STATE) return;
    int d = idx % INNER;
    int n = (idx / INNER) % D_STATE;
    int b = idx / (INNER * D_STATE);

    float a0 = A_log[d * D_STATE];
    bool uni = true;
    #pragma unroll
    for (int k = 1; k < D_STATE; ++k)
        uni = uni && (A_log[d * D_STATE + k] == a0);

    if (uni) {
        if (n != 0) return;
        float Av = -__expf(a0);
        float w = 0.0f;
        for (int c = 0; c < NCHUNK; ++c) {
            int bc = b * NCHUNK + c;
            h0_s[(size_t)bc * INNER + d] = w;
            float s = sdtb[(size_t)bc * INNER + d];
            w = fmaf(__expf(Av * s), w, hend_s[(size_t)bc * INNER + d]);
        }
    } else {
        float Av = -__expf(A_log[d * D_STATE + n]);
        float h = 0.0f;
        const size_t nd = (size_t)n * INNER + d;
        for (int c = 0; c < NCHUNK; ++c) {
            int bc = b * NCHUNK + c;
            h0buf[(size_t)bc * D_STATE * INNER + nd] = h;
            float s = sdtb[(size_t)bc * INNER + d];
            h = fmaf(__expf(Av * s), h, hend[(size_t)bc * D_STATE * INNER + nd]);
        }
    }
}

// ---------------- scan pass 2 (scalar fast path; gate fp16) ----------------
__global__ __launch_bounds__(256)
void scan_pass2(const __half* __restrict__ dt, const __half* __restrict__ u,
                const __half* __restrict__ zh,
                const float* __restrict__ A_log, const float* __restrict__ Bp,
                const float* __restrict__ Cp, const float* __restrict__ Dp,
                const float* __restrict__ h0buf, const float* __restrict__ h0_s,
                __half* __restrict__ yghi)
{
    int idx = blockIdx.x * blockDim.x + threadIdx.x;
    int d = idx % INNER;
    int c = (idx / INNER) & (NCHUNK - 1);
    int b = idx / (INNER * NCHUNK);
    int bc = b * NCHUNK + c;
    int t0 = b * SEQLEN + c * CHUNK;
    float Dv = Dp[d];

    float a0 = A_log[d * D_STATE];
    bool uni = true;
    #pragma unroll
    for (int n = 1; n < D_STATE; ++n)
        uni = uni && (A_log[d * D_STATE + n] == a0);

    if (uni) {
        const float Av0 = -__expf(a0);
        float bcsum = 0.0f;
        #pragma unroll
        for (int n = 0; n < D_STATE; ++n)
            bcsum = fmaf(Bp[d * D_STATE + n], Cp[d * D_STATE + n], bcsum);
        float w = h0_s[(size_t)bc * INNER + d];
        for (int j = 0; j < CHUNK; ++j) {
            size_t off = (size_t)(t0 + j) * INNER + d;
            float dtv = __half2float(dt[off]);
            float uv  = __half2float(u[off]);
            w = fmaf(__expf(dtv * Av0), w, dtv * uv);
            float z = __half2float(zh[off]);
            float v = fmaf(bcsum, w, Dv * uv) * siluf(z);
            yghi[off] = __float2half_rn(v);
        }
    } else {
        float Av[D_STATE], Bv[D_STATE], Cv[D_STATE], h[D_STATE];
        #pragma unroll
        for (int n = 0; n < D_STATE; ++n) {
            Av[n] = -__expf(A_log[d * D_STATE + n]);
            Bv[n] = Bp[d * D_STATE + n];
            Cv[n] = Cp[d * D_STATE + n];
            h[n]  = h0buf[(size_t)(bc * D_STATE + n) * INNER + d];
        }
        for (int j = 0; j < CHUNK; ++j) {
            size_t off = (size_t)(t0 + j) * INNER + d;
            float dtv = __half2float(dt[off]);
            float uv  = __half2float(u[off]);
            float du  = dtv * uv;
            float y = 0.0f;
            #pragma unroll
            for (int n = 0; n < D_STATE; ++n) {
                h[n] = fmaf(__expf(dtv * Av[n]), h[n], du * Bv[n]);
                y = fmaf(h[n], Cv[n], y);
            }
            float z = __half2float(zh[off]);
            float v = (y + Dv * uv) * siluf(z);
            yghi[off] = __float2half_rn(v);
        }
    }
}

// ---------------- launcher ----------------
extern "C" void kernel_launch(void* const* d_in, const int* in_sizes, int n_in,
                              void* d_out, int out_size)
{
    const float* hidden    = (const float*)d_in[0];
    const float* in_proj_w = (const float*)d_in[1];
    const float* out_proj_w= (const float*)d_in[2];
    const float* dt_proj_w = (const float*)d_in[3];
    const float* dt_proj_b = (const float*)d_in[4];
    const float* conv_w    = (const float*)d_in[5];
    const float* conv_b    = (const float*)d_in[6];
    const float* A_log     = (const float*)d_in[7];
    const float* B_param   = (const float*)d_in[8];
    const float* C_param   = (const float*)d_in[9];
    const float* D_param   = (const float*)d_in[10];
    const float* dt_bias   = (const float*)d_in[11];
    float* out = (float*)d_out;

    float *xp, *hend, *h0, *hend_s, *h0_s, *sdt;
    __half *z_h, *hid_hi, *wi_hi, *wd_hi, *wo_hi, *u_hi, *dt_h, *yg_hi;
    cudaGetSymbolAddress((void**)&xp,     g_xp);
    cudaGetSymbolAddress((void**)&hend,   g_hend);
    cudaGetSymbolAddress((void**)&h0,     g_h0);
    cudaGetSymbolAddress((void**)&hend_s, g_hend_s);
    cudaGetSymbolAddress((void**)&h0_s,   g_h0_s);
    cudaGetSymbolAddress((void**)&sdt,    g_sdt);
    cudaGetSymbolAddress((void**)&z_h,    g_z_h);
    cudaGetSymbolAddress((void**)&hid_hi, g_hid_hi);
    cudaGetSymbolAddress((void**)&wi_hi,  g_wi_hi);
    cudaGetSymbolAddress((void**)&wd_hi,  g_wd_hi);
    cudaGetSymbolAddress((void**)&wo_hi,  g_wo_hi);
    cudaGetSymbolAddress((void**)&u_hi,   g_u_hi);
    cudaGetSymbolAddress((void**)&dt_h,   g_dt_h);
    cudaGetSymbolAddress((void**)&yg_hi,  g_yg_hi);

    cudaFuncSetAttribute(gemm_fp16x<1>,
                         cudaFuncAttributeMaxDynamicSharedMemorySize, SMEM_X1);
    cudaFuncSetAttribute(gemm_fp16x<2>,
                         cudaFuncAttributeMaxDynamicSharedMemorySize, SMEM_X1);
    cudaFuncSetAttribute(gemm_out64,
                         cudaFuncAttributeMaxDynamicSharedMemorySize, OSMEM);

    // 0) fp16 converts (merged)
    split_all<<<SPL_TOT4 / 256, 256>>>(hidden, in_proj_w, dt_proj_w, out_proj_w,
                                       hid_hi, wi_hi, wd_hi, wo_hi);

    // 1) in_proj (x1, merged proj+gate; mixed fp32/fp16 epilogue)
    {
        dim3 grid(N2 / 128, NTOK / 128);
        gemm_fp16x<2><<<grid, 256, SMEM_X1>>>(hid_hi, wi_hi,
                                              xp, z_h, NTOK, D_MODEL,
                                              nullptr, nullptr);
    }
    // 2) depthwise conv + SiLU -> u_hi (fp16)
    conv_silu_kernel<<<(INNER / 4) * (NTOK / CT) / 256, 256>>>(xp, conv_w, conv_b, u_hi);
    // 3) dt_proj + softplus (x1) -> fp16
    {
        dim3 grid(INNER / 128, NTOK / 128);
        gemm_fp16x<1><<<grid, 256, SMEM_X1>>>(u_hi, wd_hi,
                                              nullptr, dt_h, NTOK, INNER,
                                              dt_proj_b, dt_bias);
    }
    // 4) chunked selective scan (scalar fast path; exact for uniform A)
    {
        int n1 = BATCH * NCHUNK * INNER;
        scan_pass1<<<n1 / 256, 256>>>(dt_h, u_hi, A_log, B_param,
                                      hend, hend_s, sdt);
        scan_fix<<<(BATCH * INNER * D_STATE) / 256, 256>>>(A_log, hend, hend_s,
                                                           sdt, h0, h0_s);
        scan_pass2<<<n1 / 256, 256>>>(dt_h, u_hi, z_h, A_log, B_param, C_param,
                                      D_param, h0, h0_s, yg_hi);
    }
    // 5) out_proj (x1, 64x64 tiles)
    {
        dim3 grid(D_MODEL / 64, NTOK / 64);
        gemm_out64<<<grid, 256, OSMEM>>>(yg_hi, wo_hi, out, NTOK, D_MODEL, INNER);
    }
}